// round 1
// baseline (speedup 1.0000x reference)
#include <cuda_runtime.h>

// Problem geometry (fixed)
#define BATCH 16
#define NTOK  1024      // H*W
#define CDIM  256
#define WDIM  32        // W (and H)

// GEMM tiling
#define BM 128
#define BN 128
#define BK 16
#define NTHREADS 256

// ---------------------------------------------------------------------------
// Scratch (device globals; allocation-free)
// ---------------------------------------------------------------------------
__device__ float g_q[BATCH * NTOK * CDIM];
__device__ float g_k[BATCH * NTOK * CDIM];
__device__ float g_v[BATCH * NTOK * CDIM];
__device__ float g_s[(size_t)BATCH * NTOK * NTOK];   // scores / attn (in-place softmax)
__device__ float g_o[BATCH * NTOK * CDIM];           // attn @ v

// ---------------------------------------------------------------------------
// Shared GEMM microkernel pieces
// ---------------------------------------------------------------------------

// Compute 8x8 per-thread outer products from smem tiles As[BK][BM], Bs[BK][BN]
__device__ __forceinline__ void mm_tile(const float* __restrict__ As,
                                        const float* __restrict__ Bs,
                                        float acc[8][8], int tx, int ty)
{
#pragma unroll
    for (int k = 0; k < BK; ++k) {
        float a[8], b[8];
        const float* Ak = As + k * BM;
        const float* Bk = Bs + k * BN;
        *reinterpret_cast<float4*>(&a[0]) = *reinterpret_cast<const float4*>(&Ak[ty * 4]);
        *reinterpret_cast<float4*>(&a[4]) = *reinterpret_cast<const float4*>(&Ak[64 + ty * 4]);
        *reinterpret_cast<float4*>(&b[0]) = *reinterpret_cast<const float4*>(&Bk[tx * 4]);
        *reinterpret_cast<float4*>(&b[4]) = *reinterpret_cast<const float4*>(&Bk[64 + tx * 4]);
#pragma unroll
        for (int i = 0; i < 8; ++i)
#pragma unroll
            for (int j = 0; j < 8; ++j)
                acc[i][j] += a[i] * b[j];
    }
}

// Load a [128 rows x 16 k] tile where k is the contiguous global dim,
// storing transposed into S[k][row]. G points at tile origin.
__device__ __forceinline__ void load_kcontig(const float* __restrict__ G, int ld,
                                             float* __restrict__ S, int tid)
{
#pragma unroll
    for (int j = 0; j < 2; ++j) {
        int idx = tid + j * 256;            // 0..511 (float4 index)
        int r   = idx >> 2;                 // 0..127
        int kq  = (idx & 3) << 2;           // 0,4,8,12
        float4 v = *reinterpret_cast<const float4*>(&G[(long)r * ld + kq]);
        S[(kq + 0) * BM + r] = v.x;
        S[(kq + 1) * BM + r] = v.y;
        S[(kq + 2) * BM + r] = v.z;
        S[(kq + 3) * BM + r] = v.w;
    }
}

// Load a [16 k x 128 n] tile where n is the contiguous global dim, into S[k][n].
__device__ __forceinline__ void load_ncontig(const float* __restrict__ G, int ld,
                                             float* __restrict__ S, int tid)
{
#pragma unroll
    for (int j = 0; j < 2; ++j) {
        int idx = tid + j * 256;            // 0..511
        int kk  = idx >> 5;                 // 0..15
        int nq  = (idx & 31) << 2;          // 0..124
        *reinterpret_cast<float4*>(&S[kk * BN + nq]) =
            *reinterpret_cast<const float4*>(&G[(long)kk * ld + nq]);
    }
}

// Store the 8x8 accumulator to Cg (tile origin), optional bias (tile-col origin).
__device__ __forceinline__ void store_tile(float* __restrict__ Cg, int ldc,
                                           const float acc[8][8], int tx, int ty,
                                           const float* __restrict__ bias)
{
    float b0[4] = {0.f, 0.f, 0.f, 0.f}, b1[4] = {0.f, 0.f, 0.f, 0.f};
    if (bias) {
#pragma unroll
        for (int j = 0; j < 4; ++j) {
            b0[j] = bias[tx * 4 + j];
            b1[j] = bias[64 + tx * 4 + j];
        }
    }
#pragma unroll
    for (int i = 0; i < 8; ++i) {
        int r = (i < 4) ? (ty * 4 + i) : (64 + ty * 4 + (i - 4));
        float4 v0 = make_float4(acc[i][0] + b0[0], acc[i][1] + b0[1],
                                acc[i][2] + b0[2], acc[i][3] + b0[3]);
        float4 v1 = make_float4(acc[i][4] + b1[0], acc[i][5] + b1[1],
                                acc[i][6] + b1[2], acc[i][7] + b1[3]);
        *reinterpret_cast<float4*>(&Cg[(long)r * ldc + tx * 4]) = v0;
        *reinterpret_cast<float4*>(&Cg[(long)r * ldc + 64 + tx * 4]) = v1;
    }
}

// ---------------------------------------------------------------------------
// Stage 1: q/k/v = x @ W^T + b   (NT GEMM, blockIdx.z selects projection)
// M = B*N = 16384, Ncols = 256, K = 256
// ---------------------------------------------------------------------------
__global__ void __launch_bounds__(NTHREADS)
proj_kernel(const float* __restrict__ x,
            const float* __restrict__ Wq, const float* __restrict__ bq,
            const float* __restrict__ Wk, const float* __restrict__ bk,
            const float* __restrict__ Wv, const float* __restrict__ bv)
{
    __shared__ float As[BK * BM];
    __shared__ float Bs[BK * BN];
    int tid = threadIdx.x, tx = tid & 15, ty = tid >> 4;
    int  n0 = blockIdx.x * BN;
    long m0 = (long)blockIdx.y * BM;
    int sel = blockIdx.z;
    const float* W    = (sel == 0) ? Wq : (sel == 1) ? Wk : Wv;
    const float* bias = (sel == 0) ? bq : (sel == 1) ? bk : bv;
    float*       out  = (sel == 0) ? g_q : (sel == 1) ? g_k : g_v;

    float acc[8][8] = {};
    for (int k0 = 0; k0 < CDIM; k0 += BK) {
        load_kcontig(x + m0 * CDIM + k0, CDIM, As, tid);
        load_kcontig(W + (long)n0 * CDIM + k0, CDIM, Bs, tid);
        __syncthreads();
        mm_tile(As, Bs, acc, tx, ty);
        __syncthreads();
    }
    store_tile(out + m0 * CDIM + n0, CDIM, acc, tx, ty, bias + n0);
}

// ---------------------------------------------------------------------------
// Stage 2: scores[b] = q[b] @ k[b]^T   (NT batched; M=N=1024, K=256)
// ---------------------------------------------------------------------------
__global__ void __launch_bounds__(NTHREADS)
scores_kernel()
{
    __shared__ float As[BK * BM];
    __shared__ float Bs[BK * BN];
    int tid = threadIdx.x, tx = tid & 15, ty = tid >> 4;
    int  n0 = blockIdx.x * BN;
    long m0 = (long)blockIdx.y * BM;
    int  b  = blockIdx.z;
    const float* Ag = g_q + (long)b * NTOK * CDIM;
    const float* Bg = g_k + (long)b * NTOK * CDIM;
    float*       Cg = g_s + (size_t)b * NTOK * NTOK;

    float acc[8][8] = {};
    for (int k0 = 0; k0 < CDIM; k0 += BK) {
        load_kcontig(Ag + m0 * CDIM + k0, CDIM, As, tid);
        load_kcontig(Bg + (long)n0 * CDIM + k0, CDIM, Bs, tid);
        __syncthreads();
        mm_tile(As, Bs, acc, tx, ty);
        __syncthreads();
    }
    store_tile(Cg + m0 * NTOK + n0, NTOK, acc, tx, ty, nullptr);
}

// ---------------------------------------------------------------------------
// Stage 3: row softmax over 1024 elements, in place on g_s.
// One block of 256 threads per row (4 elems/thread via float4).
// ---------------------------------------------------------------------------
__global__ void __launch_bounds__(NTHREADS)
softmax_kernel()
{
    size_t row = blockIdx.x;
    float* r = g_s + row * NTOK;
    int tid = threadIdx.x, lane = tid & 31, wrp = tid >> 5;
    __shared__ float red[8];

    float4 v = reinterpret_cast<float4*>(r)[tid];

    float m = fmaxf(fmaxf(v.x, v.y), fmaxf(v.z, v.w));
#pragma unroll
    for (int o = 16; o; o >>= 1) m = fmaxf(m, __shfl_xor_sync(0xffffffffu, m, o));
    if (!lane) red[wrp] = m;
    __syncthreads();
    if (wrp == 0) {
        float t = red[lane & 7];
#pragma unroll
        for (int o = 4; o; o >>= 1) t = fmaxf(t, __shfl_xor_sync(0xffffffffu, t, o));
        if (!lane) red[0] = t;
    }
    __syncthreads();
    m = red[0];
    __syncthreads();

    v.x = __expf(v.x - m);
    v.y = __expf(v.y - m);
    v.z = __expf(v.z - m);
    v.w = __expf(v.w - m);

    float s = v.x + v.y + v.z + v.w;
#pragma unroll
    for (int o = 16; o; o >>= 1) s += __shfl_xor_sync(0xffffffffu, s, o);
    if (!lane) red[wrp] = s;
    __syncthreads();
    if (wrp == 0) {
        float t = red[lane & 7];
#pragma unroll
        for (int o = 4; o; o >>= 1) t += __shfl_xor_sync(0xffffffffu, t, o);
        if (!lane) red[0] = t;
    }
    __syncthreads();
    float inv = 1.0f / red[0];

    v.x *= inv; v.y *= inv; v.z *= inv; v.w *= inv;
    reinterpret_cast<float4*>(r)[tid] = v;
}

// ---------------------------------------------------------------------------
// Stage 4: o[b] = attn[b] @ v[b]   (NN batched; M=1024, Ncols=256, K=1024)
// ---------------------------------------------------------------------------
__global__ void __launch_bounds__(NTHREADS)
av_kernel()
{
    __shared__ float As[BK * BM];
    __shared__ float Bs[BK * BN];
    int tid = threadIdx.x, tx = tid & 15, ty = tid >> 4;
    int  n0 = blockIdx.x * BN;
    long m0 = (long)blockIdx.y * BM;
    int  b  = blockIdx.z;
    const float* Ag = g_s + (size_t)b * NTOK * NTOK;
    const float* Bg = g_v + (long)b * NTOK * CDIM;
    float*       Cg = g_o + (long)b * NTOK * CDIM;

    float acc[8][8] = {};
    for (int k0 = 0; k0 < NTOK; k0 += BK) {
        load_kcontig(Ag + m0 * NTOK + k0, NTOK, As, tid);
        load_ncontig(Bg + (long)k0 * CDIM + n0, CDIM, Bs, tid);
        __syncthreads();
        mm_tile(As, Bs, acc, tx, ty);
        __syncthreads();
    }
    store_tile(Cg + m0 * CDIM + n0, CDIM, acc, tx, ty, nullptr);
}

// ---------------------------------------------------------------------------
// Stage 5: z[b, p, c] = sum_n Wp[h, n, w] * o[b, n, c],  p = h*32 + w
// A tile gathered from Wp (stride 32 floats over n; coalesced per warp in p).
// ---------------------------------------------------------------------------
__global__ void __launch_bounds__(NTHREADS)
final_kernel(const float* __restrict__ Wp, float* __restrict__ z)
{
    __shared__ float As[BK * BM];
    __shared__ float Bs[BK * BN];
    int tid = threadIdx.x, tx = tid & 15, ty = tid >> 4;
    int  c0 = blockIdx.x * BN;
    int  p0 = blockIdx.y * BM;
    int  b  = blockIdx.z;
    const float* Bg = g_o + (long)b * NTOK * CDIM;
    float*       Cg = z + ((long)b * NTOK + p0) * CDIM + c0;

    float acc[8][8] = {};
    for (int k0 = 0; k0 < NTOK; k0 += BK) {
        // gather A: As[kk][p_local] = Wp[h, k0+kk, w]
#pragma unroll
        for (int j = 0; j < 8; ++j) {
            int idx = tid + j * 256;        // 0..2047
            int pl  = idx & 127;
            int kk  = idx >> 7;             // 0..15
            int p   = p0 + pl;
            int h   = p >> 5, w = p & 31;
            int n   = k0 + kk;
            As[kk * BM + pl] = Wp[(long)h * (NTOK * WDIM) + (long)n * WDIM + w];
        }
        load_ncontig(Bg + (long)k0 * CDIM + c0, CDIM, Bs, tid);
        __syncthreads();
        mm_tile(As, Bs, acc, tx, ty);
        __syncthreads();
    }
    store_tile(Cg, CDIM, acc, tx, ty, nullptr);
}

// ---------------------------------------------------------------------------
extern "C" void kernel_launch(void* const* d_in, const int* in_sizes, int n_in,
                              void* d_out, int out_size)
{
    const float* x  = (const float*)d_in[0];
    const float* Wq = (const float*)d_in[1];
    const float* bq = (const float*)d_in[2];
    const float* Wk = (const float*)d_in[3];
    const float* bk = (const float*)d_in[4];
    const float* Wv = (const float*)d_in[5];
    const float* bv = (const float*)d_in[6];
    const float* Wp = (const float*)d_in[7];
    float* out = (float*)d_out;

    dim3 blk(NTHREADS);
    proj_kernel<<<dim3(CDIM / BN, (BATCH * NTOK) / BM, 3), blk>>>(x, Wq, bq, Wk, bk, Wv, bv);
    scores_kernel<<<dim3(NTOK / BN, NTOK / BM, BATCH), blk>>>();
    softmax_kernel<<<dim3(BATCH * NTOK), blk>>>();
    av_kernel<<<dim3(CDIM / BN, NTOK / BM, BATCH), blk>>>();
    final_kernel<<<dim3(CDIM / BN, NTOK / BM, BATCH), blk>>>(Wp, out);
}

// round 2
// speedup vs baseline: 1.0003x; 1.0003x over previous
#include <cuda_runtime.h>

// Problem geometry (fixed)
#define BATCH 16
#define NTOK  1024      // H*W
#define CDIM  256
#define WDIM  32        // W (and H)

// GEMM tiling
#define BM 128
#define BN 128
#define BK 16
#define NTHREADS 256

// ---------------------------------------------------------------------------
// Scratch (device globals; allocation-free)
// ---------------------------------------------------------------------------
__device__ float g_q[BATCH * NTOK * CDIM];
__device__ float g_k[BATCH * NTOK * CDIM];
__device__ float g_v[BATCH * NTOK * CDIM];
__device__ float g_s[(size_t)BATCH * NTOK * NTOK];   // scores / attn (in-place softmax)
__device__ float g_o[BATCH * NTOK * CDIM];           // attn @ v

// ---------------------------------------------------------------------------
// Shared GEMM microkernel pieces
// ---------------------------------------------------------------------------

// Compute 8x8 per-thread outer products from smem tiles As[BK][BM], Bs[BK][BN]
__device__ __forceinline__ void mm_tile(const float* __restrict__ As,
                                        const float* __restrict__ Bs,
                                        float acc[8][8], int tx, int ty)
{
#pragma unroll
    for (int k = 0; k < BK; ++k) {
        float a[8], b[8];
        const float* Ak = As + k * BM;
        const float* Bk = Bs + k * BN;
        *reinterpret_cast<float4*>(&a[0]) = *reinterpret_cast<const float4*>(&Ak[ty * 4]);
        *reinterpret_cast<float4*>(&a[4]) = *reinterpret_cast<const float4*>(&Ak[64 + ty * 4]);
        *reinterpret_cast<float4*>(&b[0]) = *reinterpret_cast<const float4*>(&Bk[tx * 4]);
        *reinterpret_cast<float4*>(&b[4]) = *reinterpret_cast<const float4*>(&Bk[64 + tx * 4]);
#pragma unroll
        for (int i = 0; i < 8; ++i)
#pragma unroll
            for (int j = 0; j < 8; ++j)
                acc[i][j] += a[i] * b[j];
    }
}

// Load a [128 rows x 16 k] tile where k is the contiguous global dim,
// storing transposed into S[k][row]. G points at tile origin.
__device__ __forceinline__ void load_kcontig(const float* __restrict__ G, int ld,
                                             float* __restrict__ S, int tid)
{
#pragma unroll
    for (int j = 0; j < 2; ++j) {
        int idx = tid + j * 256;            // 0..511 (float4 index)
        int r   = idx >> 2;                 // 0..127
        int kq  = (idx & 3) << 2;           // 0,4,8,12
        float4 v = *reinterpret_cast<const float4*>(&G[(long)r * ld + kq]);
        S[(kq + 0) * BM + r] = v.x;
        S[(kq + 1) * BM + r] = v.y;
        S[(kq + 2) * BM + r] = v.z;
        S[(kq + 3) * BM + r] = v.w;
    }
}

// Load a [16 k x 128 n] tile where n is the contiguous global dim, into S[k][n].
__device__ __forceinline__ void load_ncontig(const float* __restrict__ G, int ld,
                                             float* __restrict__ S, int tid)
{
#pragma unroll
    for (int j = 0; j < 2; ++j) {
        int idx = tid + j * 256;            // 0..511
        int kk  = idx >> 5;                 // 0..15
        int nq  = (idx & 31) << 2;          // 0..124
        *reinterpret_cast<float4*>(&S[kk * BN + nq]) =
            *reinterpret_cast<const float4*>(&G[(long)kk * ld + nq]);
    }
}

// Store the 8x8 accumulator to Cg (tile origin), optional bias (tile-col origin).
__device__ __forceinline__ void store_tile(float* __restrict__ Cg, int ldc,
                                           const float acc[8][8], int tx, int ty,
                                           const float* __restrict__ bias)
{
    float b0[4] = {0.f, 0.f, 0.f, 0.f}, b1[4] = {0.f, 0.f, 0.f, 0.f};
    if (bias) {
#pragma unroll
        for (int j = 0; j < 4; ++j) {
            b0[j] = bias[tx * 4 + j];
            b1[j] = bias[64 + tx * 4 + j];
        }
    }
#pragma unroll
    for (int i = 0; i < 8; ++i) {
        int r = (i < 4) ? (ty * 4 + i) : (64 + ty * 4 + (i - 4));
        float4 v0 = make_float4(acc[i][0] + b0[0], acc[i][1] + b0[1],
                                acc[i][2] + b0[2], acc[i][3] + b0[3]);
        float4 v1 = make_float4(acc[i][4] + b1[0], acc[i][5] + b1[1],
                                acc[i][6] + b1[2], acc[i][7] + b1[3]);
        *reinterpret_cast<float4*>(&Cg[(long)r * ldc + tx * 4]) = v0;
        *reinterpret_cast<float4*>(&Cg[(long)r * ldc + 64 + tx * 4]) = v1;
    }
}

// ---------------------------------------------------------------------------
// Stage 1: q/k/v = x @ W^T + b   (NT GEMM, blockIdx.z selects projection)
// M = B*N = 16384, Ncols = 256, K = 256
// ---------------------------------------------------------------------------
__global__ void __launch_bounds__(NTHREADS)
proj_kernel(const float* __restrict__ x,
            const float* __restrict__ Wq, const float* __restrict__ bq,
            const float* __restrict__ Wk, const float* __restrict__ bk,
            const float* __restrict__ Wv, const float* __restrict__ bv)
{
    __shared__ float As[BK * BM];
    __shared__ float Bs[BK * BN];
    int tid = threadIdx.x, tx = tid & 15, ty = tid >> 4;
    int  n0 = blockIdx.x * BN;
    long m0 = (long)blockIdx.y * BM;
    int sel = blockIdx.z;
    const float* W    = (sel == 0) ? Wq : (sel == 1) ? Wk : Wv;
    const float* bias = (sel == 0) ? bq : (sel == 1) ? bk : bv;
    float*       out  = (sel == 0) ? g_q : (sel == 1) ? g_k : g_v;

    float acc[8][8] = {};
    for (int k0 = 0; k0 < CDIM; k0 += BK) {
        load_kcontig(x + m0 * CDIM + k0, CDIM, As, tid);
        load_kcontig(W + (long)n0 * CDIM + k0, CDIM, Bs, tid);
        __syncthreads();
        mm_tile(As, Bs, acc, tx, ty);
        __syncthreads();
    }
    store_tile(out + m0 * CDIM + n0, CDIM, acc, tx, ty, bias + n0);
}

// ---------------------------------------------------------------------------
// Stage 2: scores[b] = q[b] @ k[b]^T   (NT batched; M=N=1024, K=256)
// ---------------------------------------------------------------------------
__global__ void __launch_bounds__(NTHREADS)
scores_kernel()
{
    __shared__ float As[BK * BM];
    __shared__ float Bs[BK * BN];
    int tid = threadIdx.x, tx = tid & 15, ty = tid >> 4;
    int  n0 = blockIdx.x * BN;
    long m0 = (long)blockIdx.y * BM;
    int  b  = blockIdx.z;
    const float* Ag = g_q + (long)b * NTOK * CDIM;
    const float* Bg = g_k + (long)b * NTOK * CDIM;
    float*       Cg = g_s + (size_t)b * NTOK * NTOK;

    float acc[8][8] = {};
    for (int k0 = 0; k0 < CDIM; k0 += BK) {
        load_kcontig(Ag + m0 * CDIM + k0, CDIM, As, tid);
        load_kcontig(Bg + (long)n0 * CDIM + k0, CDIM, Bs, tid);
        __syncthreads();
        mm_tile(As, Bs, acc, tx, ty);
        __syncthreads();
    }
    store_tile(Cg + m0 * NTOK + n0, NTOK, acc, tx, ty, nullptr);
}

// ---------------------------------------------------------------------------
// Stage 3: row softmax over 1024 elements, in place on g_s.
// One block of 256 threads per row (4 elems/thread via float4).
// ---------------------------------------------------------------------------
__global__ void __launch_bounds__(NTHREADS)
softmax_kernel()
{
    size_t row = blockIdx.x;
    float* r = g_s + row * NTOK;
    int tid = threadIdx.x, lane = tid & 31, wrp = tid >> 5;
    __shared__ float red[8];

    float4 v = reinterpret_cast<float4*>(r)[tid];

    float m = fmaxf(fmaxf(v.x, v.y), fmaxf(v.z, v.w));
#pragma unroll
    for (int o = 16; o; o >>= 1) m = fmaxf(m, __shfl_xor_sync(0xffffffffu, m, o));
    if (!lane) red[wrp] = m;
    __syncthreads();
    if (wrp == 0) {
        float t = red[lane & 7];
#pragma unroll
        for (int o = 4; o; o >>= 1) t = fmaxf(t, __shfl_xor_sync(0xffffffffu, t, o));
        if (!lane) red[0] = t;
    }
    __syncthreads();
    m = red[0];
    __syncthreads();

    v.x = __expf(v.x - m);
    v.y = __expf(v.y - m);
    v.z = __expf(v.z - m);
    v.w = __expf(v.w - m);

    float s = v.x + v.y + v.z + v.w;
#pragma unroll
    for (int o = 16; o; o >>= 1) s += __shfl_xor_sync(0xffffffffu, s, o);
    if (!lane) red[wrp] = s;
    __syncthreads();
    if (wrp == 0) {
        float t = red[lane & 7];
#pragma unroll
        for (int o = 4; o; o >>= 1) t += __shfl_xor_sync(0xffffffffu, t, o);
        if (!lane) red[0] = t;
    }
    __syncthreads();
    float inv = 1.0f / red[0];

    v.x *= inv; v.y *= inv; v.z *= inv; v.w *= inv;
    reinterpret_cast<float4*>(r)[tid] = v;
}

// ---------------------------------------------------------------------------
// Stage 4: o[b] = attn[b] @ v[b]   (NN batched; M=1024, Ncols=256, K=1024)
// ---------------------------------------------------------------------------
__global__ void __launch_bounds__(NTHREADS)
av_kernel()
{
    __shared__ float As[BK * BM];
    __shared__ float Bs[BK * BN];
    int tid = threadIdx.x, tx = tid & 15, ty = tid >> 4;
    int  n0 = blockIdx.x * BN;
    long m0 = (long)blockIdx.y * BM;
    int  b  = blockIdx.z;
    const float* Ag = g_s + (size_t)b * NTOK * NTOK;
    const float* Bg = g_v + (long)b * NTOK * CDIM;
    float*       Cg = g_o + (long)b * NTOK * CDIM;

    float acc[8][8] = {};
    for (int k0 = 0; k0 < NTOK; k0 += BK) {
        load_kcontig(Ag + m0 * NTOK + k0, NTOK, As, tid);
        load_ncontig(Bg + (long)k0 * CDIM + n0, CDIM, Bs, tid);
        __syncthreads();
        mm_tile(As, Bs, acc, tx, ty);
        __syncthreads();
    }
    store_tile(Cg + m0 * CDIM + n0, CDIM, acc, tx, ty, nullptr);
}

// ---------------------------------------------------------------------------
// Stage 5: z[b, p, c] = sum_n Wp[h, n, w] * o[b, n, c],  p = h*32 + w
// A tile gathered from Wp (stride 32 floats over n; coalesced per warp in p).
// ---------------------------------------------------------------------------
__global__ void __launch_bounds__(NTHREADS)
final_kernel(const float* __restrict__ Wp, float* __restrict__ z)
{
    __shared__ float As[BK * BM];
    __shared__ float Bs[BK * BN];
    int tid = threadIdx.x, tx = tid & 15, ty = tid >> 4;
    int  c0 = blockIdx.x * BN;
    int  p0 = blockIdx.y * BM;
    int  b  = blockIdx.z;
    const float* Bg = g_o + (long)b * NTOK * CDIM;
    float*       Cg = z + ((long)b * NTOK + p0) * CDIM + c0;

    float acc[8][8] = {};
    for (int k0 = 0; k0 < NTOK; k0 += BK) {
        // gather A: As[kk][p_local] = Wp[h, k0+kk, w]
#pragma unroll
        for (int j = 0; j < 8; ++j) {
            int idx = tid + j * 256;        // 0..2047
            int pl  = idx & 127;
            int kk  = idx >> 7;             // 0..15
            int p   = p0 + pl;
            int h   = p >> 5, w = p & 31;
            int n   = k0 + kk;
            As[kk * BM + pl] = Wp[(long)h * (NTOK * WDIM) + (long)n * WDIM + w];
        }
        load_ncontig(Bg + (long)k0 * CDIM + c0, CDIM, Bs, tid);
        __syncthreads();
        mm_tile(As, Bs, acc, tx, ty);
        __syncthreads();
    }
    store_tile(Cg, CDIM, acc, tx, ty, nullptr);
}

// ---------------------------------------------------------------------------
extern "C" void kernel_launch(void* const* d_in, const int* in_sizes, int n_in,
                              void* d_out, int out_size)
{
    const float* x  = (const float*)d_in[0];
    const float* Wq = (const float*)d_in[1];
    const float* bq = (const float*)d_in[2];
    const float* Wk = (const float*)d_in[3];
    const float* bk = (const float*)d_in[4];
    const float* Wv = (const float*)d_in[5];
    const float* bv = (const float*)d_in[6];
    const float* Wp = (const float*)d_in[7];
    float* out = (float*)d_out;

    dim3 blk(NTHREADS);
    proj_kernel<<<dim3(CDIM / BN, (BATCH * NTOK) / BM, 3), blk>>>(x, Wq, bq, Wk, bk, Wv, bv);
    scores_kernel<<<dim3(NTOK / BN, NTOK / BM, BATCH), blk>>>();
    softmax_kernel<<<dim3(BATCH * NTOK), blk>>>();
    av_kernel<<<dim3(CDIM / BN, NTOK / BM, BATCH), blk>>>();
    final_kernel<<<dim3(CDIM / BN, NTOK / BM, BATCH), blk>>>(Wp, out);
}

// round 4
// speedup vs baseline: 1.5503x; 1.5499x over previous
#include <cuda_runtime.h>
#include <cuda_bf16.h>
#include <cstdint>

#define BATCH 16
#define NTOK  1024
#define CDIM  256
#define NTHREADS 256
#define SMEM_BYTES 65536      // 2 buffers * (A 16KB + B 16KB)

// ---------------------------------------------------------------------------
// Scratch (device globals; allocation-free)
// ---------------------------------------------------------------------------
__device__ float g_q  [BATCH*NTOK*CDIM];
__device__ float g_k  [BATCH*NTOK*CDIM];
__device__ float g_vt [BATCH*CDIM*NTOK];            // v^T : [b][c][n]
__device__ float g_ot [BATCH*CDIM*NTOK];            // (attn@v)^T : [b][c][n]
__device__ float g_s  [(size_t)BATCH*NTOK*NTOK];    // scores / attn
__device__ float g_wpt[NTOK*NTOK];                  // Wp^T : [p][n]

// ---------------------------------------------------------------------------
__device__ __forceinline__ uint32_t smem_u32(const void* p){
    uint32_t a;
    asm("{ .reg .u64 t; cvta.to.shared.u64 t, %1; cvt.u32.u64 %0, t; }" : "=r"(a) : "l"(p));
    return a;
}
__device__ __forceinline__ void ldsm4(uint32_t* r, uint32_t addr){
    asm volatile("ldmatrix.sync.aligned.m8n8.x4.shared.b16 {%0,%1,%2,%3}, [%4];"
        : "=r"(r[0]), "=r"(r[1]), "=r"(r[2]), "=r"(r[3]) : "r"(addr));
}
__device__ __forceinline__ void mma_bf16(float* d, const uint32_t* a, const uint32_t* b){
    asm volatile("mma.sync.aligned.m16n8k16.row.col.f32.bf16.bf16.f32 "
        "{%0,%1,%2,%3}, {%4,%5,%6,%7}, {%8,%9}, {%0,%1,%2,%3};"
        : "+f"(d[0]), "+f"(d[1]), "+f"(d[2]), "+f"(d[3])
        : "r"(a[0]), "r"(a[1]), "r"(a[2]), "r"(a[3]), "r"(b[0]), "r"(b[1]));
}

// ---------------------------------------------------------------------------
// Global -> registers: per matrix, thread loads 2 granules of 8 floats.
// Granule (r, cc): rows r = w*16 + i*8 + (lane&7), 16B-chunk cc = lane>>3 (k=cc*8..cc*8+7).
// Warp covers 8 rows x 128B contiguous -> fully coalesced.
// ---------------------------------------------------------------------------
__device__ __forceinline__ void gld(float4* dst, const float* __restrict__ src, long ld)
{
    int tid = threadIdx.x, lane = tid & 31, w = tid >> 5;
    int cc = lane >> 3, rl = lane & 7;
#pragma unroll
    for (int i = 0; i < 2; ++i) {
        int r = w * 16 + i * 8 + rl;
        const float4* p = reinterpret_cast<const float4*>(src + (long)r * ld + cc * 8);
        dst[i * 2]     = p[0];
        dst[i * 2 + 1] = p[1];
    }
}

// Registers -> smem slab: row r holds [hi chunks 0-3 | lo chunks 4-7],
// physical 16B chunk = logical ^ (r & 7)  (swizzle; ldmatrix conflict-free).
__device__ __forceinline__ void sst(char* slab, const float4* v)
{
    int tid = threadIdx.x, lane = tid & 31, w = tid >> 5;
    int cc = lane >> 3, rl = lane & 7;
#pragma unroll
    for (int i = 0; i < 2; ++i) {
        int r = w * 16 + i * 8 + rl;
        float4 v0 = v[i * 2], v1 = v[i * 2 + 1];
        __nv_bfloat162 h0 = __floats2bfloat162_rn(v0.x, v0.y);
        __nv_bfloat162 h1 = __floats2bfloat162_rn(v0.z, v0.w);
        __nv_bfloat162 h2 = __floats2bfloat162_rn(v1.x, v1.y);
        __nv_bfloat162 h3 = __floats2bfloat162_rn(v1.z, v1.w);
        __nv_bfloat162 l0 = __floats2bfloat162_rn(v0.x - __low2float(h0), v0.y - __high2float(h0));
        __nv_bfloat162 l1 = __floats2bfloat162_rn(v0.z - __low2float(h1), v0.w - __high2float(h1));
        __nv_bfloat162 l2 = __floats2bfloat162_rn(v1.x - __low2float(h2), v1.y - __high2float(h2));
        __nv_bfloat162 l3 = __floats2bfloat162_rn(v1.z - __low2float(h3), v1.w - __high2float(h3));
        uint4 H = make_uint4(*(uint32_t*)&h0, *(uint32_t*)&h1, *(uint32_t*)&h2, *(uint32_t*)&h3);
        uint4 L = make_uint4(*(uint32_t*)&l0, *(uint32_t*)&l1, *(uint32_t*)&l2, *(uint32_t*)&l3);
        char* rowp = slab + r * 128;
        *reinterpret_cast<uint4*>(rowp + (((cc    ) ^ (r & 7)) << 4)) = H;
        *reinterpret_cast<uint4*>(rowp + (((cc + 4) ^ (r & 7)) << 4)) = L;
    }
}

// ---------------------------------------------------------------------------
// Compute one K=32 slab: 8 warps in 2(M)x4(N), warp tile 64x32.
// acc[mi][j][4] : mi = m16 tile, j = n8 group.
// ---------------------------------------------------------------------------
__device__ __forceinline__ void compute_slab(char* buf, float acc[4][4][4])
{
    int tid = threadIdx.x, lane = tid & 31, wid = tid >> 5;
    uint32_t sA = smem_u32(buf), sB = sA + 16384;
    int mw = (wid & 1) * 64, nw = (wid >> 1) * 32;
    int arow = lane & 15, ahalf = lane >> 4;
    int brow = (lane & 7) + ((lane >> 4) & 1) * 8, bhalf = (lane >> 3) & 1;

#pragma unroll
    for (int ks = 0; ks < 2; ++ks) {
        uint32_t bh[8], bl[8];
#pragma unroll
        for (int nj = 0; nj < 2; ++nj) {
            int r = nw + nj * 16 + brow;
            int c = ks * 2 + bhalf;
            ldsm4(bh + nj * 4, sB + r * 128 + (((c    ) ^ (r & 7)) << 4));
            ldsm4(bl + nj * 4, sB + r * 128 + (((c + 4) ^ (r & 7)) << 4));
        }
#pragma unroll
        for (int mi = 0; mi < 4; ++mi) {
            int r = mw + mi * 16 + arow;
            int c = ks * 2 + ahalf;
            uint32_t ah[4], al[4];
            ldsm4(ah, sA + r * 128 + (((c    ) ^ (r & 7)) << 4));
            ldsm4(al, sA + r * 128 + (((c + 4) ^ (r & 7)) << 4));
#pragma unroll
            for (int j = 0; j < 4; ++j) {
                const uint32_t* bhf = &bh[(j >> 1) * 4 + (j & 1) * 2];
                const uint32_t* blf = &bl[(j >> 1) * 4 + (j & 1) * 2];
                float* d = acc[mi][j];
                mma_bf16(d, ah, bhf);   // hi*hi
                mma_bf16(d, al, bhf);   // lo*hi
                mma_bf16(d, ah, blf);   // hi*lo
            }
        }
    }
}

// ---------------------------------------------------------------------------
// Full GEMM mainloop: C(128x128) = A(128 rows, K) . B(128 rows, K)^T
// A, B: fp32, K-contiguous rows. Double-buffered, register prefetch.
// ---------------------------------------------------------------------------
__device__ __forceinline__ void gemm_run(const float* __restrict__ A, long lda,
                                         const float* __restrict__ B, long ldb,
                                         int NC, char* smem, float acc[4][4][4])
{
    float4 pa[4], pb[4];
    gld(pa, A, lda); gld(pb, B, ldb);
    sst(smem, pa); sst(smem + 16384, pb);
    __syncthreads();

    for (int c = 0; c < NC; ++c) {
        bool more = (c + 1 < NC);
        if (more) {
            gld(pa, A + (c + 1) * 32, lda);
            gld(pb, B + (c + 1) * 32, ldb);
        }
        compute_slab(smem + (c & 1) * 32768, acc);
        if (more) {
            char* nb = smem + ((c + 1) & 1) * 32768;
            sst(nb, pa); sst(nb + 16384, pb);
            __syncthreads();
        }
    }
}

// ---------------------------------------------------------------------------
// Epilogues. D frag: d0,d1 = (row = lane>>2, col = (lane&3)*2 + e), d2,d3 row+8.
// ---------------------------------------------------------------------------
__device__ __forceinline__ void epi_normal(const float acc[4][4][4],
        float* __restrict__ Cg, int ldc, const float* __restrict__ bias)
{
    int tid = threadIdx.x, lane = tid & 31, wid = tid >> 5;
    int mw = (wid & 1) * 64, nw = (wid >> 1) * 32;
    int row0 = mw + (lane >> 2), col0 = nw + (lane & 3) * 2;
#pragma unroll
    for (int mi = 0; mi < 4; ++mi)
#pragma unroll
        for (int j = 0; j < 4; ++j) {
            int c = col0 + j * 8;
            float b0 = bias ? bias[c] : 0.0f;
            float b1 = bias ? bias[c + 1] : 0.0f;
#pragma unroll
            for (int h = 0; h < 2; ++h) {
                int r = row0 + mi * 16 + h * 8;
                float2 val = make_float2(acc[mi][j][h * 2] + b0, acc[mi][j][h * 2 + 1] + b1);
                *reinterpret_cast<float2*>(Cg + (long)r * ldc + c) = val;
            }
        }
}

// element (m, n) -> Ct[n*ldt + m]
__device__ __forceinline__ void epi_trans(const float acc[4][4][4],
        float* __restrict__ Ct, int ldt, const float* __restrict__ bias)
{
    int tid = threadIdx.x, lane = tid & 31, wid = tid >> 5;
    int mw = (wid & 1) * 64, nw = (wid >> 1) * 32;
    int row0 = mw + (lane >> 2), col0 = nw + (lane & 3) * 2;
#pragma unroll
    for (int mi = 0; mi < 4; ++mi)
#pragma unroll
        for (int j = 0; j < 4; ++j)
#pragma unroll
            for (int h = 0; h < 2; ++h) {
                int m = row0 + mi * 16 + h * 8;
#pragma unroll
                for (int e = 0; e < 2; ++e) {
                    int n = col0 + j * 8 + e;
                    float bv = bias ? bias[n] : 0.0f;
                    Ct[(long)n * ldt + m] = acc[mi][j][h * 2 + e] + bv;
                }
            }
}

// ---------------------------------------------------------------------------
// Stage 0: Wp^T  g_wpt[p][n] = Wp[h][n][w], p = h*32+w
// ---------------------------------------------------------------------------
__global__ void __launch_bounds__(NTHREADS) wpt_kernel(const float* __restrict__ Wp)
{
    __shared__ float t[32][33];
    int h = blockIdx.x, n0 = blockIdx.y * 32;
    int tx = threadIdx.x & 31, ty = threadIdx.x >> 5;
    const float* src = Wp + (long)h * 32768 + (long)n0 * 32;
#pragma unroll
    for (int i = 0; i < 4; ++i) t[ty + i * 8][tx] = src[(ty + i * 8) * 32 + tx];
    __syncthreads();
#pragma unroll
    for (int i = 0; i < 4; ++i) {
        int w = ty + i * 8;
        g_wpt[((long)h * 32 + w) * NTOK + n0 + tx] = t[tx][w];
    }
}

// ---------------------------------------------------------------------------
// Stage 1: q/k (normal out) and v (transposed out). grid (2, 128, 3)
// ---------------------------------------------------------------------------
__global__ void __launch_bounds__(NTHREADS)
proj_kernel(const float* __restrict__ x,
            const float* __restrict__ Wq, const float* __restrict__ bq,
            const float* __restrict__ Wk, const float* __restrict__ bk,
            const float* __restrict__ Wv, const float* __restrict__ bv)
{
    extern __shared__ char smem[];
    int n0 = blockIdx.x * 128; long m0 = (long)blockIdx.y * 128; int sel = blockIdx.z;
    const float* W    = sel == 0 ? Wq : sel == 1 ? Wk : Wv;
    const float* bias = sel == 0 ? bq : sel == 1 ? bk : bv;

    float acc[4][4][4] = {};
    gemm_run(x + m0 * CDIM, CDIM, W + (long)n0 * CDIM, CDIM, CDIM / 32, smem, acc);

    if (sel < 2) {
        float* out = sel == 0 ? g_q : g_k;
        epi_normal(acc, out + m0 * CDIM + n0, CDIM, bias + n0);
    } else {
        int b = (int)(m0 >> 10), tok0 = (int)(m0 & 1023);
        epi_trans(acc, g_vt + ((long)b * CDIM + n0) * NTOK + tok0, NTOK, bias + n0);
    }
}

// ---------------------------------------------------------------------------
// Stage 2: scores = q k^T. grid (8, 8, 16)
// ---------------------------------------------------------------------------
__global__ void __launch_bounds__(NTHREADS) scores_kernel()
{
    extern __shared__ char smem[];
    int n0 = blockIdx.x * 128, m0 = blockIdx.y * 128, b = blockIdx.z;
    float acc[4][4][4] = {};
    gemm_run(g_q + ((long)b * NTOK + m0) * CDIM, CDIM,
             g_k + ((long)b * NTOK + n0) * CDIM, CDIM, CDIM / 32, smem, acc);
    epi_normal(acc, g_s + (size_t)b * NTOK * NTOK + (long)m0 * NTOK + n0, NTOK, nullptr);
}

// ---------------------------------------------------------------------------
// Stage 3: softmax rows of g_s (in place)
// ---------------------------------------------------------------------------
__global__ void __launch_bounds__(NTHREADS) softmax_kernel()
{
    size_t row = blockIdx.x;
    float* r = g_s + row * NTOK;
    int tid = threadIdx.x, lane = tid & 31, wrp = tid >> 5;
    __shared__ float red[8];
    float4 v = reinterpret_cast<float4*>(r)[tid];

    float m = fmaxf(fmaxf(v.x, v.y), fmaxf(v.z, v.w));
#pragma unroll
    for (int o = 16; o; o >>= 1) m = fmaxf(m, __shfl_xor_sync(0xffffffffu, m, o));
    if (!lane) red[wrp] = m;
    __syncthreads();
    if (wrp == 0) {
        float t = red[lane & 7];
#pragma unroll
        for (int o = 4; o; o >>= 1) t = fmaxf(t, __shfl_xor_sync(0xffffffffu, t, o));
        if (!lane) red[0] = t;
    }
    __syncthreads();
    m = red[0];
    __syncthreads();
    v.x = __expf(v.x - m); v.y = __expf(v.y - m);
    v.z = __expf(v.z - m); v.w = __expf(v.w - m);
    float s = v.x + v.y + v.z + v.w;
#pragma unroll
    for (int o = 16; o; o >>= 1) s += __shfl_xor_sync(0xffffffffu, s, o);
    if (!lane) red[wrp] = s;
    __syncthreads();
    if (wrp == 0) {
        float t = red[lane & 7];
#pragma unroll
        for (int o = 4; o; o >>= 1) t += __shfl_xor_sync(0xffffffffu, t, o);
        if (!lane) red[0] = t;
    }
    __syncthreads();
    float inv = 1.0f / red[0];
    v.x *= inv; v.y *= inv; v.z *= inv; v.w *= inv;
    reinterpret_cast<float4*>(r)[tid] = v;
}

// ---------------------------------------------------------------------------
// Stage 4: (attn @ v)^T -> g_ot. grid (2, 8, 16)
// ---------------------------------------------------------------------------
__global__ void __launch_bounds__(NTHREADS) av_kernel()
{
    extern __shared__ char smem[];
    int c0 = blockIdx.x * 128, tok0 = blockIdx.y * 128, b = blockIdx.z;
    float acc[4][4][4] = {};
    gemm_run(g_s + (size_t)b * NTOK * NTOK + (long)tok0 * NTOK, NTOK,
             g_vt + ((long)b * CDIM + c0) * NTOK, NTOK, NTOK / 32, smem, acc);
    epi_trans(acc, g_ot + ((long)b * CDIM + c0) * NTOK + tok0, NTOK, nullptr);
}

// ---------------------------------------------------------------------------
// Stage 5: z[b,p,c] = sum_n wpt[p][n] * ot[c][n]. grid (2, 8, 16)
// ---------------------------------------------------------------------------
__global__ void __launch_bounds__(NTHREADS) final_kernel(float* __restrict__ z)
{
    extern __shared__ char smem[];
    int c0 = blockIdx.x * 128, p0 = blockIdx.y * 128, b = blockIdx.z;
    float acc[4][4][4] = {};
    gemm_run(g_wpt + (long)p0 * NTOK, NTOK,
             g_ot + ((long)b * CDIM + c0) * NTOK, NTOK, NTOK / 32, smem, acc);
    epi_normal(acc, z + ((long)b * NTOK + p0) * CDIM + c0, CDIM, nullptr);
}

// ---------------------------------------------------------------------------
extern "C" void kernel_launch(void* const* d_in, const int* in_sizes, int n_in,
                              void* d_out, int out_size)
{
    const float* x  = (const float*)d_in[0];
    const float* Wq = (const float*)d_in[1];
    const float* bq = (const float*)d_in[2];
    const float* Wk = (const float*)d_in[3];
    const float* bk = (const float*)d_in[4];
    const float* Wv = (const float*)d_in[5];
    const float* bv = (const float*)d_in[6];
    const float* Wp = (const float*)d_in[7];
    float* out = (float*)d_out;

    static bool configured = false;
    if (!configured) {
        cudaFuncSetAttribute(proj_kernel,   cudaFuncAttributeMaxDynamicSharedMemorySize, SMEM_BYTES);
        cudaFuncSetAttribute(scores_kernel, cudaFuncAttributeMaxDynamicSharedMemorySize, SMEM_BYTES);
        cudaFuncSetAttribute(av_kernel,     cudaFuncAttributeMaxDynamicSharedMemorySize, SMEM_BYTES);
        cudaFuncSetAttribute(final_kernel,  cudaFuncAttributeMaxDynamicSharedMemorySize, SMEM_BYTES);
        configured = true;
    }

    wpt_kernel<<<dim3(32, 32), NTHREADS>>>(Wp);
    proj_kernel<<<dim3(2, 128, 3), NTHREADS, SMEM_BYTES>>>(x, Wq, bq, Wk, bk, Wv, bv);
    scores_kernel<<<dim3(8, 8, 16), NTHREADS, SMEM_BYTES>>>();
    softmax_kernel<<<dim3(BATCH * NTOK), NTHREADS>>>();
    av_kernel<<<dim3(2, 8, 16), NTHREADS, SMEM_BYTES>>>();
    final_kernel<<<dim3(2, 8, 16), NTHREADS, SMEM_BYTES>>>(out);
}

// round 5
// speedup vs baseline: 2.5005x; 1.6128x over previous
#include <cuda_runtime.h>
#include <cuda_bf16.h>
#include <cstdint>

#define BATCH 16
#define NTOK  1024
#define CDIM  256
#define NTHREADS 256
#define NSTAGE 3
#define SLABB 16384                    // one matrix slab: 128 rows x 128B
#define STAGEB (2*SLABB)               // A + B
#define SMEM_BYTES (NSTAGE*STAGEB)     // 98304

// ---------------------------------------------------------------------------
// Scratch. "sbf" format: row-major, per row the K dim is split into groups of
// 32; group g occupies 128 bytes: [64B hi bf16 | 64B lo bf16]. Row stride in
// bytes = K*4 (same as fp32).
// ---------------------------------------------------------------------------
__device__ __align__(128) char g_xs  [16384*1024];     // x sbf (rows tok, K=256)
__device__ __align__(128) char g_ws  [3*256*1024];     // Wq|Wk|Wv sbf (rows d, K=256)
__device__ __align__(128) char g_qs  [16384*1024];     // q sbf
__device__ __align__(128) char g_ks  [16384*1024];     // k sbf
__device__ __align__(128) char g_vts [16*256*4096];    // v^T sbf (rows c, K=n)
__device__ __align__(128) char g_ots [16*256*4096];    // (attn v)^T sbf
__device__ __align__(128) char g_attns[(size_t)16384*4096]; // attn sbf (rows m, K=n)
__device__ __align__(128) char g_wpts[1024*4096];      // Wp^T sbf (rows p, K=n)
__device__ float g_s[(size_t)BATCH*NTOK*NTOK];         // scores fp32

// ---------------------------------------------------------------------------
__device__ __forceinline__ uint32_t smem_u32(const void* p){
    uint32_t a;
    asm("{ .reg .u64 t; cvta.to.shared.u64 t, %1; cvt.u32.u64 %0, t; }" : "=r"(a) : "l"(p));
    return a;
}
__device__ __forceinline__ void ldsm4(uint32_t* r, uint32_t addr){
    asm volatile("ldmatrix.sync.aligned.m8n8.x4.shared.b16 {%0,%1,%2,%3}, [%4];"
        : "=r"(r[0]), "=r"(r[1]), "=r"(r[2]), "=r"(r[3]) : "r"(addr));
}
__device__ __forceinline__ void mma_bf16(float* d, const uint32_t* a, const uint32_t* b){
    asm volatile("mma.sync.aligned.m16n8k16.row.col.f32.bf16.bf16.f32 "
        "{%0,%1,%2,%3}, {%4,%5,%6,%7}, {%8,%9}, {%0,%1,%2,%3};"
        : "+f"(d[0]), "+f"(d[1]), "+f"(d[2]), "+f"(d[3])
        : "r"(a[0]), "r"(a[1]), "r"(a[2]), "r"(a[3]), "r"(b[0]), "r"(b[1]));
}
__device__ __forceinline__ void split2(float v0, float v1,
        __nv_bfloat162& h, __nv_bfloat162& l){
    h = __floats2bfloat162_rn(v0, v1);
    l = __floats2bfloat162_rn(v0 - __low2float(h), v1 - __high2float(h));
}

// ---------------------------------------------------------------------------
// cp.async one slab: 128 rows x 8 16B-chunks, swizzled chunk = cc ^ (r&7).
// src points at (row 0, k-group of this slab); ld = row stride bytes.
// ---------------------------------------------------------------------------
__device__ __forceinline__ void load_slab_async(char* slab, const char* __restrict__ src, long ld)
{
    int tid = threadIdx.x;
#pragma unroll
    for (int i = 0; i < 4; ++i) {
        int idx = tid + i * 256;
        int r = idx >> 3, cc = idx & 7;
        uint32_t dst = smem_u32(slab + r * 128 + ((cc ^ (r & 7)) << 4));
        const char* s = src + (long)r * ld + cc * 16;
        asm volatile("cp.async.cg.shared.global [%0], [%1], 16;" :: "r"(dst), "l"(s));
    }
}

// ---------------------------------------------------------------------------
// One K=32 slab of MMAs. 8 warps in 2(M)x4(N); warp tile 64x32.
// ---------------------------------------------------------------------------
__device__ __forceinline__ void compute_slab(char* buf, float acc[4][4][4])
{
    int tid = threadIdx.x, lane = tid & 31, wid = tid >> 5;
    uint32_t sA = smem_u32(buf), sB = sA + SLABB;
    int mw = (wid & 1) * 64, nw = (wid >> 1) * 32;
    int arow = lane & 15, ahalf = lane >> 4;
    int brow = (lane & 7) + ((lane >> 4) & 1) * 8, bhalf = (lane >> 3) & 1;

#pragma unroll
    for (int ks = 0; ks < 2; ++ks) {
        uint32_t bh[8], bl[8];
#pragma unroll
        for (int nj = 0; nj < 2; ++nj) {
            int r = nw + nj * 16 + brow;
            int c = ks * 2 + bhalf;
            ldsm4(bh + nj * 4, sB + r * 128 + (((c    ) ^ (r & 7)) << 4));
            ldsm4(bl + nj * 4, sB + r * 128 + (((c + 4) ^ (r & 7)) << 4));
        }
#pragma unroll
        for (int mi = 0; mi < 4; ++mi) {
            int r = mw + mi * 16 + arow;
            int c = ks * 2 + ahalf;
            uint32_t ah[4], al[4];
            ldsm4(ah, sA + r * 128 + (((c    ) ^ (r & 7)) << 4));
            ldsm4(al, sA + r * 128 + (((c + 4) ^ (r & 7)) << 4));
#pragma unroll
            for (int j = 0; j < 4; ++j) {
                const uint32_t* bhf = &bh[(j >> 1) * 4 + (j & 1) * 2];
                const uint32_t* blf = &bl[(j >> 1) * 4 + (j & 1) * 2];
                float* d = acc[mi][j];
                mma_bf16(d, ah, bhf);
                mma_bf16(d, al, bhf);
                mma_bf16(d, ah, blf);
            }
        }
    }
}

// ---------------------------------------------------------------------------
// 3-stage cp.async GEMM mainloop over sbf operands.
// ---------------------------------------------------------------------------
__device__ __forceinline__ void gemm_async(const char* __restrict__ A, long ldA,
                                           const char* __restrict__ B, long ldB,
                                           int NC, char* smem, float acc[4][4][4])
{
#pragma unroll
    for (int s = 0; s < NSTAGE - 1; ++s) {
        char* b = smem + s * STAGEB;
        load_slab_async(b,         A + (long)s * 128, ldA);
        load_slab_async(b + SLABB, B + (long)s * 128, ldB);
        asm volatile("cp.async.commit_group;" ::: "memory");
    }
    for (int c = 0; c < NC; ++c) {
        asm volatile("cp.async.wait_group %0;" :: "n"(NSTAGE - 2) : "memory");
        __syncthreads();
        int nc = c + NSTAGE - 1;
        if (nc < NC) {
            char* b = smem + (nc % NSTAGE) * STAGEB;
            load_slab_async(b,         A + (long)nc * 128, ldA);
            load_slab_async(b + SLABB, B + (long)nc * 128, ldB);
        }
        asm volatile("cp.async.commit_group;" ::: "memory");
        compute_slab(smem + (c % NSTAGE) * STAGEB, acc);
    }
}

// ---------------------------------------------------------------------------
// Epilogues. Frag: d0,d1 -> (row=lane>>2, col=(lane&3)*2 + e), d2,d3 row+8.
// ---------------------------------------------------------------------------
__device__ __forceinline__ void epi_f32(const float acc[4][4][4],
        float* __restrict__ Cg, int ldc)
{
    int tid = threadIdx.x, lane = tid & 31, wid = tid >> 5;
    int row0 = (wid & 1) * 64 + (lane >> 2), col0 = (wid >> 1) * 32 + (lane & 3) * 2;
#pragma unroll
    for (int mi = 0; mi < 4; ++mi)
#pragma unroll
        for (int j = 0; j < 4; ++j) {
            int c = col0 + j * 8;
#pragma unroll
            for (int h = 0; h < 2; ++h) {
                int r = row0 + mi * 16 + h * 8;
                *reinterpret_cast<float2*>(Cg + (long)r * ldc + c) =
                    make_float2(acc[mi][j][h * 2], acc[mi][j][h * 2 + 1]);
            }
        }
}

// write C(128x128) in sbf at base (row origin; col origin folded, col0%32==0)
__device__ __forceinline__ void epi_sbf(const float acc[4][4][4],
        char* base, long ld, const float* __restrict__ bias)
{
    int tid = threadIdx.x, lane = tid & 31, wid = tid >> 5;
    int row0 = (wid & 1) * 64 + (lane >> 2), col0 = (wid >> 1) * 32 + (lane & 3) * 2;
#pragma unroll
    for (int mi = 0; mi < 4; ++mi)
#pragma unroll
        for (int j = 0; j < 4; ++j) {
            int c = col0 + j * 8;
            float b0 = bias ? bias[c] : 0.0f, b1 = bias ? bias[c + 1] : 0.0f;
#pragma unroll
            for (int h = 0; h < 2; ++h) {
                int r = row0 + mi * 16 + h * 8;
                __nv_bfloat162 hh, ll;
                split2(acc[mi][j][h * 2] + b0, acc[mi][j][h * 2 + 1] + b1, hh, ll);
                char* p = base + (long)r * ld + (c >> 5) * 128 + (c & 31) * 2;
                *reinterpret_cast<__nv_bfloat162*>(p)      = hh;
                *reinterpret_cast<__nv_bfloat162*>(p + 64) = ll;
            }
        }
}

// transposed sbf: element (m, n) -> row n, k-position m (k origin folded, %32==0)
__device__ __forceinline__ void epi_sbf_t(const float acc[4][4][4],
        char* base, long ld, const float* __restrict__ bias)
{
    int tid = threadIdx.x, lane = tid & 31, wid = tid >> 5;
    int row0 = (wid & 1) * 64 + (lane >> 2), col0 = (wid >> 1) * 32 + (lane & 3) * 2;
#pragma unroll
    for (int mi = 0; mi < 4; ++mi)
#pragma unroll
        for (int j = 0; j < 4; ++j)
#pragma unroll
            for (int h = 0; h < 2; ++h) {
                int m = row0 + mi * 16 + h * 8;
#pragma unroll
                for (int e = 0; e < 2; ++e) {
                    int n = col0 + j * 8 + e;
                    float v = acc[mi][j][h * 2 + e] + (bias ? bias[n] : 0.0f);
                    __nv_bfloat16 hb = __float2bfloat16(v);
                    __nv_bfloat16 lb = __float2bfloat16(v - __bfloat162float(hb));
                    char* p = base + (long)n * ld + (m >> 5) * 128 + (m & 31) * 2;
                    *reinterpret_cast<__nv_bfloat16*>(p)      = hb;
                    *reinterpret_cast<__nv_bfloat16*>(p + 64) = lb;
                }
            }
}

// ---------------------------------------------------------------------------
// fp32 array -> sbf (row length must be multiple of 32; preserved layout)
// ---------------------------------------------------------------------------
__global__ void __launch_bounds__(NTHREADS) conv_kernel(const float* __restrict__ src,
        char* __restrict__ dst)
{
    long i = (long)blockIdx.x * NTHREADS + threadIdx.x;   // float4 index
    float4 v = reinterpret_cast<const float4*>(src)[i];
    long e = i * 4;
    char* p = dst + (e & ~31L) * 4 + (e & 31) * 2;
    __nv_bfloat162 h0, l0, h1, l1;
    split2(v.x, v.y, h0, l0);
    split2(v.z, v.w, h1, l1);
    *reinterpret_cast<__nv_bfloat162*>(p)          = h0;
    *reinterpret_cast<__nv_bfloat162*>(p + 4)      = h1;
    *reinterpret_cast<__nv_bfloat162*>(p + 64)     = l0;
    *reinterpret_cast<__nv_bfloat162*>(p + 68)     = l1;
}

// Wp[h][n][w] -> wpts sbf row p=h*32+w, k=n
__global__ void __launch_bounds__(NTHREADS) wpt_kernel(const float* __restrict__ Wp)
{
    __shared__ float t[32][33];
    int h = blockIdx.x, n0 = blockIdx.y * 32;
    int tx = threadIdx.x & 31, ty = threadIdx.x >> 5;
    const float* src = Wp + (long)h * 32768 + (long)n0 * 32;
#pragma unroll
    for (int i = 0; i < 4; ++i) t[ty + i * 8][tx] = src[(ty + i * 8) * 32 + tx];
    __syncthreads();
#pragma unroll
    for (int i = 0; i < 4; ++i) {
        int w = ty + i * 8;
        float v = t[tx][w];
        int n = n0 + tx;
        __nv_bfloat16 hb = __float2bfloat16(v);
        __nv_bfloat16 lb = __float2bfloat16(v - __bfloat162float(hb));
        char* p = g_wpts + ((long)h * 32 + w) * 4096 + (n >> 5) * 128 + (n & 31) * 2;
        *reinterpret_cast<__nv_bfloat16*>(p)      = hb;
        *reinterpret_cast<__nv_bfloat16*>(p + 64) = lb;
    }
}

// ---------------------------------------------------------------------------
// Stage 1: proj. grid (2, 128, 3). q/k -> sbf normal; v -> sbf transposed.
// ---------------------------------------------------------------------------
__global__ void __launch_bounds__(NTHREADS, 2)
proj_kernel(const float* __restrict__ bq, const float* __restrict__ bk,
            const float* __restrict__ bv)
{
    extern __shared__ char smem[];
    int n0 = blockIdx.x * 128; long m0 = (long)blockIdx.y * 128; int sel = blockIdx.z;
    const float* bias = sel == 0 ? bq : sel == 1 ? bk : bv;
    float acc[4][4][4] = {};
    gemm_async(g_xs + m0 * 1024, 1024,
               g_ws + ((long)sel * 256 + n0) * 1024, 1024, CDIM / 32, smem, acc);
    if (sel < 2) {
        char* out = sel == 0 ? g_qs : g_ks;
        epi_sbf(acc, out + m0 * 1024 + (n0 >> 5) * 128, 1024, bias + n0);
    } else {
        int b = (int)(m0 >> 10), tok0 = (int)(m0 & 1023);
        epi_sbf_t(acc, g_vts + ((long)b * CDIM + n0) * 4096 + (tok0 >> 5) * 128, 4096, bias + n0);
    }
}

// ---------------------------------------------------------------------------
// Stage 2: scores = q k^T -> fp32. grid (8, 8, 16)
// ---------------------------------------------------------------------------
__global__ void __launch_bounds__(NTHREADS, 2) scores_kernel()
{
    extern __shared__ char smem[];
    int n0 = blockIdx.x * 128, m0 = blockIdx.y * 128, b = blockIdx.z;
    float acc[4][4][4] = {};
    gemm_async(g_qs + ((long)b * NTOK + m0) * 1024, 1024,
               g_ks + ((long)b * NTOK + n0) * 1024, 1024, CDIM / 32, smem, acc);
    epi_f32(acc, g_s + (size_t)b * NTOK * NTOK + (long)m0 * NTOK + n0, NTOK);
}

// ---------------------------------------------------------------------------
// Stage 3: softmax row of g_s -> attn sbf
// ---------------------------------------------------------------------------
__global__ void __launch_bounds__(NTHREADS) softmax_kernel()
{
    size_t row = blockIdx.x;
    const float* r = g_s + row * NTOK;
    int tid = threadIdx.x, lane = tid & 31, wrp = tid >> 5;
    __shared__ float red[8];
    float4 v = reinterpret_cast<const float4*>(r)[tid];

    float m = fmaxf(fmaxf(v.x, v.y), fmaxf(v.z, v.w));
#pragma unroll
    for (int o = 16; o; o >>= 1) m = fmaxf(m, __shfl_xor_sync(0xffffffffu, m, o));
    if (!lane) red[wrp] = m;
    __syncthreads();
    if (wrp == 0) {
        float t = red[lane & 7];
#pragma unroll
        for (int o = 4; o; o >>= 1) t = fmaxf(t, __shfl_xor_sync(0xffffffffu, t, o));
        if (!lane) red[0] = t;
    }
    __syncthreads();
    m = red[0];
    __syncthreads();
    v.x = __expf(v.x - m); v.y = __expf(v.y - m);
    v.z = __expf(v.z - m); v.w = __expf(v.w - m);
    float s = v.x + v.y + v.z + v.w;
#pragma unroll
    for (int o = 16; o; o >>= 1) s += __shfl_xor_sync(0xffffffffu, s, o);
    if (!lane) red[wrp] = s;
    __syncthreads();
    if (wrp == 0) {
        float t = red[lane & 7];
#pragma unroll
        for (int o = 4; o; o >>= 1) t += __shfl_xor_sync(0xffffffffu, t, o);
        if (!lane) red[0] = t;
    }
    __syncthreads();
    float inv = 1.0f / red[0];
    v.x *= inv; v.y *= inv; v.z *= inv; v.w *= inv;

    int n = tid * 4;
    char* p = g_attns + row * 4096 + (n >> 5) * 128 + (n & 31) * 2;
    __nv_bfloat162 h0, l0, h1, l1;
    split2(v.x, v.y, h0, l0);
    split2(v.z, v.w, h1, l1);
    *reinterpret_cast<__nv_bfloat162*>(p)      = h0;
    *reinterpret_cast<__nv_bfloat162*>(p + 4)  = h1;
    *reinterpret_cast<__nv_bfloat162*>(p + 64) = l0;
    *reinterpret_cast<__nv_bfloat162*>(p + 68) = l1;
}

// ---------------------------------------------------------------------------
// Stage 4: (attn @ v)^T -> ots sbf. grid (2, 8, 16)
// ---------------------------------------------------------------------------
__global__ void __launch_bounds__(NTHREADS, 2) av_kernel()
{
    extern __shared__ char smem[];
    int c0 = blockIdx.x * 128, tok0 = blockIdx.y * 128, b = blockIdx.z;
    float acc[4][4][4] = {};
    gemm_async(g_attns + ((size_t)b * NTOK + tok0) * 4096, 4096,
               g_vts + ((long)b * CDIM + c0) * 4096, 4096, NTOK / 32, smem, acc);
    epi_sbf_t(acc, g_ots + ((long)b * CDIM + c0) * 4096 + (tok0 >> 5) * 128, 4096, nullptr);
}

// ---------------------------------------------------------------------------
// Stage 5: z[b,p,c] = sum_n wpt[p][n] * ot[c][n] -> fp32 out. grid (2, 8, 16)
// ---------------------------------------------------------------------------
__global__ void __launch_bounds__(NTHREADS, 2) final_kernel(float* __restrict__ z)
{
    extern __shared__ char smem[];
    int c0 = blockIdx.x * 128, p0 = blockIdx.y * 128, b = blockIdx.z;
    float acc[4][4][4] = {};
    gemm_async(g_wpts + (long)p0 * 4096, 4096,
               g_ots + ((long)b * CDIM + c0) * 4096, 4096, NTOK / 32, smem, acc);
    epi_f32(acc, z + ((long)b * NTOK + p0) * CDIM + c0, CDIM);
}

// ---------------------------------------------------------------------------
extern "C" void kernel_launch(void* const* d_in, const int* in_sizes, int n_in,
                              void* d_out, int out_size)
{
    const float* x  = (const float*)d_in[0];
    const float* Wq = (const float*)d_in[1];
    const float* bq = (const float*)d_in[2];
    const float* Wk = (const float*)d_in[3];
    const float* bk = (const float*)d_in[4];
    const float* Wv = (const float*)d_in[5];
    const float* bv = (const float*)d_in[6];
    const float* Wp = (const float*)d_in[7];
    float* out = (float*)d_out;

    cudaFuncSetAttribute(proj_kernel,   cudaFuncAttributeMaxDynamicSharedMemorySize, SMEM_BYTES);
    cudaFuncSetAttribute(scores_kernel, cudaFuncAttributeMaxDynamicSharedMemorySize, SMEM_BYTES);
    cudaFuncSetAttribute(av_kernel,     cudaFuncAttributeMaxDynamicSharedMemorySize, SMEM_BYTES);
    cudaFuncSetAttribute(final_kernel,  cudaFuncAttributeMaxDynamicSharedMemorySize, SMEM_BYTES);

    char *d_xs, *d_ws;
    cudaGetSymbolAddress((void**)&d_xs, g_xs);
    cudaGetSymbolAddress((void**)&d_ws, g_ws);

    conv_kernel<<<dim3(4096), NTHREADS>>>(x, d_xs);                 // 16M floats
    conv_kernel<<<dim3(64),   NTHREADS>>>(Wq, d_ws);
    conv_kernel<<<dim3(64),   NTHREADS>>>(Wk, d_ws + 256*1024);
    conv_kernel<<<dim3(64),   NTHREADS>>>(Wv, d_ws + 2*256*1024);
    wpt_kernel<<<dim3(32, 32), NTHREADS>>>(Wp);

    proj_kernel<<<dim3(2, 128, 3), NTHREADS, SMEM_BYTES>>>(bq, bk, bv);
    scores_kernel<<<dim3(8, 8, 16), NTHREADS, SMEM_BYTES>>>();
    softmax_kernel<<<dim3(BATCH * NTOK), NTHREADS>>>();
    av_kernel<<<dim3(2, 8, 16), NTHREADS, SMEM_BYTES>>>();
    final_kernel<<<dim3(2, 8, 16), NTHREADS, SMEM_BYTES>>>(out);
}

// round 6
// speedup vs baseline: 2.6238x; 1.0493x over previous
#include <cuda_runtime.h>
#include <cuda_bf16.h>
#include <cstdint>

#define BATCH 16
#define NTOK  1024
#define CDIM  256
#define NTHREADS 256
#define NSTAGE 3
#define SLABB 16384                    // one matrix slab: 128 rows x 128B
#define STAGEB (2*SLABB)               // A + B
#define SMEM_BYTES (NSTAGE*STAGEB)     // 98304

// ---------------------------------------------------------------------------
// Scratch. "sbf" format: row-major, per row the K dim is split into groups of
// 32; group g occupies 128 bytes: [64B hi bf16 | 64B lo bf16]. Row stride in
// bytes = K*4 (same as fp32).
// ---------------------------------------------------------------------------
__device__ __align__(128) char g_xs  [16384*1024];     // x sbf (rows tok, K=256)
__device__ __align__(128) char g_ws  [3*256*1024];     // Wq|Wk|Wv sbf
__device__ __align__(128) char g_qs  [16384*1024];     // q sbf
__device__ __align__(128) char g_ks  [16384*1024];     // k sbf
__device__ __align__(128) char g_vts [16*256*4096];    // v^T sbf (rows c, K=n)
__device__ __align__(128) char g_ots [16*256*4096];    // (attn v)^T sbf, normalized
__device__ __align__(128) char g_attns[(size_t)16384*4096]; // exp(scores) sbf (rows tok, K=n)
__device__ __align__(128) char g_wpts[1024*4096];      // Wp^T sbf (rows p, K=n)
__device__ float g_zp[BATCH*8*NTOK];                   // per (b, n-tile, tok) exp-sums

// ---------------------------------------------------------------------------
__device__ __forceinline__ uint32_t smem_u32(const void* p){
    uint32_t a;
    asm("{ .reg .u64 t; cvta.to.shared.u64 t, %1; cvt.u32.u64 %0, t; }" : "=r"(a) : "l"(p));
    return a;
}
__device__ __forceinline__ void ldsm4(uint32_t* r, uint32_t addr){
    asm volatile("ldmatrix.sync.aligned.m8n8.x4.shared.b16 {%0,%1,%2,%3}, [%4];"
        : "=r"(r[0]), "=r"(r[1]), "=r"(r[2]), "=r"(r[3]) : "r"(addr));
}
__device__ __forceinline__ void mma_bf16(float* d, const uint32_t* a, const uint32_t* b){
    asm volatile("mma.sync.aligned.m16n8k16.row.col.f32.bf16.bf16.f32 "
        "{%0,%1,%2,%3}, {%4,%5,%6,%7}, {%8,%9}, {%0,%1,%2,%3};"
        : "+f"(d[0]), "+f"(d[1]), "+f"(d[2]), "+f"(d[3])
        : "r"(a[0]), "r"(a[1]), "r"(a[2]), "r"(a[3]), "r"(b[0]), "r"(b[1]));
}
__device__ __forceinline__ void split2(float v0, float v1,
        __nv_bfloat162& h, __nv_bfloat162& l){
    h = __floats2bfloat162_rn(v0, v1);
    l = __floats2bfloat162_rn(v0 - __low2float(h), v1 - __high2float(h));
}

// ---------------------------------------------------------------------------
// cp.async one slab: 128 rows x 8 16B-chunks, swizzled chunk = cc ^ (r&7).
// ---------------------------------------------------------------------------
__device__ __forceinline__ void load_slab_async(char* slab, const char* __restrict__ src, long ld)
{
    int tid = threadIdx.x;
#pragma unroll
    for (int i = 0; i < 4; ++i) {
        int idx = tid + i * 256;
        int r = idx >> 3, cc = idx & 7;
        uint32_t dst = smem_u32(slab + r * 128 + ((cc ^ (r & 7)) << 4));
        const char* s = src + (long)r * ld + cc * 16;
        asm volatile("cp.async.cg.shared.global [%0], [%1], 16;" :: "r"(dst), "l"(s));
    }
}

// ---------------------------------------------------------------------------
// One K=32 slab of MMAs. 8 warps in 2(M)x4(N); warp tile 64x32.
// ---------------------------------------------------------------------------
__device__ __forceinline__ void compute_slab(char* buf, float acc[4][4][4])
{
    int tid = threadIdx.x, lane = tid & 31, wid = tid >> 5;
    uint32_t sA = smem_u32(buf), sB = sA + SLABB;
    int mw = (wid & 1) * 64, nw = (wid >> 1) * 32;
    int arow = lane & 15, ahalf = lane >> 4;
    int brow = (lane & 7) + ((lane >> 4) & 1) * 8, bhalf = (lane >> 3) & 1;

#pragma unroll
    for (int ks = 0; ks < 2; ++ks) {
        uint32_t bh[8], bl[8];
#pragma unroll
        for (int nj = 0; nj < 2; ++nj) {
            int r = nw + nj * 16 + brow;
            int c = ks * 2 + bhalf;
            ldsm4(bh + nj * 4, sB + r * 128 + (((c    ) ^ (r & 7)) << 4));
            ldsm4(bl + nj * 4, sB + r * 128 + (((c + 4) ^ (r & 7)) << 4));
        }
#pragma unroll
        for (int mi = 0; mi < 4; ++mi) {
            int r = mw + mi * 16 + arow;
            int c = ks * 2 + ahalf;
            uint32_t ah[4], al[4];
            ldsm4(ah, sA + r * 128 + (((c    ) ^ (r & 7)) << 4));
            ldsm4(al, sA + r * 128 + (((c + 4) ^ (r & 7)) << 4));
#pragma unroll
            for (int j = 0; j < 4; ++j) {
                const uint32_t* bhf = &bh[(j >> 1) * 4 + (j & 1) * 2];
                const uint32_t* blf = &bl[(j >> 1) * 4 + (j & 1) * 2];
                float* d = acc[mi][j];
                mma_bf16(d, ah, bhf);
                mma_bf16(d, al, bhf);
                mma_bf16(d, ah, blf);
            }
        }
    }
}

// ---------------------------------------------------------------------------
// 3-stage cp.async GEMM mainloop over sbf operands.
// ---------------------------------------------------------------------------
__device__ __forceinline__ void gemm_async(const char* __restrict__ A, long ldA,
                                           const char* __restrict__ B, long ldB,
                                           int NC, char* smem, float acc[4][4][4])
{
#pragma unroll
    for (int s = 0; s < NSTAGE - 1; ++s) {
        char* b = smem + s * STAGEB;
        load_slab_async(b,         A + (long)s * 128, ldA);
        load_slab_async(b + SLABB, B + (long)s * 128, ldB);
        asm volatile("cp.async.commit_group;" ::: "memory");
    }
    for (int c = 0; c < NC; ++c) {
        asm volatile("cp.async.wait_group %0;" :: "n"(NSTAGE - 2) : "memory");
        __syncthreads();
        int nc = c + NSTAGE - 1;
        if (nc < NC) {
            char* b = smem + (nc % NSTAGE) * STAGEB;
            load_slab_async(b,         A + (long)nc * 128, ldA);
            load_slab_async(b + SLABB, B + (long)nc * 128, ldB);
        }
        asm volatile("cp.async.commit_group;" ::: "memory");
        compute_slab(smem + (c % NSTAGE) * STAGEB, acc);
    }
}

// ---------------------------------------------------------------------------
// Epilogues. Frag: d0,d1 -> (row=lane>>2, col=(lane&3)*2 + e), d2,d3 row+8.
// ---------------------------------------------------------------------------
__device__ __forceinline__ void epi_f32(const float acc[4][4][4],
        float* __restrict__ Cg, int ldc)
{
    int tid = threadIdx.x, lane = tid & 31, wid = tid >> 5;
    int row0 = (wid & 1) * 64 + (lane >> 2), col0 = (wid >> 1) * 32 + (lane & 3) * 2;
#pragma unroll
    for (int mi = 0; mi < 4; ++mi)
#pragma unroll
        for (int j = 0; j < 4; ++j) {
            int c = col0 + j * 8;
#pragma unroll
            for (int h = 0; h < 2; ++h) {
                int r = row0 + mi * 16 + h * 8;
                *reinterpret_cast<float2*>(Cg + (long)r * ldc + c) =
                    make_float2(acc[mi][j][h * 2], acc[mi][j][h * 2 + 1]);
            }
        }
}

// write C(128x128) in sbf at base (col origin folded, col0%32==0)
__device__ __forceinline__ void epi_sbf(const float acc[4][4][4],
        char* base, long ld, const float* __restrict__ bias)
{
    int tid = threadIdx.x, lane = tid & 31, wid = tid >> 5;
    int row0 = (wid & 1) * 64 + (lane >> 2), col0 = (wid >> 1) * 32 + (lane & 3) * 2;
#pragma unroll
    for (int mi = 0; mi < 4; ++mi)
#pragma unroll
        for (int j = 0; j < 4; ++j) {
            int c = col0 + j * 8;
            float b0 = bias ? bias[c] : 0.0f, b1 = bias ? bias[c + 1] : 0.0f;
#pragma unroll
            for (int h = 0; h < 2; ++h) {
                int r = row0 + mi * 16 + h * 8;
                __nv_bfloat162 hh, ll;
                split2(acc[mi][j][h * 2] + b0, acc[mi][j][h * 2 + 1] + b1, hh, ll);
                char* p = base + (long)r * ld + (c >> 5) * 128 + (c & 31) * 2;
                *reinterpret_cast<__nv_bfloat162*>(p)      = hh;
                *reinterpret_cast<__nv_bfloat162*>(p + 64) = ll;
            }
        }
}

// transposed sbf with optional per-m scale: element (m,n) -> row n, k-pos m
__device__ __forceinline__ void epi_sbf_t(const float acc[4][4][4],
        char* base, long ld, const float* __restrict__ bias,
        const float* __restrict__ rz /* smem [128] per-m scale or null */)
{
    int tid = threadIdx.x, lane = tid & 31, wid = tid >> 5;
    int row0 = (wid & 1) * 64 + (lane >> 2), col0 = (wid >> 1) * 32 + (lane & 3) * 2;
#pragma unroll
    for (int mi = 0; mi < 4; ++mi)
#pragma unroll
        for (int j = 0; j < 4; ++j)
#pragma unroll
            for (int h = 0; h < 2; ++h) {
                int m = row0 + mi * 16 + h * 8;
                float sc = rz ? rz[m] : 1.0f;
#pragma unroll
                for (int e = 0; e < 2; ++e) {
                    int n = col0 + j * 8 + e;
                    float v = acc[mi][j][h * 2 + e] * sc + (bias ? bias[n] : 0.0f);
                    __nv_bfloat16 hb = __float2bfloat16(v);
                    __nv_bfloat16 lb = __float2bfloat16(v - __bfloat162float(hb));
                    char* p = base + (long)n * ld + (m >> 5) * 128 + (m & 31) * 2;
                    *reinterpret_cast<__nv_bfloat16*>(p)      = hb;
                    *reinterpret_cast<__nv_bfloat16*>(p + 64) = lb;
                }
            }
}

// exp + attn-sbf store + deterministic per-row partial sums -> g_zp
__device__ __forceinline__ void epi_attn(const float acc[4][4][4], char* smem,
        char* base, long ld, float* __restrict__ zp_out /* &g_zp[b][nt][m0] */)
{
    int tid = threadIdx.x, lane = tid & 31, wid = tid >> 5;
    int row0 = (wid & 1) * 64 + (lane >> 2), col0 = (wid >> 1) * 32 + (lane & 3) * 2;
    float* zsm = reinterpret_cast<float*>(smem);     // [4 nwarp][128 rows]
    __syncthreads();                                 // smem free after mainloop

    float ex[4][4][4];
#pragma unroll
    for (int mi = 0; mi < 4; ++mi) {
#pragma unroll
        for (int h = 0; h < 2; ++h) {
            float rs = 0.0f;
#pragma unroll
            for (int j = 0; j < 4; ++j) {
                float e0 = __expf(acc[mi][j][h * 2]);
                float e1 = __expf(acc[mi][j][h * 2 + 1]);
                ex[mi][j][h * 2] = e0; ex[mi][j][h * 2 + 1] = e1;
                rs += e0 + e1;
            }
            rs += __shfl_xor_sync(0xffffffffu, rs, 1);
            rs += __shfl_xor_sync(0xffffffffu, rs, 2);
            if ((lane & 3) == 0) {
                int rloc = row0 + mi * 16 + h * 8;
                zsm[(wid >> 1) * 128 + rloc] = rs;
            }
        }
    }
    __syncthreads();
    if (tid < 128) {
        float z = zsm[tid] + zsm[128 + tid] + zsm[256 + tid] + zsm[384 + tid];
        zp_out[tid] = z;
    }
    // sbf store of exp values
#pragma unroll
    for (int mi = 0; mi < 4; ++mi)
#pragma unroll
        for (int j = 0; j < 4; ++j) {
            int c = col0 + j * 8;
#pragma unroll
            for (int h = 0; h < 2; ++h) {
                int r = row0 + mi * 16 + h * 8;
                __nv_bfloat162 hh, ll;
                split2(ex[mi][j][h * 2], ex[mi][j][h * 2 + 1], hh, ll);
                char* p = base + (long)r * ld + (c >> 5) * 128 + (c & 31) * 2;
                *reinterpret_cast<__nv_bfloat162*>(p)      = hh;
                *reinterpret_cast<__nv_bfloat162*>(p + 64) = ll;
            }
        }
}

// ---------------------------------------------------------------------------
// fp32 array -> sbf
// ---------------------------------------------------------------------------
__global__ void __launch_bounds__(NTHREADS) conv_kernel(const float* __restrict__ src,
        char* __restrict__ dst)
{
    long i = (long)blockIdx.x * NTHREADS + threadIdx.x;
    float4 v = reinterpret_cast<const float4*>(src)[i];
    long e = i * 4;
    char* p = dst + (e & ~31L) * 4 + (e & 31) * 2;
    __nv_bfloat162 h0, l0, h1, l1;
    split2(v.x, v.y, h0, l0);
    split2(v.z, v.w, h1, l1);
    *reinterpret_cast<__nv_bfloat162*>(p)      = h0;
    *reinterpret_cast<__nv_bfloat162*>(p + 4)  = h1;
    *reinterpret_cast<__nv_bfloat162*>(p + 64) = l0;
    *reinterpret_cast<__nv_bfloat162*>(p + 68) = l1;
}

// Wp[h][n][w] -> wpts sbf row p=h*32+w, k=n
__global__ void __launch_bounds__(NTHREADS) wpt_kernel(const float* __restrict__ Wp)
{
    __shared__ float t[32][33];
    int h = blockIdx.x, n0 = blockIdx.y * 32;
    int tx = threadIdx.x & 31, ty = threadIdx.x >> 5;
    const float* src = Wp + (long)h * 32768 + (long)n0 * 32;
#pragma unroll
    for (int i = 0; i < 4; ++i) t[ty + i * 8][tx] = src[(ty + i * 8) * 32 + tx];
    __syncthreads();
#pragma unroll
    for (int i = 0; i < 4; ++i) {
        int w = ty + i * 8;
        float v = t[tx][w];
        int n = n0 + tx;
        __nv_bfloat16 hb = __float2bfloat16(v);
        __nv_bfloat16 lb = __float2bfloat16(v - __bfloat162float(hb));
        char* p = g_wpts + ((long)h * 32 + w) * 4096 + (n >> 5) * 128 + (n & 31) * 2;
        *reinterpret_cast<__nv_bfloat16*>(p)      = hb;
        *reinterpret_cast<__nv_bfloat16*>(p + 64) = lb;
    }
}

// ---------------------------------------------------------------------------
// Stage 1: proj. grid (2, 128, 3). q/k -> sbf normal; v -> sbf transposed.
// ---------------------------------------------------------------------------
__global__ void __launch_bounds__(NTHREADS, 2)
proj_kernel(const float* __restrict__ bq, const float* __restrict__ bk,
            const float* __restrict__ bv)
{
    extern __shared__ char smem[];
    int n0 = blockIdx.x * 128; long m0 = (long)blockIdx.y * 128; int sel = blockIdx.z;
    const float* bias = sel == 0 ? bq : sel == 1 ? bk : bv;
    float acc[4][4][4] = {};
    gemm_async(g_xs + m0 * 1024, 1024,
               g_ws + ((long)sel * 256 + n0) * 1024, 1024, CDIM / 32, smem, acc);
    if (sel < 2) {
        char* out = sel == 0 ? g_qs : g_ks;
        epi_sbf(acc, out + m0 * 1024 + (n0 >> 5) * 128, 1024, bias + n0);
    } else {
        int b = (int)(m0 >> 10), tok0 = (int)(m0 & 1023);
        epi_sbf_t(acc, g_vts + ((long)b * CDIM + n0) * 4096 + (tok0 >> 5) * 128, 4096,
                  bias + n0, nullptr);
    }
}

// ---------------------------------------------------------------------------
// Stage 2: attn_un = exp(q k^T) -> sbf + row partial sums. grid (8, 8, 16)
// ---------------------------------------------------------------------------
__global__ void __launch_bounds__(NTHREADS, 2) scores_kernel()
{
    extern __shared__ char smem[];
    int n0 = blockIdx.x * 128, m0 = blockIdx.y * 128, b = blockIdx.z;
    float acc[4][4][4] = {};
    gemm_async(g_qs + ((long)b * NTOK + m0) * 1024, 1024,
               g_ks + ((long)b * NTOK + n0) * 1024, 1024, CDIM / 32, smem, acc);
    char* base = g_attns + ((size_t)b * NTOK + m0) * 4096 + (n0 >> 5) * 128;
    epi_attn(acc, smem, base, 4096, g_zp + ((long)b * 8 + blockIdx.x) * NTOK + m0);
}

// ---------------------------------------------------------------------------
// Stage 3: o^T = (attn_un @ v)^T / Z -> ots sbf. grid (2, 8, 16)
// ---------------------------------------------------------------------------
__global__ void __launch_bounds__(NTHREADS, 2) av_kernel()
{
    extern __shared__ char smem[];
    int c0 = blockIdx.x * 128, tok0 = blockIdx.y * 128, b = blockIdx.z;
    float acc[4][4][4] = {};
    gemm_async(g_attns + ((size_t)b * NTOK + tok0) * 4096, 4096,
               g_vts + ((long)b * CDIM + c0) * 4096, 4096, NTOK / 32, smem, acc);
    __syncthreads();
    float* rzs = reinterpret_cast<float*>(smem);    // [128]
    if (threadIdx.x < 128) {
        float z = 0.0f;
#pragma unroll
        for (int t = 0; t < 8; ++t)
            z += g_zp[((long)b * 8 + t) * NTOK + tok0 + threadIdx.x];
        rzs[threadIdx.x] = 1.0f / z;
    }
    __syncthreads();
    epi_sbf_t(acc, g_ots + ((long)b * CDIM + c0) * 4096 + (tok0 >> 5) * 128, 4096,
              nullptr, rzs);
}

// ---------------------------------------------------------------------------
// Stage 4: z[b,p,c] = sum_n wpt[p][n] * ot[c][n] -> fp32 out. grid (2, 8, 16)
// ---------------------------------------------------------------------------
__global__ void __launch_bounds__(NTHREADS, 2) final_kernel(float* __restrict__ z)
{
    extern __shared__ char smem[];
    int c0 = blockIdx.x * 128, p0 = blockIdx.y * 128, b = blockIdx.z;
    float acc[4][4][4] = {};
    gemm_async(g_wpts + (long)p0 * 4096, 4096,
               g_ots + ((long)b * CDIM + c0) * 4096, 4096, NTOK / 32, smem, acc);
    epi_f32(acc, z + ((long)b * NTOK + p0) * CDIM + c0, CDIM);
}

// ---------------------------------------------------------------------------
extern "C" void kernel_launch(void* const* d_in, const int* in_sizes, int n_in,
                              void* d_out, int out_size)
{
    const float* x  = (const float*)d_in[0];
    const float* Wq = (const float*)d_in[1];
    const float* bq = (const float*)d_in[2];
    const float* Wk = (const float*)d_in[3];
    const float* bk = (const float*)d_in[4];
    const float* Wv = (const float*)d_in[5];
    const float* bv = (const float*)d_in[6];
    const float* Wp = (const float*)d_in[7];
    float* out = (float*)d_out;

    cudaFuncSetAttribute(proj_kernel,   cudaFuncAttributeMaxDynamicSharedMemorySize, SMEM_BYTES);
    cudaFuncSetAttribute(scores_kernel, cudaFuncAttributeMaxDynamicSharedMemorySize, SMEM_BYTES);
    cudaFuncSetAttribute(av_kernel,     cudaFuncAttributeMaxDynamicSharedMemorySize, SMEM_BYTES);
    cudaFuncSetAttribute(final_kernel,  cudaFuncAttributeMaxDynamicSharedMemorySize, SMEM_BYTES);

    char *d_xs, *d_ws;
    cudaGetSymbolAddress((void**)&d_xs, g_xs);
    cudaGetSymbolAddress((void**)&d_ws, g_ws);

    conv_kernel<<<dim3(4096), NTHREADS>>>(x, d_xs);
    conv_kernel<<<dim3(64),   NTHREADS>>>(Wq, d_ws);
    conv_kernel<<<dim3(64),   NTHREADS>>>(Wk, d_ws + 256*1024);
    conv_kernel<<<dim3(64),   NTHREADS>>>(Wv, d_ws + 2*256*1024);
    wpt_kernel<<<dim3(32, 32), NTHREADS>>>(Wp);

    proj_kernel<<<dim3(2, 128, 3), NTHREADS, SMEM_BYTES>>>(bq, bk, bv);
    scores_kernel<<<dim3(8, 8, 16), NTHREADS, SMEM_BYTES>>>();
    av_kernel<<<dim3(2, 8, 16), NTHREADS, SMEM_BYTES>>>();
    final_kernel<<<dim3(2, 8, 16), NTHREADS, SMEM_BYTES>>>(out);
}

// round 7
// speedup vs baseline: 2.6240x; 1.0001x over previous
#include <cuda_runtime.h>
#include <cuda_bf16.h>
#include <cstdint>

#define BATCH 16
#define NTOK  1024
#define CDIM  256
#define NTHREADS 256
#define NSTAGE 3
#define SLABB 16384                    // 128-row slab: 128 x 128B
#define SLABB2 32768                   // 256-row slab
#define STAGEB (2*SLABB)               // narrow stage: A + B
#define SMEM_BYTES (NSTAGE*STAGEB)     // 98304
#define STAGEB_W (SLABB + SLABB2)      // wide stage: A(128) + B(256)
#define SMEM_W (NSTAGE*STAGEB_W)       // 147456

// ---------------------------------------------------------------------------
// "sbf" format: row-major; K split into groups of 32; group = 128B:
// [64B hi bf16 | 64B lo bf16]. Row stride bytes = K*4.
// ---------------------------------------------------------------------------
__device__ __align__(128) char g_xs  [16384*1024];
__device__ __align__(128) char g_ws  [3*256*1024];
__device__ __align__(128) char g_qs  [16384*1024];
__device__ __align__(128) char g_ks  [16384*1024];
__device__ __align__(128) char g_vts [16*256*4096];
__device__ __align__(128) char g_ots [16*256*4096];
__device__ __align__(128) char g_attns[(size_t)16384*4096];
__device__ __align__(128) char g_wpts[1024*4096];
__device__ float g_zp[BATCH*8*NTOK];

// ---------------------------------------------------------------------------
__device__ __forceinline__ uint32_t smem_u32(const void* p){
    uint32_t a;
    asm("{ .reg .u64 t; cvta.to.shared.u64 t, %1; cvt.u32.u64 %0, t; }" : "=r"(a) : "l"(p));
    return a;
}
__device__ __forceinline__ void ldsm4(uint32_t* r, uint32_t addr){
    asm volatile("ldmatrix.sync.aligned.m8n8.x4.shared.b16 {%0,%1,%2,%3}, [%4];"
        : "=r"(r[0]), "=r"(r[1]), "=r"(r[2]), "=r"(r[3]) : "r"(addr));
}
__device__ __forceinline__ void mma_bf16(float* d, const uint32_t* a, const uint32_t* b){
    asm volatile("mma.sync.aligned.m16n8k16.row.col.f32.bf16.bf16.f32 "
        "{%0,%1,%2,%3}, {%4,%5,%6,%7}, {%8,%9}, {%0,%1,%2,%3};"
        : "+f"(d[0]), "+f"(d[1]), "+f"(d[2]), "+f"(d[3])
        : "r"(a[0]), "r"(a[1]), "r"(a[2]), "r"(a[3]), "r"(b[0]), "r"(b[1]));
}
__device__ __forceinline__ void split2(float v0, float v1,
        __nv_bfloat162& h, __nv_bfloat162& l){
    h = __floats2bfloat162_rn(v0, v1);
    l = __floats2bfloat162_rn(v0 - __low2float(h), v1 - __high2float(h));
}

// ---------------------------------------------------------------------------
// cp.async slab loader (ROWS x 128B, swizzled chunk = cc ^ (r&7))
// ---------------------------------------------------------------------------
template<int ROWS>
__device__ __forceinline__ void load_slab_async(char* slab, const char* __restrict__ src, long ld)
{
    int tid = threadIdx.x;
#pragma unroll
    for (int i = 0; i < ROWS / 32; ++i) {
        int idx = tid + i * 256;
        int r = idx >> 3, cc = idx & 7;
        uint32_t dst = smem_u32(slab + r * 128 + ((cc ^ (r & 7)) << 4));
        const char* s = src + (long)r * ld + cc * 16;
        asm volatile("cp.async.cg.shared.global [%0], [%1], 16;" :: "r"(dst), "l"(s));
    }
}

// ---------------------------------------------------------------------------
// Narrow compute: CTA 128x128, warps 2(M)x4(N), warp tile 64x32.
// ---------------------------------------------------------------------------
__device__ __forceinline__ void compute_slab(char* buf, float acc[4][4][4])
{
    int tid = threadIdx.x, lane = tid & 31, wid = tid >> 5;
    uint32_t sA = smem_u32(buf), sB = sA + SLABB;
    int mw = (wid & 1) * 64, nw = (wid >> 1) * 32;
    int arow = lane & 15, ahalf = lane >> 4;
    int brow = (lane & 7) + ((lane >> 4) & 1) * 8, bhalf = (lane >> 3) & 1;

#pragma unroll
    for (int ks = 0; ks < 2; ++ks) {
        uint32_t bh[8], bl[8];
#pragma unroll
        for (int nj = 0; nj < 2; ++nj) {
            int r = nw + nj * 16 + brow;
            int c = ks * 2 + bhalf;
            ldsm4(bh + nj * 4, sB + r * 128 + (((c    ) ^ (r & 7)) << 4));
            ldsm4(bl + nj * 4, sB + r * 128 + (((c + 4) ^ (r & 7)) << 4));
        }
#pragma unroll
        for (int mi = 0; mi < 4; ++mi) {
            int r = mw + mi * 16 + arow;
            int c = ks * 2 + ahalf;
            uint32_t ah[4], al[4];
            ldsm4(ah, sA + r * 128 + (((c    ) ^ (r & 7)) << 4));
            ldsm4(al, sA + r * 128 + (((c + 4) ^ (r & 7)) << 4));
#pragma unroll
            for (int j = 0; j < 4; ++j) {
                const uint32_t* bhf = &bh[(j >> 1) * 4 + (j & 1) * 2];
                const uint32_t* blf = &bl[(j >> 1) * 4 + (j & 1) * 2];
                float* d = acc[mi][j];
                mma_bf16(d, ah, bhf);
                mma_bf16(d, al, bhf);
                mma_bf16(d, ah, blf);
            }
        }
    }
}

// ---------------------------------------------------------------------------
// Wide compute: CTA 128x256, warps 2(M)x4(N), warp tile 64x64.
// ---------------------------------------------------------------------------
__device__ __forceinline__ void compute_slab_w(char* buf, float acc[4][8][4])
{
    int tid = threadIdx.x, lane = tid & 31, wid = tid >> 5;
    uint32_t sA = smem_u32(buf), sB = sA + SLABB;
    int mw = (wid & 1) * 64, nw = (wid >> 1) * 64;
    int arow = lane & 15, ahalf = lane >> 4;
    int brow = (lane & 7) + ((lane >> 4) & 1) * 8, bhalf = (lane >> 3) & 1;

#pragma unroll
    for (int ks = 0; ks < 2; ++ks) {
        uint32_t bh[16], bl[16];
#pragma unroll
        for (int nj = 0; nj < 4; ++nj) {
            int r = nw + nj * 16 + brow;
            int c = ks * 2 + bhalf;
            ldsm4(bh + nj * 4, sB + r * 128 + (((c    ) ^ (r & 7)) << 4));
            ldsm4(bl + nj * 4, sB + r * 128 + (((c + 4) ^ (r & 7)) << 4));
        }
#pragma unroll
        for (int mi = 0; mi < 4; ++mi) {
            int r = mw + mi * 16 + arow;
            int c = ks * 2 + ahalf;
            uint32_t ah[4], al[4];
            ldsm4(ah, sA + r * 128 + (((c    ) ^ (r & 7)) << 4));
            ldsm4(al, sA + r * 128 + (((c + 4) ^ (r & 7)) << 4));
#pragma unroll
            for (int j = 0; j < 8; ++j) {
                const uint32_t* bhf = &bh[(j >> 1) * 4 + (j & 1) * 2];
                const uint32_t* blf = &bl[(j >> 1) * 4 + (j & 1) * 2];
                float* d = acc[mi][j];
                mma_bf16(d, ah, bhf);
                mma_bf16(d, al, bhf);
                mma_bf16(d, ah, blf);
            }
        }
    }
}

// ---------------------------------------------------------------------------
// Mainloops
// ---------------------------------------------------------------------------
__device__ __forceinline__ void gemm_async(const char* __restrict__ A, long ldA,
                                           const char* __restrict__ B, long ldB,
                                           int NC, char* smem, float acc[4][4][4])
{
#pragma unroll
    for (int s = 0; s < NSTAGE - 1; ++s) {
        char* b = smem + s * STAGEB;
        load_slab_async<128>(b,         A + (long)s * 128, ldA);
        load_slab_async<128>(b + SLABB, B + (long)s * 128, ldB);
        asm volatile("cp.async.commit_group;" ::: "memory");
    }
    for (int c = 0; c < NC; ++c) {
        asm volatile("cp.async.wait_group %0;" :: "n"(NSTAGE - 2) : "memory");
        __syncthreads();
        int nc = c + NSTAGE - 1;
        if (nc < NC) {
            char* b = smem + (nc % NSTAGE) * STAGEB;
            load_slab_async<128>(b,         A + (long)nc * 128, ldA);
            load_slab_async<128>(b + SLABB, B + (long)nc * 128, ldB);
        }
        asm volatile("cp.async.commit_group;" ::: "memory");
        compute_slab(smem + (c % NSTAGE) * STAGEB, acc);
    }
}

__device__ __forceinline__ void gemm_async_w(const char* __restrict__ A, long ldA,
                                             const char* __restrict__ B, long ldB,
                                             int NC, char* smem, float acc[4][8][4])
{
#pragma unroll
    for (int s = 0; s < NSTAGE - 1; ++s) {
        char* b = smem + s * STAGEB_W;
        load_slab_async<128>(b,         A + (long)s * 128, ldA);
        load_slab_async<256>(b + SLABB, B + (long)s * 128, ldB);
        asm volatile("cp.async.commit_group;" ::: "memory");
    }
    for (int c = 0; c < NC; ++c) {
        asm volatile("cp.async.wait_group %0;" :: "n"(NSTAGE - 2) : "memory");
        __syncthreads();
        int nc = c + NSTAGE - 1;
        if (nc < NC) {
            char* b = smem + (nc % NSTAGE) * STAGEB_W;
            load_slab_async<128>(b,         A + (long)nc * 128, ldA);
            load_slab_async<256>(b + SLABB, B + (long)nc * 128, ldB);
        }
        asm volatile("cp.async.commit_group;" ::: "memory");
        compute_slab_w(smem + (c % NSTAGE) * STAGEB_W, acc);
    }
}

// ---------------------------------------------------------------------------
// Epilogues. Frag: d0,d1 -> (row=lane>>2, col=(lane&3)*2+e), d2,d3 row+8.
// ---------------------------------------------------------------------------
__device__ __forceinline__ void epi_sbf(const float acc[4][4][4],
        char* base, long ld, const float* __restrict__ bias)
{
    int tid = threadIdx.x, lane = tid & 31, wid = tid >> 5;
    int row0 = (wid & 1) * 64 + (lane >> 2), col0 = (wid >> 1) * 32 + (lane & 3) * 2;
#pragma unroll
    for (int mi = 0; mi < 4; ++mi)
#pragma unroll
        for (int j = 0; j < 4; ++j) {
            int c = col0 + j * 8;
            float b0 = bias ? bias[c] : 0.0f, b1 = bias ? bias[c + 1] : 0.0f;
#pragma unroll
            for (int h = 0; h < 2; ++h) {
                int r = row0 + mi * 16 + h * 8;
                __nv_bfloat162 hh, ll;
                split2(acc[mi][j][h * 2] + b0, acc[mi][j][h * 2 + 1] + b1, hh, ll);
                char* p = base + (long)r * ld + (c >> 5) * 128 + (c & 31) * 2;
                *reinterpret_cast<__nv_bfloat162*>(p)      = hh;
                *reinterpret_cast<__nv_bfloat162*>(p + 64) = ll;
            }
        }
}

__device__ __forceinline__ void epi_sbf_t(const float acc[4][4][4],
        char* base, long ld, const float* __restrict__ bias)
{
    int tid = threadIdx.x, lane = tid & 31, wid = tid >> 5;
    int row0 = (wid & 1) * 64 + (lane >> 2), col0 = (wid >> 1) * 32 + (lane & 3) * 2;
#pragma unroll
    for (int mi = 0; mi < 4; ++mi)
#pragma unroll
        for (int j = 0; j < 4; ++j)
#pragma unroll
            for (int h = 0; h < 2; ++h) {
                int m = row0 + mi * 16 + h * 8;
#pragma unroll
                for (int e = 0; e < 2; ++e) {
                    int n = col0 + j * 8 + e;
                    float v = acc[mi][j][h * 2 + e] + (bias ? bias[n] : 0.0f);
                    __nv_bfloat16 hb = __float2bfloat16(v);
                    __nv_bfloat16 lb = __float2bfloat16(v - __bfloat162float(hb));
                    char* p = base + (long)n * ld + (m >> 5) * 128 + (m & 31) * 2;
                    *reinterpret_cast<__nv_bfloat16*>(p)      = hb;
                    *reinterpret_cast<__nv_bfloat16*>(p + 64) = lb;
                }
            }
}

// wide transposed sbf with per-m scale (av)
__device__ __forceinline__ void epi_sbf_t_w(const float acc[4][8][4],
        char* base, long ld, const float* __restrict__ rz)
{
    int tid = threadIdx.x, lane = tid & 31, wid = tid >> 5;
    int row0 = (wid & 1) * 64 + (lane >> 2), col0 = (wid >> 1) * 64 + (lane & 3) * 2;
#pragma unroll
    for (int mi = 0; mi < 4; ++mi)
#pragma unroll
        for (int j = 0; j < 8; ++j)
#pragma unroll
            for (int h = 0; h < 2; ++h) {
                int m = row0 + mi * 16 + h * 8;
                float sc = rz[m];
#pragma unroll
                for (int e = 0; e < 2; ++e) {
                    int n = col0 + j * 8 + e;
                    float v = acc[mi][j][h * 2 + e] * sc;
                    __nv_bfloat16 hb = __float2bfloat16(v);
                    __nv_bfloat16 lb = __float2bfloat16(v - __bfloat162float(hb));
                    char* p = base + (long)n * ld + (m >> 5) * 128 + (m & 31) * 2;
                    *reinterpret_cast<__nv_bfloat16*>(p)      = hb;
                    *reinterpret_cast<__nv_bfloat16*>(p + 64) = lb;
                }
            }
}

// wide fp32 store (final)
__device__ __forceinline__ void epi_f32_w(const float acc[4][8][4],
        float* __restrict__ Cg, int ldc)
{
    int tid = threadIdx.x, lane = tid & 31, wid = tid >> 5;
    int row0 = (wid & 1) * 64 + (lane >> 2), col0 = (wid >> 1) * 64 + (lane & 3) * 2;
#pragma unroll
    for (int mi = 0; mi < 4; ++mi)
#pragma unroll
        for (int j = 0; j < 8; ++j) {
            int c = col0 + j * 8;
#pragma unroll
            for (int h = 0; h < 2; ++h) {
                int r = row0 + mi * 16 + h * 8;
                *reinterpret_cast<float2*>(Cg + (long)r * ldc + c) =
                    make_float2(acc[mi][j][h * 2], acc[mi][j][h * 2 + 1]);
            }
        }
}

// exp + attn-sbf store + deterministic per-row partial sums -> g_zp
__device__ __forceinline__ void epi_attn(const float acc[4][4][4], char* smem,
        char* base, long ld, float* __restrict__ zp_out)
{
    int tid = threadIdx.x, lane = tid & 31, wid = tid >> 5;
    int row0 = (wid & 1) * 64 + (lane >> 2), col0 = (wid >> 1) * 32 + (lane & 3) * 2;
    float* zsm = reinterpret_cast<float*>(smem);
    __syncthreads();

    float ex[4][4][4];
#pragma unroll
    for (int mi = 0; mi < 4; ++mi) {
#pragma unroll
        for (int h = 0; h < 2; ++h) {
            float rs = 0.0f;
#pragma unroll
            for (int j = 0; j < 4; ++j) {
                float e0 = __expf(acc[mi][j][h * 2]);
                float e1 = __expf(acc[mi][j][h * 2 + 1]);
                ex[mi][j][h * 2] = e0; ex[mi][j][h * 2 + 1] = e1;
                rs += e0 + e1;
            }
            rs += __shfl_xor_sync(0xffffffffu, rs, 1);
            rs += __shfl_xor_sync(0xffffffffu, rs, 2);
            if ((lane & 3) == 0) {
                int rloc = row0 + mi * 16 + h * 8;
                zsm[(wid >> 1) * 128 + rloc] = rs;
            }
        }
    }
    __syncthreads();
    if (tid < 128) {
        zp_out[tid] = zsm[tid] + zsm[128 + tid] + zsm[256 + tid] + zsm[384 + tid];
    }
#pragma unroll
    for (int mi = 0; mi < 4; ++mi)
#pragma unroll
        for (int j = 0; j < 4; ++j) {
            int c = col0 + j * 8;
#pragma unroll
            for (int h = 0; h < 2; ++h) {
                int r = row0 + mi * 16 + h * 8;
                __nv_bfloat162 hh, ll;
                split2(ex[mi][j][h * 2], ex[mi][j][h * 2 + 1], hh, ll);
                char* p = base + (long)r * ld + (c >> 5) * 128 + (c & 31) * 2;
                *reinterpret_cast<__nv_bfloat162*>(p)      = hh;
                *reinterpret_cast<__nv_bfloat162*>(p + 64) = ll;
            }
        }
}

// ---------------------------------------------------------------------------
// fp32 -> sbf conversion kernels
// ---------------------------------------------------------------------------
__global__ void __launch_bounds__(NTHREADS) conv_kernel(const float* __restrict__ src,
        char* __restrict__ dst)
{
    long i = (long)blockIdx.x * NTHREADS + threadIdx.x;
    float4 v = reinterpret_cast<const float4*>(src)[i];
    long e = i * 4;
    char* p = dst + (e & ~31L) * 4 + (e & 31) * 2;
    __nv_bfloat162 h0, l0, h1, l1;
    split2(v.x, v.y, h0, l0);
    split2(v.z, v.w, h1, l1);
    *reinterpret_cast<__nv_bfloat162*>(p)      = h0;
    *reinterpret_cast<__nv_bfloat162*>(p + 4)  = h1;
    *reinterpret_cast<__nv_bfloat162*>(p + 64) = l0;
    *reinterpret_cast<__nv_bfloat162*>(p + 68) = l1;
}

__global__ void __launch_bounds__(NTHREADS) wpt_kernel(const float* __restrict__ Wp)
{
    __shared__ float t[32][33];
    int h = blockIdx.x, n0 = blockIdx.y * 32;
    int tx = threadIdx.x & 31, ty = threadIdx.x >> 5;
    const float* src = Wp + (long)h * 32768 + (long)n0 * 32;
#pragma unroll
    for (int i = 0; i < 4; ++i) t[ty + i * 8][tx] = src[(ty + i * 8) * 32 + tx];
    __syncthreads();
#pragma unroll
    for (int i = 0; i < 4; ++i) {
        int w = ty + i * 8;
        float v = t[tx][w];
        int n = n0 + tx;
        __nv_bfloat16 hb = __float2bfloat16(v);
        __nv_bfloat16 lb = __float2bfloat16(v - __bfloat162float(hb));
        char* p = g_wpts + ((long)h * 32 + w) * 4096 + (n >> 5) * 128 + (n & 31) * 2;
        *reinterpret_cast<__nv_bfloat16*>(p)      = hb;
        *reinterpret_cast<__nv_bfloat16*>(p + 64) = lb;
    }
}

// ---------------------------------------------------------------------------
// Stage 1: proj. grid (2, 128, 3).
// ---------------------------------------------------------------------------
__global__ void __launch_bounds__(NTHREADS, 2)
proj_kernel(const float* __restrict__ bq, const float* __restrict__ bk,
            const float* __restrict__ bv)
{
    extern __shared__ char smem[];
    int n0 = blockIdx.x * 128; long m0 = (long)blockIdx.y * 128; int sel = blockIdx.z;
    const float* bias = sel == 0 ? bq : sel == 1 ? bk : bv;
    float acc[4][4][4] = {};
    gemm_async(g_xs + m0 * 1024, 1024,
               g_ws + ((long)sel * 256 + n0) * 1024, 1024, CDIM / 32, smem, acc);
    if (sel < 2) {
        char* out = sel == 0 ? g_qs : g_ks;
        epi_sbf(acc, out + m0 * 1024 + (n0 >> 5) * 128, 1024, bias + n0);
    } else {
        int b = (int)(m0 >> 10), tok0 = (int)(m0 & 1023);
        epi_sbf_t(acc, g_vts + ((long)b * CDIM + n0) * 4096 + (tok0 >> 5) * 128, 4096,
                  bias + n0);
    }
}

// ---------------------------------------------------------------------------
// Stage 2: attn_un = exp(q k^T) -> sbf + partial sums. grid (8, 8, 16)
// ---------------------------------------------------------------------------
__global__ void __launch_bounds__(NTHREADS, 2) scores_kernel()
{
    extern __shared__ char smem[];
    int n0 = blockIdx.x * 128, m0 = blockIdx.y * 128, b = blockIdx.z;
    float acc[4][4][4] = {};
    gemm_async(g_qs + ((long)b * NTOK + m0) * 1024, 1024,
               g_ks + ((long)b * NTOK + n0) * 1024, 1024, CDIM / 32, smem, acc);
    char* base = g_attns + ((size_t)b * NTOK + m0) * 4096 + (n0 >> 5) * 128;
    epi_attn(acc, smem, base, 4096, g_zp + ((long)b * 8 + blockIdx.x) * NTOK + m0);
}

// ---------------------------------------------------------------------------
// Stage 3 (wide): o^T = (attn_un @ v)^T / Z -> ots sbf. grid (8, 16)
// ---------------------------------------------------------------------------
__global__ void __launch_bounds__(NTHREADS, 1) av_kernel()
{
    extern __shared__ char smem[];
    int tok0 = blockIdx.x * 128, b = blockIdx.y;
    float acc[4][8][4] = {};
    gemm_async_w(g_attns + ((size_t)b * NTOK + tok0) * 4096, 4096,
                 g_vts + (long)b * CDIM * 4096, 4096, NTOK / 32, smem, acc);
    __syncthreads();
    float* rzs = reinterpret_cast<float*>(smem);
    if (threadIdx.x < 128) {
        float z = 0.0f;
#pragma unroll
        for (int t = 0; t < 8; ++t)
            z += g_zp[((long)b * 8 + t) * NTOK + tok0 + threadIdx.x];
        rzs[threadIdx.x] = 1.0f / z;
    }
    __syncthreads();
    epi_sbf_t_w(acc, g_ots + (long)b * CDIM * 4096 + (tok0 >> 5) * 128, 4096, rzs);
}

// ---------------------------------------------------------------------------
// Stage 4 (wide): z[b,p,c] = sum_n wpt[p][n] * ot[c][n]. grid (8, 16)
// ---------------------------------------------------------------------------
__global__ void __launch_bounds__(NTHREADS, 1) final_kernel(float* __restrict__ z)
{
    extern __shared__ char smem[];
    int p0 = blockIdx.x * 128, b = blockIdx.y;
    float acc[4][8][4] = {};
    gemm_async_w(g_wpts + (long)p0 * 4096, 4096,
                 g_ots + (long)b * CDIM * 4096, 4096, NTOK / 32, smem, acc);
    epi_f32_w(acc, z + ((long)b * NTOK + p0) * CDIM, CDIM);
}

// ---------------------------------------------------------------------------
extern "C" void kernel_launch(void* const* d_in, const int* in_sizes, int n_in,
                              void* d_out, int out_size)
{
    const float* x  = (const float*)d_in[0];
    const float* Wq = (const float*)d_in[1];
    const float* bq = (const float*)d_in[2];
    const float* Wk = (const float*)d_in[3];
    const float* bk = (const float*)d_in[4];
    const float* Wv = (const float*)d_in[5];
    const float* bv = (const float*)d_in[6];
    const float* Wp = (const float*)d_in[7];
    float* out = (float*)d_out;

    cudaFuncSetAttribute(proj_kernel,   cudaFuncAttributeMaxDynamicSharedMemorySize, SMEM_BYTES);
    cudaFuncSetAttribute(scores_kernel, cudaFuncAttributeMaxDynamicSharedMemorySize, SMEM_BYTES);
    cudaFuncSetAttribute(av_kernel,     cudaFuncAttributeMaxDynamicSharedMemorySize, SMEM_W);
    cudaFuncSetAttribute(final_kernel,  cudaFuncAttributeMaxDynamicSharedMemorySize, SMEM_W);

    char *d_xs, *d_ws;
    cudaGetSymbolAddress((void**)&d_xs, g_xs);
    cudaGetSymbolAddress((void**)&d_ws, g_ws);

    conv_kernel<<<dim3(4096), NTHREADS>>>(x, d_xs);
    conv_kernel<<<dim3(64),   NTHREADS>>>(Wq, d_ws);
    conv_kernel<<<dim3(64),   NTHREADS>>>(Wk, d_ws + 256*1024);
    conv_kernel<<<dim3(64),   NTHREADS>>>(Wv, d_ws + 2*256*1024);
    wpt_kernel<<<dim3(32, 32), NTHREADS>>>(Wp);

    proj_kernel<<<dim3(2, 128, 3), NTHREADS, SMEM_BYTES>>>(bq, bk, bv);
    scores_kernel<<<dim3(8, 8, 16), NTHREADS, SMEM_BYTES>>>();
    av_kernel<<<dim3(8, 16), NTHREADS, SMEM_W>>>();
    final_kernel<<<dim3(8, 16), NTHREADS, SMEM_W>>>(out);
}

// round 8
// speedup vs baseline: 2.8467x; 1.0849x over previous
#include <cuda_runtime.h>
#include <cuda_bf16.h>
#include <cstdint>

#define BATCH 16
#define NTOK  1024
#define CDIM  256
#define NTHREADS 256
#define NSTAGE 3
#define SLABB 16384                    // one slab: 128 rows x 128B (contiguous, pre-swizzled)
#define STAGEB (2*SLABB)
#define SMEM_BYTES (NSTAGE*STAGEB + 1024)   // + mbarrier area

// ---------------------------------------------------------------------------
// Tiled sbf format: operand rows grouped in tiles of 128; for tile t, k-slab s
// (32 k each), the 16KB block at base + (t*nslab + s)*16384 holds the EXACT
// smem image: row r (0..127) at r*128, 16B chunk cc stored at (cc ^ (r&7))*16;
// chunks 0-3 = bf16 hi of k 0..31, chunks 4-7 = bf16 lo (addr = hi ^ 64).
// ---------------------------------------------------------------------------
__device__ __align__(128) char g_xs  [16384*1024];      // x     (16384 rows, K=256, nslab 8)
__device__ __align__(128) char g_ws  [3*256*1024];      // Wq|Wk|Wv (256 rows ea, K=256)
__device__ __align__(128) char g_qs  [16384*1024];
__device__ __align__(128) char g_ks  [16384*1024];
__device__ __align__(128) char g_vts [16*256*4096];     // v^T  (4096 rows c, K=n=1024, nslab 32)
__device__ __align__(128) char g_ots [16*256*4096];     // o^T
__device__ __align__(128) char g_attns[(size_t)16384*4096]; // exp(scores) (16384 rows, K=1024)
__device__ __align__(128) char g_wpts[1024*4096];       // Wp^T (1024 rows p, K=n=1024)
__device__ float g_zp[BATCH*8*NTOK];

// ---------------------------------------------------------------------------
__device__ __forceinline__ uint32_t smem_u32(const void* p){
    uint32_t a;
    asm("{ .reg .u64 t; cvta.to.shared.u64 t, %1; cvt.u32.u64 %0, t; }" : "=r"(a) : "l"(p));
    return a;
}
__device__ __forceinline__ void ldsm4(uint32_t* r, uint32_t addr){
    asm volatile("ldmatrix.sync.aligned.m8n8.x4.shared.b16 {%0,%1,%2,%3}, [%4];"
        : "=r"(r[0]), "=r"(r[1]), "=r"(r[2]), "=r"(r[3]) : "r"(addr));
}
__device__ __forceinline__ void mma_bf16(float* d, const uint32_t* a, const uint32_t* b){
    asm volatile("mma.sync.aligned.m16n8k16.row.col.f32.bf16.bf16.f32 "
        "{%0,%1,%2,%3}, {%4,%5,%6,%7}, {%8,%9}, {%0,%1,%2,%3};"
        : "+f"(d[0]), "+f"(d[1]), "+f"(d[2]), "+f"(d[3])
        : "r"(a[0]), "r"(a[1]), "r"(a[2]), "r"(a[3]), "r"(b[0]), "r"(b[1]));
}
__device__ __forceinline__ void split2(float v0, float v1,
        __nv_bfloat162& h, __nv_bfloat162& l){
    h = __floats2bfloat162_rn(v0, v1);
    l = __floats2bfloat162_rn(v0 - __low2float(h), v1 - __high2float(h));
}
__device__ __forceinline__ uint32_t b2u(__nv_bfloat162 v){
    uint32_t u; memcpy(&u, &v, 4); return u;
}
__device__ __forceinline__ uint16_t b2s(__nv_bfloat16 v){
    uint16_t u; memcpy(&u, &v, 2); return u;
}

// byte offset (hi) of element (tile-local row r, k) in tiled sbf; lo = off ^ 64
__device__ __forceinline__ size_t sbf_off(long tile, int nslab, int r, int k){
    int cc = (k & 31) >> 3;
    return ((size_t)(tile * nslab + (k >> 5)) << 14)
         + (size_t)(r * 128) + (size_t)(((cc ^ (r & 7)) << 4) + (k & 7) * 2);
}

#define MBAR_INIT(mb,c)  asm volatile("mbarrier.init.shared.b64 [%0], %1;" :: "r"(mb), "r"((uint32_t)(c)) : "memory")
#define MBAR_EXPECT(mb,n) asm volatile("mbarrier.arrive.expect_tx.shared.b64 _, [%0], %1;" :: "r"(mb), "r"((uint32_t)(n)) : "memory")
#define BULK_G2S(dst,src,n,mb) asm volatile("cp.async.bulk.shared::cta.global.mbarrier::complete_tx::bytes [%0], [%1], %2, [%3];" :: "r"(dst), "l"(src), "r"((uint32_t)(n)), "r"(mb) : "memory")
#define FENCE_ASYNC() asm volatile("fence.proxy.async.shared::cta;" ::: "memory")

#define MBAR_WAIT(mb, par) do { \
    uint32_t _m = (uint32_t)(mb), _p = (uint32_t)(par), _d; \
    asm volatile("{\n\t.reg .pred p;\n\t" \
        "mbarrier.try_wait.parity.acquire.cta.shared::cta.b64 p, [%1], %2;\n\t" \
        "selp.b32 %0, 1, 0, p;\n\t}" : "=r"(_d) : "r"(_m), "r"(_p) : "memory"); \
    if (!_d) { \
        asm volatile("{\n\t.reg .pred P1;\n\t" \
            "WL_%=:\n\t" \
            "mbarrier.try_wait.parity.acquire.cta.shared::cta.b64 P1, [%0], %1, 0x989680;\n\t" \
            "@P1 bra.uni WD_%=;\n\t" \
            "bra.uni WL_%=;\n\t" \
            "WD_%=:\n\t}" :: "r"(_m), "r"(_p) : "memory"); \
    } \
} while(0)

// ---------------------------------------------------------------------------
// Narrow compute: CTA 128x128, warps 2(M)x4(N), warp tile 64x32.
// ---------------------------------------------------------------------------
__device__ __forceinline__ void compute_slab(char* buf, float acc[4][4][4])
{
    int tid = threadIdx.x, lane = tid & 31, wid = tid >> 5;
    uint32_t sA = smem_u32(buf), sB = sA + SLABB;
    int mw = (wid & 1) * 64, nw = (wid >> 1) * 32;
    int arow = lane & 15, ahalf = lane >> 4;
    int brow = (lane & 7) + ((lane >> 4) & 1) * 8, bhalf = (lane >> 3) & 1;

#pragma unroll
    for (int ks = 0; ks < 2; ++ks) {
        uint32_t bh[8], bl[8];
#pragma unroll
        for (int nj = 0; nj < 2; ++nj) {
            int r = nw + nj * 16 + brow;
            int c = ks * 2 + bhalf;
            ldsm4(bh + nj * 4, sB + r * 128 + (((c    ) ^ (r & 7)) << 4));
            ldsm4(bl + nj * 4, sB + r * 128 + (((c + 4) ^ (r & 7)) << 4));
        }
#pragma unroll
        for (int mi = 0; mi < 4; ++mi) {
            int r = mw + mi * 16 + arow;
            int c = ks * 2 + ahalf;
            uint32_t ah[4], al[4];
            ldsm4(ah, sA + r * 128 + (((c    ) ^ (r & 7)) << 4));
            ldsm4(al, sA + r * 128 + (((c + 4) ^ (r & 7)) << 4));
#pragma unroll
            for (int j = 0; j < 4; ++j) {
                const uint32_t* bhf = &bh[(j >> 1) * 4 + (j & 1) * 2];
                const uint32_t* blf = &bl[(j >> 1) * 4 + (j & 1) * 2];
                float* d = acc[mi][j];
                mma_bf16(d, ah, bhf);
                mma_bf16(d, al, bhf);
                mma_bf16(d, ah, blf);
            }
        }
    }
}

// ---------------------------------------------------------------------------
// Bulk-copy mainloop: A/B point at tile start; slab c at +c*16KB each.
// ---------------------------------------------------------------------------
__device__ __forceinline__ void gemm_bulk(const char* __restrict__ A,
                                          const char* __restrict__ B,
                                          int NC, char* smem, float acc[4][4][4])
{
    uint32_t mb = smem_u32(smem + NSTAGE * STAGEB);   // 3 x 8B mbarriers
    int tid = threadIdx.x;
    if (tid == 0) {
        MBAR_INIT(mb, 1); MBAR_INIT(mb + 8, 1); MBAR_INIT(mb + 16, 1);
        FENCE_ASYNC();
    }
    __syncthreads();
    if (tid == 0) {
#pragma unroll
        for (int s = 0; s < NSTAGE - 1; ++s) {
            uint32_t m = mb + 8 * s;
            uint32_t d = smem_u32(smem + s * STAGEB);
            MBAR_EXPECT(m, STAGEB);
            BULK_G2S(d,         A + (size_t)s * SLABB, SLABB, m);
            BULK_G2S(d + SLABB, B + (size_t)s * SLABB, SLABB, m);
        }
    }
    for (int c = 0; c < NC; ++c) {
        int s = c % NSTAGE;
        MBAR_WAIT(mb + 8 * s, (c / NSTAGE) & 1);
        __syncthreads();          // all threads done with stage being refilled below
        int nc = c + NSTAGE - 1;
        if (tid == 0 && nc < NC) {
            int sn = nc % NSTAGE;
            uint32_t m = mb + 8 * sn;
            uint32_t d = smem_u32(smem + sn * STAGEB);
            MBAR_EXPECT(m, STAGEB);
            BULK_G2S(d,         A + (size_t)nc * SLABB, SLABB, m);
            BULK_G2S(d + SLABB, B + (size_t)nc * SLABB, SLABB, m);
        }
        compute_slab(smem + s * STAGEB, acc);
    }
}

// ---------------------------------------------------------------------------
// Epilogues. Frag: d0,d1 -> (row=lane>>2, col=(lane&3)*2+e), d2,d3 row+8.
// ---------------------------------------------------------------------------
__device__ __forceinline__ void epi_f32(const float acc[4][4][4],
        float* __restrict__ Cg, int ldc)
{
    int tid = threadIdx.x, lane = tid & 31, wid = tid >> 5;
    int row0 = (wid & 1) * 64 + (lane >> 2), col0 = (wid >> 1) * 32 + (lane & 3) * 2;
#pragma unroll
    for (int mi = 0; mi < 4; ++mi)
#pragma unroll
        for (int j = 0; j < 4; ++j) {
            int c = col0 + j * 8;
#pragma unroll
            for (int h = 0; h < 2; ++h) {
                int r = row0 + mi * 16 + h * 8;
                *reinterpret_cast<float2*>(Cg + (long)r * ldc + c) =
                    make_float2(acc[mi][j][h * 2], acc[mi][j][h * 2 + 1]);
            }
        }
}

// C(128x128) -> tiled sbf; row0 = global row origin (mult of 128), k0 = k origin
__device__ __forceinline__ void epi_sbf(const float acc[4][4][4],
        char* base, long row0, int k0, int nslab, const float* __restrict__ bias)
{
    int tid = threadIdx.x, lane = tid & 31, wid = tid >> 5;
    long tile = row0 >> 7;
    int rw0 = (wid & 1) * 64 + (lane >> 2), cw0 = (wid >> 1) * 32 + (lane & 3) * 2;
#pragma unroll
    for (int mi = 0; mi < 4; ++mi)
#pragma unroll
        for (int j = 0; j < 4; ++j) {
            int c = cw0 + j * 8;
            float b0 = bias ? bias[c] : 0.0f, b1 = bias ? bias[c + 1] : 0.0f;
#pragma unroll
            for (int h = 0; h < 2; ++h) {
                int r = rw0 + mi * 16 + h * 8;
                __nv_bfloat162 hh, ll;
                split2(acc[mi][j][h * 2] + b0, acc[mi][j][h * 2 + 1] + b1, hh, ll);
                size_t off = sbf_off(tile, nslab, r, k0 + c);
                *reinterpret_cast<uint32_t*>(base + off)        = b2u(hh);
                *reinterpret_cast<uint32_t*>(base + (off ^ 64)) = b2u(ll);
            }
        }
}

// transposed: element (m,n) -> tiled row rowbase+n, k = k0+m; optional per-m scale
__device__ __forceinline__ void epi_sbf_t(const float acc[4][4][4],
        char* base, long rowbase, int k0, int nslab,
        const float* __restrict__ bias, const float* __restrict__ rz)
{
    int tid = threadIdx.x, lane = tid & 31, wid = tid >> 5;
    long tile = rowbase >> 7;
    int rw0 = (wid & 1) * 64 + (lane >> 2), cw0 = (wid >> 1) * 32 + (lane & 3) * 2;
#pragma unroll
    for (int mi = 0; mi < 4; ++mi)
#pragma unroll
        for (int j = 0; j < 4; ++j)
#pragma unroll
            for (int h = 0; h < 2; ++h) {
                int m = rw0 + mi * 16 + h * 8;
                float sc = rz ? rz[m] : 1.0f;
#pragma unroll
                for (int e = 0; e < 2; ++e) {
                    int n = cw0 + j * 8 + e;
                    float v = acc[mi][j][h * 2 + e] * sc + (bias ? bias[n] : 0.0f);
                    __nv_bfloat16 hb = __float2bfloat16(v);
                    __nv_bfloat16 lb = __float2bfloat16(v - __bfloat162float(hb));
                    size_t off = sbf_off(tile, nslab, n, k0 + m);
                    *reinterpret_cast<uint16_t*>(base + off)        = b2s(hb);
                    *reinterpret_cast<uint16_t*>(base + (off ^ 64)) = b2s(lb);
                }
            }
}

// exp + tiled sbf store + deterministic per-row partial sums -> g_zp
__device__ __forceinline__ void epi_attn(const float acc[4][4][4], char* smem,
        char* base, long row0, int k0, float* __restrict__ zp_out)
{
    int tid = threadIdx.x, lane = tid & 31, wid = tid >> 5;
    long tile = row0 >> 7;
    int rw0 = (wid & 1) * 64 + (lane >> 2), cw0 = (wid >> 1) * 32 + (lane & 3) * 2;
    float* zsm = reinterpret_cast<float*>(smem);
    __syncthreads();

    float ex[4][4][4];
#pragma unroll
    for (int mi = 0; mi < 4; ++mi) {
#pragma unroll
        for (int h = 0; h < 2; ++h) {
            float rs = 0.0f;
#pragma unroll
            for (int j = 0; j < 4; ++j) {
                float e0 = __expf(acc[mi][j][h * 2]);
                float e1 = __expf(acc[mi][j][h * 2 + 1]);
                ex[mi][j][h * 2] = e0; ex[mi][j][h * 2 + 1] = e1;
                rs += e0 + e1;
            }
            rs += __shfl_xor_sync(0xffffffffu, rs, 1);
            rs += __shfl_xor_sync(0xffffffffu, rs, 2);
            if ((lane & 3) == 0)
                zsm[(wid >> 1) * 128 + rw0 + mi * 16 + h * 8] = rs;
        }
    }
    __syncthreads();
    if (tid < 128)
        zp_out[tid] = zsm[tid] + zsm[128 + tid] + zsm[256 + tid] + zsm[384 + tid];
#pragma unroll
    for (int mi = 0; mi < 4; ++mi)
#pragma unroll
        for (int j = 0; j < 4; ++j) {
            int c = cw0 + j * 8;
#pragma unroll
            for (int h = 0; h < 2; ++h) {
                int r = rw0 + mi * 16 + h * 8;
                __nv_bfloat162 hh, ll;
                split2(ex[mi][j][h * 2], ex[mi][j][h * 2 + 1], hh, ll);
                size_t off = sbf_off(tile, 32, r, k0 + c);
                *reinterpret_cast<uint32_t*>(base + off)        = b2u(hh);
                *reinterpret_cast<uint32_t*>(base + (off ^ 64)) = b2u(ll);
            }
        }
}

// ---------------------------------------------------------------------------
// fp32 (rows x K=256) -> tiled sbf, nslab=8
// ---------------------------------------------------------------------------
__global__ void __launch_bounds__(NTHREADS) conv_kernel(const float* __restrict__ src,
        char* __restrict__ dst)
{
    long i = (long)blockIdx.x * NTHREADS + threadIdx.x;
    float4 v = reinterpret_cast<const float4*>(src)[i];
    long e = i * 4;
    int r = (int)(e >> 8), k = (int)(e & 255);
    size_t off = sbf_off(r >> 7, 8, r & 127, k);
    __nv_bfloat162 h0, l0, h1, l1;
    split2(v.x, v.y, h0, l0);
    split2(v.z, v.w, h1, l1);
    *reinterpret_cast<uint2*>(dst + off)        = make_uint2(b2u(h0), b2u(h1));
    *reinterpret_cast<uint2*>(dst + (off ^ 64)) = make_uint2(b2u(l0), b2u(l1));
}

// Wp[h][n][w] -> wpts tiled sbf (row p=h*32+w, k=n, nslab=32)
__global__ void __launch_bounds__(NTHREADS) wpt_kernel(const float* __restrict__ Wp)
{
    __shared__ float t[32][33];
    int h = blockIdx.x, n0 = blockIdx.y * 32;
    int tx = threadIdx.x & 31, ty = threadIdx.x >> 5;
    const float* src = Wp + (long)h * 32768 + (long)n0 * 32;
#pragma unroll
    for (int i = 0; i < 4; ++i) t[ty + i * 8][tx] = src[(ty + i * 8) * 32 + tx];
    __syncthreads();
#pragma unroll
    for (int i = 0; i < 4; ++i) {
        int w = ty + i * 8;
        float v = t[tx][w];
        int p = h * 32 + w, n = n0 + tx;
        __nv_bfloat16 hb = __float2bfloat16(v);
        __nv_bfloat16 lb = __float2bfloat16(v - __bfloat162float(hb));
        size_t off = sbf_off(p >> 7, 32, p & 127, n);
        *reinterpret_cast<uint16_t*>(g_wpts + off)        = b2s(hb);
        *reinterpret_cast<uint16_t*>(g_wpts + (off ^ 64)) = b2s(lb);
    }
}

// ---------------------------------------------------------------------------
// Stage 1: proj. grid (2, 128, 3).
// ---------------------------------------------------------------------------
__global__ void __launch_bounds__(NTHREADS, 2)
proj_kernel(const float* __restrict__ bq, const float* __restrict__ bk,
            const float* __restrict__ bv)
{
    extern __shared__ char smem[];
    int n0 = blockIdx.x * 128; long m0 = (long)blockIdx.y * 128; int sel = blockIdx.z;
    const float* bias = sel == 0 ? bq : sel == 1 ? bk : bv;
    float acc[4][4][4] = {};
    gemm_bulk(g_xs + (m0 >> 7) * 8 * SLABB,
              g_ws + (size_t)sel * 262144 + (size_t)(n0 >> 7) * 8 * SLABB,
              8, smem, acc);
    if (sel < 2) {
        char* out = sel == 0 ? g_qs : g_ks;
        epi_sbf(acc, out, m0, n0, 8, bias + n0);
    } else {
        int b = (int)(m0 >> 10), tok0 = (int)(m0 & 1023);
        epi_sbf_t(acc, g_vts, (long)b * 256 + n0, tok0, 32, bias + n0, nullptr);
    }
}

// ---------------------------------------------------------------------------
// Stage 2: attn_un = exp(q k^T) -> tiled sbf + partials. grid (8, 8, 16)
// ---------------------------------------------------------------------------
__global__ void __launch_bounds__(NTHREADS, 2) scores_kernel()
{
    extern __shared__ char smem[];
    int n0 = blockIdx.x * 128, m0 = blockIdx.y * 128, b = blockIdx.z;
    float acc[4][4][4] = {};
    gemm_bulk(g_qs + (size_t)((b * NTOK + m0) >> 7) * 8 * SLABB,
              g_ks + (size_t)((b * NTOK + n0) >> 7) * 8 * SLABB,
              8, smem, acc);
    epi_attn(acc, smem, g_attns, (long)b * NTOK + m0, n0,
             g_zp + ((long)b * 8 + blockIdx.x) * NTOK + m0);
}

// ---------------------------------------------------------------------------
// Stage 3: o^T = (attn_un @ v)^T / Z. grid (2, 8, 16)
// ---------------------------------------------------------------------------
__global__ void __launch_bounds__(NTHREADS, 2) av_kernel()
{
    extern __shared__ char smem[];
    int c0 = blockIdx.x * 128, tok0 = blockIdx.y * 128, b = blockIdx.z;
    float acc[4][4][4] = {};
    gemm_bulk(g_attns + (size_t)(b * 8 + (tok0 >> 7)) * 32 * SLABB,
              g_vts   + (size_t)(b * 2 + (c0 >> 7))   * 32 * SLABB,
              32, smem, acc);
    __syncthreads();
    float* rzs = reinterpret_cast<float*>(smem);
    if (threadIdx.x < 128) {
        float z = 0.0f;
#pragma unroll
        for (int t = 0; t < 8; ++t)
            z += g_zp[((long)b * 8 + t) * NTOK + tok0 + threadIdx.x];
        rzs[threadIdx.x] = 1.0f / z;
    }
    __syncthreads();
    epi_sbf_t(acc, g_ots, (long)b * 256 + c0, tok0, 32, nullptr, rzs);
}

// ---------------------------------------------------------------------------
// Stage 4: z[b,p,c] = sum_n wpt[p][n] * ot[c][n]. grid (2, 8, 16)
// ---------------------------------------------------------------------------
__global__ void __launch_bounds__(NTHREADS, 2) final_kernel(float* __restrict__ z)
{
    extern __shared__ char smem[];
    int c0 = blockIdx.x * 128, p0 = blockIdx.y * 128, b = blockIdx.z;
    float acc[4][4][4] = {};
    gemm_bulk(g_wpts + (size_t)(p0 >> 7) * 32 * SLABB,
              g_ots  + (size_t)(b * 2 + (c0 >> 7)) * 32 * SLABB,
              32, smem, acc);
    epi_f32(acc, z + ((long)b * NTOK + p0) * CDIM + c0, CDIM);
}

// ---------------------------------------------------------------------------
extern "C" void kernel_launch(void* const* d_in, const int* in_sizes, int n_in,
                              void* d_out, int out_size)
{
    const float* x  = (const float*)d_in[0];
    const float* Wq = (const float*)d_in[1];
    const float* bq = (const float*)d_in[2];
    const float* Wk = (const float*)d_in[3];
    const float* bk = (const float*)d_in[4];
    const float* Wv = (const float*)d_in[5];
    const float* bv = (const float*)d_in[6];
    const float* Wp = (const float*)d_in[7];
    float* out = (float*)d_out;

    cudaFuncSetAttribute(proj_kernel,   cudaFuncAttributeMaxDynamicSharedMemorySize, SMEM_BYTES);
    cudaFuncSetAttribute(scores_kernel, cudaFuncAttributeMaxDynamicSharedMemorySize, SMEM_BYTES);
    cudaFuncSetAttribute(av_kernel,     cudaFuncAttributeMaxDynamicSharedMemorySize, SMEM_BYTES);
    cudaFuncSetAttribute(final_kernel,  cudaFuncAttributeMaxDynamicSharedMemorySize, SMEM_BYTES);

    char *d_xs, *d_ws;
    cudaGetSymbolAddress((void**)&d_xs, g_xs);
    cudaGetSymbolAddress((void**)&d_ws, g_ws);

    conv_kernel<<<dim3(4096), NTHREADS>>>(x, d_xs);
    conv_kernel<<<dim3(64),   NTHREADS>>>(Wq, d_ws);
    conv_kernel<<<dim3(64),   NTHREADS>>>(Wk, d_ws + 262144);
    conv_kernel<<<dim3(64),   NTHREADS>>>(Wv, d_ws + 2*262144);
    wpt_kernel<<<dim3(32, 32), NTHREADS>>>(Wp);

    proj_kernel<<<dim3(2, 128, 3), NTHREADS, SMEM_BYTES>>>(bq, bk, bv);
    scores_kernel<<<dim3(8, 8, 16), NTHREADS, SMEM_BYTES>>>();
    av_kernel<<<dim3(2, 8, 16), NTHREADS, SMEM_BYTES>>>();
    final_kernel<<<dim3(2, 8, 16), NTHREADS, SMEM_BYTES>>>(out);
}

// round 9
// speedup vs baseline: 2.9307x; 1.0295x over previous
#include <cuda_runtime.h>
#include <cuda_bf16.h>
#include <cstdint>

#define BATCH 16
#define NTOK  1024
#define CDIM  256
#define NTHREADS 256
#define NSTAGE 3
#define SLABB 16384                    // one slab: 128 rows x 128B (contiguous, pre-swizzled)
#define STAGEB (2*SLABB)
#define SMEM_BYTES (NSTAGE*STAGEB + 1024)   // + mbarrier area

// ---------------------------------------------------------------------------
// Tiled sbf format: operand rows grouped in tiles of 128; for tile t, k-slab s
// (32 k each), the 16KB block at base + (t*nslab + s)*16384 holds the EXACT
// smem image: row r (0..127) at r*128, 16B chunk cc stored at (cc ^ (r&7))*16;
// chunks 0-3 = bf16 hi of k 0..31, chunks 4-7 = bf16 lo (addr = hi ^ 64).
// ---------------------------------------------------------------------------
__device__ __align__(128) char g_xs  [16384*1024];      // x     (16384 rows, K=256, nslab 8)
__device__ __align__(128) char g_ws  [3*256*1024];      // Wq|Wk|Wv (256 rows ea, K=256)
__device__ __align__(128) char g_qs  [16384*1024];
__device__ __align__(128) char g_ks  [16384*1024];
__device__ __align__(128) char g_vts [16*256*4096];     // v^T  (4096 rows c, K=n=1024, nslab 32)
__device__ __align__(128) char g_ots [16*256*4096];     // o^T
__device__ __align__(128) char g_attns[(size_t)16384*4096]; // exp(scores) (16384 rows, K=1024)
__device__ __align__(128) char g_wpts[1024*4096];       // Wp^T (1024 rows p, K=n=1024)
__device__ float g_zp[BATCH*8*NTOK];

// ---------------------------------------------------------------------------
__device__ __forceinline__ uint32_t smem_u32(const void* p){
    uint32_t a;
    asm("{ .reg .u64 t; cvta.to.shared.u64 t, %1; cvt.u32.u64 %0, t; }" : "=r"(a) : "l"(p));
    return a;
}
__device__ __forceinline__ void ldsm4(uint32_t* r, uint32_t addr){
    asm volatile("ldmatrix.sync.aligned.m8n8.x4.shared.b16 {%0,%1,%2,%3}, [%4];"
        : "=r"(r[0]), "=r"(r[1]), "=r"(r[2]), "=r"(r[3]) : "r"(addr));
}
__device__ __forceinline__ void mma_bf16(float* d, const uint32_t* a, const uint32_t* b){
    asm volatile("mma.sync.aligned.m16n8k16.row.col.f32.bf16.bf16.f32 "
        "{%0,%1,%2,%3}, {%4,%5,%6,%7}, {%8,%9}, {%0,%1,%2,%3};"
        : "+f"(d[0]), "+f"(d[1]), "+f"(d[2]), "+f"(d[3])
        : "r"(a[0]), "r"(a[1]), "r"(a[2]), "r"(a[3]), "r"(b[0]), "r"(b[1]));
}
__device__ __forceinline__ void split2(float v0, float v1,
        __nv_bfloat162& h, __nv_bfloat162& l){
    h = __floats2bfloat162_rn(v0, v1);
    l = __floats2bfloat162_rn(v0 - __low2float(h), v1 - __high2float(h));
}
__device__ __forceinline__ uint32_t b2u(__nv_bfloat162 v){
    uint32_t u; memcpy(&u, &v, 4); return u;
}
__device__ __forceinline__ uint16_t b2s(__nv_bfloat16 v){
    uint16_t u; memcpy(&u, &v, 2); return u;
}

// byte offset (hi) of element (tile-local row r, k) in tiled sbf; lo = off ^ 64
__device__ __forceinline__ size_t sbf_off(long tile, int nslab, int r, int k){
    int cc = (k & 31) >> 3;
    return ((size_t)(tile * nslab + (k >> 5)) << 14)
         + (size_t)(r * 128) + (size_t)(((cc ^ (r & 7)) << 4) + (k & 7) * 2);
}

#define MBAR_INIT(mb,c)  asm volatile("mbarrier.init.shared.b64 [%0], %1;" :: "r"(mb), "r"((uint32_t)(c)) : "memory")
#define MBAR_EXPECT(mb,n) asm volatile("mbarrier.arrive.expect_tx.shared.b64 _, [%0], %1;" :: "r"(mb), "r"((uint32_t)(n)) : "memory")
#define BULK_G2S(dst,src,n,mb) asm volatile("cp.async.bulk.shared::cta.global.mbarrier::complete_tx::bytes [%0], [%1], %2, [%3];" :: "r"(dst), "l"(src), "r"((uint32_t)(n)), "r"(mb) : "memory")
#define FENCE_ASYNC() asm volatile("fence.proxy.async.shared::cta;" ::: "memory")

#define MBAR_WAIT(mb, par) do { \
    uint32_t _m = (uint32_t)(mb), _p = (uint32_t)(par), _d; \
    asm volatile("{\n\t.reg .pred p;\n\t" \
        "mbarrier.try_wait.parity.acquire.cta.shared::cta.b64 p, [%1], %2;\n\t" \
        "selp.b32 %0, 1, 0, p;\n\t}" : "=r"(_d) : "r"(_m), "r"(_p) : "memory"); \
    if (!_d) { \
        asm volatile("{\n\t.reg .pred P1;\n\t" \
            "WL_%=:\n\t" \
            "mbarrier.try_wait.parity.acquire.cta.shared::cta.b64 P1, [%0], %1, 0x989680;\n\t" \
            "@P1 bra.uni WD_%=;\n\t" \
            "bra.uni WL_%=;\n\t" \
            "WD_%=:\n\t}" :: "r"(_m), "r"(_p) : "memory"); \
    } \
} while(0)

// ---------------------------------------------------------------------------
// Narrow compute: CTA 128x128, warps 2(M)x4(N), warp tile 64x32.
// ---------------------------------------------------------------------------
__device__ __forceinline__ void compute_slab(char* buf, float acc[4][4][4])
{
    int tid = threadIdx.x, lane = tid & 31, wid = tid >> 5;
    uint32_t sA = smem_u32(buf), sB = sA + SLABB;
    int mw = (wid & 1) * 64, nw = (wid >> 1) * 32;
    int arow = lane & 15, ahalf = lane >> 4;
    int brow = (lane & 7) + ((lane >> 4) & 1) * 8, bhalf = (lane >> 3) & 1;

#pragma unroll
    for (int ks = 0; ks < 2; ++ks) {
        uint32_t bh[8], bl[8];
#pragma unroll
        for (int nj = 0; nj < 2; ++nj) {
            int r = nw + nj * 16 + brow;
            int c = ks * 2 + bhalf;
            ldsm4(bh + nj * 4, sB + r * 128 + (((c    ) ^ (r & 7)) << 4));
            ldsm4(bl + nj * 4, sB + r * 128 + (((c + 4) ^ (r & 7)) << 4));
        }
#pragma unroll
        for (int mi = 0; mi < 4; ++mi) {
            int r = mw + mi * 16 + arow;
            int c = ks * 2 + ahalf;
            uint32_t ah[4], al[4];
            ldsm4(ah, sA + r * 128 + (((c    ) ^ (r & 7)) << 4));
            ldsm4(al, sA + r * 128 + (((c + 4) ^ (r & 7)) << 4));
#pragma unroll
            for (int j = 0; j < 4; ++j) {
                const uint32_t* bhf = &bh[(j >> 1) * 4 + (j & 1) * 2];
                const uint32_t* blf = &bl[(j >> 1) * 4 + (j & 1) * 2];
                float* d = acc[mi][j];
                mma_bf16(d, ah, bhf);
                mma_bf16(d, al, bhf);
                mma_bf16(d, ah, blf);
            }
        }
    }
}

// ---------------------------------------------------------------------------
// Bulk-copy mainloop (compile-time trip count).
// ---------------------------------------------------------------------------
template<int NC>
__device__ __forceinline__ void gemm_bulk(const char* __restrict__ A,
                                          const char* __restrict__ B,
                                          char* smem, float acc[4][4][4])
{
    uint32_t mb = smem_u32(smem + NSTAGE * STAGEB);   // 3 x 8B mbarriers
    int tid = threadIdx.x;
    if (tid == 0) {
        MBAR_INIT(mb, 1); MBAR_INIT(mb + 8, 1); MBAR_INIT(mb + 16, 1);
        FENCE_ASYNC();
    }
    __syncthreads();
    if (tid == 0) {
#pragma unroll
        for (int s = 0; s < NSTAGE - 1; ++s) {
            uint32_t m = mb + 8 * s;
            uint32_t d = smem_u32(smem + s * STAGEB);
            MBAR_EXPECT(m, STAGEB);
            BULK_G2S(d,         A + (size_t)s * SLABB, SLABB, m);
            BULK_G2S(d + SLABB, B + (size_t)s * SLABB, SLABB, m);
        }
    }
#pragma unroll 4
    for (int c = 0; c < NC; ++c) {
        int s = c % NSTAGE;
        MBAR_WAIT(mb + 8 * s, (c / NSTAGE) & 1);
        __syncthreads();          // all warps done with the stage refilled below
        int nc = c + NSTAGE - 1;
        if (tid == 0 && nc < NC) {
            int sn = nc % NSTAGE;
            uint32_t m = mb + 8 * sn;
            uint32_t d = smem_u32(smem + sn * STAGEB);
            MBAR_EXPECT(m, STAGEB);
            BULK_G2S(d,         A + (size_t)nc * SLABB, SLABB, m);
            BULK_G2S(d + SLABB, B + (size_t)nc * SLABB, SLABB, m);
        }
        compute_slab(smem + s * STAGEB, acc);
    }
}

// ---------------------------------------------------------------------------
// Epilogues. Frag: d0,d1 -> (row=lane>>2, col=(lane&3)*2+e), d2,d3 row+8.
// ---------------------------------------------------------------------------
__device__ __forceinline__ void epi_f32(const float acc[4][4][4],
        float* __restrict__ Cg, int ldc)
{
    int tid = threadIdx.x, lane = tid & 31, wid = tid >> 5;
    int row0 = (wid & 1) * 64 + (lane >> 2), col0 = (wid >> 1) * 32 + (lane & 3) * 2;
#pragma unroll
    for (int mi = 0; mi < 4; ++mi)
#pragma unroll
        for (int j = 0; j < 4; ++j) {
            int c = col0 + j * 8;
#pragma unroll
            for (int h = 0; h < 2; ++h) {
                int r = row0 + mi * 16 + h * 8;
                *reinterpret_cast<float2*>(Cg + (long)r * ldc + c) =
                    make_float2(acc[mi][j][h * 2], acc[mi][j][h * 2 + 1]);
            }
        }
}

// C(128x128) -> tiled sbf; row0 = global row origin (mult of 128), k0 = k origin
__device__ __forceinline__ void epi_sbf(const float acc[4][4][4],
        char* base, long row0, int k0, int nslab, const float* __restrict__ bias)
{
    int tid = threadIdx.x, lane = tid & 31, wid = tid >> 5;
    long tile = row0 >> 7;
    int rw0 = (wid & 1) * 64 + (lane >> 2), cw0 = (wid >> 1) * 32 + (lane & 3) * 2;
#pragma unroll
    for (int mi = 0; mi < 4; ++mi)
#pragma unroll
        for (int j = 0; j < 4; ++j) {
            int c = cw0 + j * 8;
            float b0 = bias ? bias[c] : 0.0f, b1 = bias ? bias[c + 1] : 0.0f;
#pragma unroll
            for (int h = 0; h < 2; ++h) {
                int r = rw0 + mi * 16 + h * 8;
                __nv_bfloat162 hh, ll;
                split2(acc[mi][j][h * 2] + b0, acc[mi][j][h * 2 + 1] + b1, hh, ll);
                size_t off = sbf_off(tile, nslab, r, k0 + c);
                *reinterpret_cast<uint32_t*>(base + off)        = b2u(hh);
                *reinterpret_cast<uint32_t*>(base + (off ^ 64)) = b2u(ll);
            }
        }
}

// transposed: element (m,n) -> tiled row rowbase+n, k = k0+m; optional per-m scale
__device__ __forceinline__ void epi_sbf_t(const float acc[4][4][4],
        char* base, long rowbase, int k0, int nslab,
        const float* __restrict__ bias, const float* __restrict__ rz)
{
    int tid = threadIdx.x, lane = tid & 31, wid = tid >> 5;
    long tile = rowbase >> 7;
    int rw0 = (wid & 1) * 64 + (lane >> 2), cw0 = (wid >> 1) * 32 + (lane & 3) * 2;
#pragma unroll
    for (int mi = 0; mi < 4; ++mi)
#pragma unroll
        for (int j = 0; j < 4; ++j)
#pragma unroll
            for (int h = 0; h < 2; ++h) {
                int m = rw0 + mi * 16 + h * 8;
                float sc = rz ? rz[m] : 1.0f;
#pragma unroll
                for (int e = 0; e < 2; ++e) {
                    int n = cw0 + j * 8 + e;
                    float v = acc[mi][j][h * 2 + e] * sc + (bias ? bias[n] : 0.0f);
                    __nv_bfloat16 hb = __float2bfloat16(v);
                    __nv_bfloat16 lb = __float2bfloat16(v - __bfloat162float(hb));
                    size_t off = sbf_off(tile, nslab, n, k0 + m);
                    *reinterpret_cast<uint16_t*>(base + off)        = b2s(hb);
                    *reinterpret_cast<uint16_t*>(base + (off ^ 64)) = b2s(lb);
                }
            }
}

// exp + tiled sbf store + deterministic per-row partial sums -> g_zp
__device__ __forceinline__ void epi_attn(const float acc[4][4][4], char* smem,
        char* base, long row0, int k0, float* __restrict__ zp_out)
{
    int tid = threadIdx.x, lane = tid & 31, wid = tid >> 5;
    long tile = row0 >> 7;
    int rw0 = (wid & 1) * 64 + (lane >> 2), cw0 = (wid >> 1) * 32 + (lane & 3) * 2;
    float* zsm = reinterpret_cast<float*>(smem);
    __syncthreads();

    float ex[4][4][4];
#pragma unroll
    for (int mi = 0; mi < 4; ++mi) {
#pragma unroll
        for (int h = 0; h < 2; ++h) {
            float rs = 0.0f;
#pragma unroll
            for (int j = 0; j < 4; ++j) {
                float e0 = __expf(acc[mi][j][h * 2]);
                float e1 = __expf(acc[mi][j][h * 2 + 1]);
                ex[mi][j][h * 2] = e0; ex[mi][j][h * 2 + 1] = e1;
                rs += e0 + e1;
            }
            rs += __shfl_xor_sync(0xffffffffu, rs, 1);
            rs += __shfl_xor_sync(0xffffffffu, rs, 2);
            if ((lane & 3) == 0)
                zsm[(wid >> 1) * 128 + rw0 + mi * 16 + h * 8] = rs;
        }
    }
    __syncthreads();
    if (tid < 128)
        zp_out[tid] = zsm[tid] + zsm[128 + tid] + zsm[256 + tid] + zsm[384 + tid];
#pragma unroll
    for (int mi = 0; mi < 4; ++mi)
#pragma unroll
        for (int j = 0; j < 4; ++j) {
            int c = cw0 + j * 8;
#pragma unroll
            for (int h = 0; h < 2; ++h) {
                int r = rw0 + mi * 16 + h * 8;
                __nv_bfloat162 hh, ll;
                split2(ex[mi][j][h * 2], ex[mi][j][h * 2 + 1], hh, ll);
                size_t off = sbf_off(tile, 32, r, k0 + c);
                *reinterpret_cast<uint32_t*>(base + off)        = b2u(hh);
                *reinterpret_cast<uint32_t*>(base + (off ^ 64)) = b2u(ll);
            }
        }
}

// ---------------------------------------------------------------------------
// Prep: W conversions (blocks 0..191) + Wp transpose (blocks 192..1215)
// ---------------------------------------------------------------------------
__global__ void __launch_bounds__(NTHREADS) prep_kernel(
        const float* __restrict__ Wq, const float* __restrict__ Wk,
        const float* __restrict__ Wv, const float* __restrict__ Wp)
{
    int bid = blockIdx.x;
    if (bid < 192) {
        int sel = bid >> 6;                          // 64 blocks per W
        const float* src = sel == 0 ? Wq : sel == 1 ? Wk : Wv;
        char* dst = g_ws + (size_t)sel * 262144;
        long i = (long)(bid & 63) * NTHREADS + threadIdx.x;   // float4 idx in 65536 floats
        float4 v = reinterpret_cast<const float4*>(src)[i];
        long e = i * 4;
        int r = (int)(e >> 8), k = (int)(e & 255);
        size_t off = sbf_off(r >> 7, 8, r & 127, k);
        __nv_bfloat162 h0, l0, h1, l1;
        split2(v.x, v.y, h0, l0);
        split2(v.z, v.w, h1, l1);
        *reinterpret_cast<uint2*>(dst + off)        = make_uint2(b2u(h0), b2u(h1));
        *reinterpret_cast<uint2*>(dst + (off ^ 64)) = make_uint2(b2u(l0), b2u(l1));
    } else {
        __shared__ float t[32][33];
        int b2 = bid - 192;
        int h = b2 >> 5, n0 = (b2 & 31) * 32;
        int tx = threadIdx.x & 31, ty = threadIdx.x >> 5;
        const float* src = Wp + (long)h * 32768 + (long)n0 * 32;
#pragma unroll
        for (int i = 0; i < 4; ++i) t[ty + i * 8][tx] = src[(ty + i * 8) * 32 + tx];
        __syncthreads();
#pragma unroll
        for (int i = 0; i < 4; ++i) {
            int w = ty + i * 8;
            float v = t[tx][w];
            int p = h * 32 + w, n = n0 + tx;
            __nv_bfloat16 hb = __float2bfloat16(v);
            __nv_bfloat16 lb = __float2bfloat16(v - __bfloat162float(hb));
            size_t off = sbf_off(p >> 7, 32, p & 127, n);
            *reinterpret_cast<uint16_t*>(g_wpts + off)        = b2s(hb);
            *reinterpret_cast<uint16_t*>(g_wpts + (off ^ 64)) = b2s(lb);
        }
    }
}

// x fp32 (16384 rows x K=256) -> tiled sbf, nslab=8
__global__ void __launch_bounds__(NTHREADS) xconv_kernel(const float* __restrict__ src)
{
    long i = (long)blockIdx.x * NTHREADS + threadIdx.x;
    float4 v = reinterpret_cast<const float4*>(src)[i];
    long e = i * 4;
    int r = (int)(e >> 8), k = (int)(e & 255);
    size_t off = sbf_off(r >> 7, 8, r & 127, k);
    __nv_bfloat162 h0, l0, h1, l1;
    split2(v.x, v.y, h0, l0);
    split2(v.z, v.w, h1, l1);
    *reinterpret_cast<uint2*>(g_xs + off)        = make_uint2(b2u(h0), b2u(h1));
    *reinterpret_cast<uint2*>(g_xs + (off ^ 64)) = make_uint2(b2u(l0), b2u(l1));
}

// ---------------------------------------------------------------------------
// Stage 1: proj. grid (2, 128, 3).
// ---------------------------------------------------------------------------
__global__ void __launch_bounds__(NTHREADS, 2)
proj_kernel(const float* __restrict__ bq, const float* __restrict__ bk,
            const float* __restrict__ bv)
{
    extern __shared__ char smem[];
    int n0 = blockIdx.x * 128; long m0 = (long)blockIdx.y * 128; int sel = blockIdx.z;
    const float* bias = sel == 0 ? bq : sel == 1 ? bk : bv;
    float acc[4][4][4] = {};
    gemm_bulk<8>(g_xs + (m0 >> 7) * 8 * SLABB,
                 g_ws + (size_t)sel * 262144 + (size_t)(n0 >> 7) * 8 * SLABB,
                 smem, acc);
    if (sel < 2) {
        char* out = sel == 0 ? g_qs : g_ks;
        epi_sbf(acc, out, m0, n0, 8, bias + n0);
    } else {
        int b = (int)(m0 >> 10), tok0 = (int)(m0 & 1023);
        epi_sbf_t(acc, g_vts, (long)b * 256 + n0, tok0, 32, bias + n0, nullptr);
    }
}

// ---------------------------------------------------------------------------
// Stage 2: attn_un = exp(q k^T) -> tiled sbf + partials. grid (8, 8, 16)
// ---------------------------------------------------------------------------
__global__ void __launch_bounds__(NTHREADS, 2) scores_kernel()
{
    extern __shared__ char smem[];
    int n0 = blockIdx.x * 128, m0 = blockIdx.y * 128, b = blockIdx.z;
    float acc[4][4][4] = {};
    gemm_bulk<8>(g_qs + (size_t)((b * NTOK + m0) >> 7) * 8 * SLABB,
                 g_ks + (size_t)((b * NTOK + n0) >> 7) * 8 * SLABB,
                 smem, acc);
    epi_attn(acc, smem, g_attns, (long)b * NTOK + m0, n0,
             g_zp + ((long)b * 8 + blockIdx.x) * NTOK + m0);
}

// ---------------------------------------------------------------------------
// Stage 3: o^T = (attn_un @ v)^T / Z. grid (2, 8, 16)
// ---------------------------------------------------------------------------
__global__ void __launch_bounds__(NTHREADS, 2) av_kernel()
{
    extern __shared__ char smem[];
    int c0 = blockIdx.x * 128, tok0 = blockIdx.y * 128, b = blockIdx.z;
    float acc[4][4][4] = {};
    gemm_bulk<32>(g_attns + (size_t)(b * 8 + (tok0 >> 7)) * 32 * SLABB,
                  g_vts   + (size_t)(b * 2 + (c0 >> 7))   * 32 * SLABB,
                  smem, acc);
    __syncthreads();
    float* rzs = reinterpret_cast<float*>(smem);
    if (threadIdx.x < 128) {
        float z = 0.0f;
#pragma unroll
        for (int t = 0; t < 8; ++t)
            z += g_zp[((long)b * 8 + t) * NTOK + tok0 + threadIdx.x];
        rzs[threadIdx.x] = 1.0f / z;
    }
    __syncthreads();
    epi_sbf_t(acc, g_ots, (long)b * 256 + c0, tok0, 32, nullptr, rzs);
}

// ---------------------------------------------------------------------------
// Stage 4: z[b,p,c] = sum_n wpt[p][n] * ot[c][n]. grid (2, 8, 16)
// ---------------------------------------------------------------------------
__global__ void __launch_bounds__(NTHREADS, 2) final_kernel(float* __restrict__ z)
{
    extern __shared__ char smem[];
    int c0 = blockIdx.x * 128, p0 = blockIdx.y * 128, b = blockIdx.z;
    float acc[4][4][4] = {};
    gemm_bulk<32>(g_wpts + (size_t)(p0 >> 7) * 32 * SLABB,
                  g_ots  + (size_t)(b * 2 + (c0 >> 7)) * 32 * SLABB,
                  smem, acc);
    epi_f32(acc, z + ((long)b * NTOK + p0) * CDIM + c0, CDIM);
}

// ---------------------------------------------------------------------------
extern "C" void kernel_launch(void* const* d_in, const int* in_sizes, int n_in,
                              void* d_out, int out_size)
{
    const float* x  = (const float*)d_in[0];
    const float* Wq = (const float*)d_in[1];
    const float* bq = (const float*)d_in[2];
    const float* Wk = (const float*)d_in[3];
    const float* bk = (const float*)d_in[4];
    const float* Wv = (const float*)d_in[5];
    const float* bv = (const float*)d_in[6];
    const float* Wp = (const float*)d_in[7];
    float* out = (float*)d_out;

    cudaFuncSetAttribute(proj_kernel,   cudaFuncAttributeMaxDynamicSharedMemorySize, SMEM_BYTES);
    cudaFuncSetAttribute(scores_kernel, cudaFuncAttributeMaxDynamicSharedMemorySize, SMEM_BYTES);
    cudaFuncSetAttribute(av_kernel,     cudaFuncAttributeMaxDynamicSharedMemorySize, SMEM_BYTES);
    cudaFuncSetAttribute(final_kernel,  cudaFuncAttributeMaxDynamicSharedMemorySize, SMEM_BYTES);

    prep_kernel <<<dim3(1216), NTHREADS>>>(Wq, Wk, Wv, Wp);      // launch 1
    xconv_kernel<<<dim3(4096), NTHREADS>>>(x);                   // launch 2
    proj_kernel  <<<dim3(2, 128, 3), NTHREADS, SMEM_BYTES>>>(bq, bk, bv);  // 3
    scores_kernel<<<dim3(8, 8, 16),  NTHREADS, SMEM_BYTES>>>();            // 4 <- profiled
    av_kernel    <<<dim3(2, 8, 16),  NTHREADS, SMEM_BYTES>>>();            // 5
    final_kernel <<<dim3(2, 8, 16),  NTHREADS, SMEM_BYTES>>>(out);         // 6
}

// round 10
// speedup vs baseline: 3.1486x; 1.0744x over previous
#include <cuda_runtime.h>
#include <cuda_bf16.h>
#include <cuda_fp16.h>
#include <cstdint>

#define BATCH 16
#define NTOK  1024
#define CDIM  256
#define NTHREADS 256
#define NSTAGE 3
#define ASLAB 16384                     // A slab: 128 rows x 128B (hi+lo split)
#define BSLAB_FULL 16384                // B slab, split operand
#define BSLAB_HALF 8192                 // B slab, fp16-single operand (64B rows)
#define SMEM_3T (NSTAGE*(ASLAB+BSLAB_FULL) + 1024)   // 99328
#define SMEM_2T (NSTAGE*(ASLAB+BSLAB_HALF) + 1024)   // 74752

// ---------------------------------------------------------------------------
// Split tiled format ("s16"): rows grouped in tiles of 128; tile t, k-slab s
// (32 k) is a contiguous 16KB smem image: row r at r*128, 16B chunk cc at
// (cc ^ (r&7))*16; chunks 0-3 = hi of k0..31, 4-7 = lo (addr = hi ^ 64).
// Element type: fp16 pairs (x, W, q, k, Wp^T) or bf16 pairs (v^T, attn).
// Single fp16 format ("h16", o^T): slab 8KB, row r at r*64, chunk cc (0..3)
// at (cc ^ ((r>>1)&3))*16.
// ---------------------------------------------------------------------------
__device__ __align__(128) char g_xs  [16384*1024];      // x  fp16 split
__device__ __align__(128) char g_ws  [3*256*1024];      // W  fp16 split
__device__ __align__(128) char g_qs  [16384*1024];      // q  fp16 split
__device__ __align__(128) char g_ks  [16384*1024];      // k  fp16 split
__device__ __align__(128) char g_vts [16*256*4096];     // v^T  bf16 split
__device__ __align__(128) char g_ots [16*256*2048];     // o^T  fp16 single (8MB)
__device__ __align__(128) char g_attns[(size_t)16384*4096]; // exp(scores) bf16 split
__device__ __align__(128) char g_wpts[1024*4096];       // Wp^T fp16 split
__device__ float g_zp[BATCH*8*NTOK];

// ---------------------------------------------------------------------------
__device__ __forceinline__ uint32_t smem_u32(const void* p){
    uint32_t a;
    asm("{ .reg .u64 t; cvta.to.shared.u64 t, %1; cvt.u32.u64 %0, t; }" : "=r"(a) : "l"(p));
    return a;
}
__device__ __forceinline__ void ldsm4(uint32_t* r, uint32_t addr){
    asm volatile("ldmatrix.sync.aligned.m8n8.x4.shared.b16 {%0,%1,%2,%3}, [%4];"
        : "=r"(r[0]), "=r"(r[1]), "=r"(r[2]), "=r"(r[3]) : "r"(addr));
}
__device__ __forceinline__ void mma_bf16(float* d, const uint32_t* a, const uint32_t* b){
    asm volatile("mma.sync.aligned.m16n8k16.row.col.f32.bf16.bf16.f32 "
        "{%0,%1,%2,%3}, {%4,%5,%6,%7}, {%8,%9}, {%0,%1,%2,%3};"
        : "+f"(d[0]), "+f"(d[1]), "+f"(d[2]), "+f"(d[3])
        : "r"(a[0]), "r"(a[1]), "r"(a[2]), "r"(a[3]), "r"(b[0]), "r"(b[1]));
}
__device__ __forceinline__ void mma_f16(float* d, const uint32_t* a, const uint32_t* b){
    asm volatile("mma.sync.aligned.m16n8k16.row.col.f32.f16.f16.f32 "
        "{%0,%1,%2,%3}, {%4,%5,%6,%7}, {%8,%9}, {%0,%1,%2,%3};"
        : "+f"(d[0]), "+f"(d[1]), "+f"(d[2]), "+f"(d[3])
        : "r"(a[0]), "r"(a[1]), "r"(a[2]), "r"(a[3]), "r"(b[0]), "r"(b[1]));
}
template<int MODE>   // 0 = bf16, 1/2 = fp16
__device__ __forceinline__ void mma_any(float* d, const uint32_t* a, const uint32_t* b){
    if (MODE == 0) mma_bf16(d, a, b); else mma_f16(d, a, b);
}
__device__ __forceinline__ void split2b(float v0, float v1,
        __nv_bfloat162& h, __nv_bfloat162& l){
    h = __floats2bfloat162_rn(v0, v1);
    l = __floats2bfloat162_rn(v0 - __low2float(h), v1 - __high2float(h));
}
__device__ __forceinline__ void split2h(float v0, float v1, __half2& h, __half2& l){
    h = __floats2half2_rn(v0, v1);
    l = __floats2half2_rn(v0 - __half2float(__low2half(h)),
                          v1 - __half2float(__high2half(h)));
}
template<class T> __device__ __forceinline__ uint32_t b2u(T v){
    uint32_t u; memcpy(&u, &v, 4); return u;
}
template<class T> __device__ __forceinline__ uint16_t b2s(T v){
    uint16_t u; memcpy(&u, &v, 2); return u;
}

// split format: byte offset of hi element (tile-local row r, k); lo = off ^ 64
__device__ __forceinline__ size_t sbf_off(long tile, int nslab, int r, int k){
    int cc = (k & 31) >> 3;
    return ((size_t)(tile * nslab + (k >> 5)) << 14)
         + (size_t)(r * 128) + (size_t)(((cc ^ (r & 7)) << 4) + (k & 7) * 2);
}
// fp16-single format (8KB slabs, 64B rows)
__device__ __forceinline__ size_t h16_off(long tile, int nslab, int r, int k){
    int cc = (k & 31) >> 3;
    return ((size_t)(tile * nslab + (k >> 5)) << 13)
         + (size_t)(r * 64) + (size_t)(((cc ^ ((r >> 1) & 3)) << 4) + (k & 7) * 2);
}

#define MBAR_INIT(mb,c)  asm volatile("mbarrier.init.shared.b64 [%0], %1;" :: "r"(mb), "r"((uint32_t)(c)) : "memory")
#define MBAR_EXPECT(mb,n) asm volatile("mbarrier.arrive.expect_tx.shared.b64 _, [%0], %1;" :: "r"(mb), "r"((uint32_t)(n)) : "memory")
#define BULK_G2S(dst,src,n,mb) asm volatile("cp.async.bulk.shared::cta.global.mbarrier::complete_tx::bytes [%0], [%1], %2, [%3];" :: "r"(dst), "l"(src), "r"((uint32_t)(n)), "r"(mb) : "memory")
#define FENCE_ASYNC() asm volatile("fence.proxy.async.shared::cta;" ::: "memory")

#define MBAR_WAIT(mb, par) do { \
    uint32_t _m = (uint32_t)(mb), _p = (uint32_t)(par), _d; \
    asm volatile("{\n\t.reg .pred p;\n\t" \
        "mbarrier.try_wait.parity.acquire.cta.shared::cta.b64 p, [%1], %2;\n\t" \
        "selp.b32 %0, 1, 0, p;\n\t}" : "=r"(_d) : "r"(_m), "r"(_p) : "memory"); \
    if (!_d) { \
        asm volatile("{\n\t.reg .pred P1;\n\t" \
            "WL_%=:\n\t" \
            "mbarrier.try_wait.parity.acquire.cta.shared::cta.b64 P1, [%0], %1, 0x989680;\n\t" \
            "@P1 bra.uni WD_%=;\n\t" \
            "bra.uni WL_%=;\n\t" \
            "WD_%=:\n\t}" :: "r"(_m), "r"(_p) : "memory"); \
    } \
} while(0)

// ---------------------------------------------------------------------------
// 3-term compute (split A, split B). CTA 128x128, warps 2(M)x4(N).
// ---------------------------------------------------------------------------
template<int MODE>
__device__ __forceinline__ void compute_slab3(char* buf, float acc[4][4][4])
{
    int tid = threadIdx.x, lane = tid & 31, wid = tid >> 5;
    uint32_t sA = smem_u32(buf), sB = sA + ASLAB;
    int mw = (wid & 1) * 64, nw = (wid >> 1) * 32;
    int arow = lane & 15, ahalf = lane >> 4;
    int brow = (lane & 7) + ((lane >> 4) & 1) * 8, bhalf = (lane >> 3) & 1;

#pragma unroll
    for (int ks = 0; ks < 2; ++ks) {
        uint32_t bh[8], bl[8];
#pragma unroll
        for (int nj = 0; nj < 2; ++nj) {
            int r = nw + nj * 16 + brow;
            int c = ks * 2 + bhalf;
            ldsm4(bh + nj * 4, sB + r * 128 + (((c    ) ^ (r & 7)) << 4));
            ldsm4(bl + nj * 4, sB + r * 128 + (((c + 4) ^ (r & 7)) << 4));
        }
#pragma unroll
        for (int mi = 0; mi < 4; ++mi) {
            int r = mw + mi * 16 + arow;
            int c = ks * 2 + ahalf;
            uint32_t ah[4], al[4];
            ldsm4(ah, sA + r * 128 + (((c    ) ^ (r & 7)) << 4));
            ldsm4(al, sA + r * 128 + (((c + 4) ^ (r & 7)) << 4));
#pragma unroll
            for (int j = 0; j < 4; ++j) {
                const uint32_t* bhf = &bh[(j >> 1) * 4 + (j & 1) * 2];
                const uint32_t* blf = &bl[(j >> 1) * 4 + (j & 1) * 2];
                float* d = acc[mi][j];
                mma_any<MODE>(d, ah, bhf);
                mma_any<MODE>(d, al, bhf);
                mma_any<MODE>(d, ah, blf);
            }
        }
    }
}

// ---------------------------------------------------------------------------
// 2-term fp16 compute (split A, single-fp16 B in 64B-row layout).
// ---------------------------------------------------------------------------
__device__ __forceinline__ void compute_slab2(char* buf, float acc[4][4][4])
{
    int tid = threadIdx.x, lane = tid & 31, wid = tid >> 5;
    uint32_t sA = smem_u32(buf), sB = sA + ASLAB;
    int mw = (wid & 1) * 64, nw = (wid >> 1) * 32;
    int arow = lane & 15, ahalf = lane >> 4;
    int brow = (lane & 7) + ((lane >> 4) & 1) * 8, bhalf = (lane >> 3) & 1;

#pragma unroll
    for (int ks = 0; ks < 2; ++ks) {
        uint32_t bh[8];
#pragma unroll
        for (int nj = 0; nj < 2; ++nj) {
            int r = nw + nj * 16 + brow;
            int c = ks * 2 + bhalf;
            ldsm4(bh + nj * 4, sB + r * 64 + (((c ^ ((r >> 1) & 3))) << 4));
        }
#pragma unroll
        for (int mi = 0; mi < 4; ++mi) {
            int r = mw + mi * 16 + arow;
            int c = ks * 2 + ahalf;
            uint32_t ah[4], al[4];
            ldsm4(ah, sA + r * 128 + (((c    ) ^ (r & 7)) << 4));
            ldsm4(al, sA + r * 128 + (((c + 4) ^ (r & 7)) << 4));
#pragma unroll
            for (int j = 0; j < 4; ++j) {
                const uint32_t* bhf = &bh[(j >> 1) * 4 + (j & 1) * 2];
                float* d = acc[mi][j];
                mma_f16(d, ah, bhf);
                mma_f16(d, al, bhf);
            }
        }
    }
}

// ---------------------------------------------------------------------------
// Bulk-copy mainloop. MODE: 0 bf16 3-term, 1 fp16 3-term, 2 fp16 2-term.
// ---------------------------------------------------------------------------
template<int NC, int MODE>
__device__ __forceinline__ void gemm_bulk(const char* __restrict__ A,
                                          const char* __restrict__ B,
                                          char* smem, float acc[4][4][4])
{
    constexpr int BSL = (MODE == 2) ? BSLAB_HALF : BSLAB_FULL;
    constexpr int STG = ASLAB + BSL;
    uint32_t mb = smem_u32(smem + NSTAGE * STG);
    int tid = threadIdx.x;
    if (tid == 0) {
        MBAR_INIT(mb, 1); MBAR_INIT(mb + 8, 1); MBAR_INIT(mb + 16, 1);
        FENCE_ASYNC();
    }
    __syncthreads();
    if (tid == 0) {
#pragma unroll
        for (int s = 0; s < NSTAGE - 1; ++s) {
            uint32_t m = mb + 8 * s;
            uint32_t d = smem_u32(smem + s * STG);
            MBAR_EXPECT(m, STG);
            BULK_G2S(d,         A + (size_t)s * ASLAB, ASLAB, m);
            BULK_G2S(d + ASLAB, B + (size_t)s * BSL,   BSL,   m);
        }
    }
#pragma unroll 4
    for (int c = 0; c < NC; ++c) {
        int s = c % NSTAGE;
        MBAR_WAIT(mb + 8 * s, (c / NSTAGE) & 1);
        __syncthreads();
        int nc = c + NSTAGE - 1;
        if (tid == 0 && nc < NC) {
            int sn = nc % NSTAGE;
            uint32_t m = mb + 8 * sn;
            uint32_t d = smem_u32(smem + sn * STG);
            MBAR_EXPECT(m, STG);
            BULK_G2S(d,         A + (size_t)nc * ASLAB, ASLAB, m);
            BULK_G2S(d + ASLAB, B + (size_t)nc * BSL,   BSL,   m);
        }
        if (MODE == 2) compute_slab2(smem + s * STG, acc);
        else           compute_slab3<MODE>(smem + s * STG, acc);
    }
}

// ---------------------------------------------------------------------------
// Epilogues. Frag: d0,d1 -> (row=lane>>2, col=(lane&3)*2+e), d2,d3 row+8.
// ---------------------------------------------------------------------------
__device__ __forceinline__ void epi_f32(const float acc[4][4][4],
        float* __restrict__ Cg, int ldc)
{
    int tid = threadIdx.x, lane = tid & 31, wid = tid >> 5;
    int row0 = (wid & 1) * 64 + (lane >> 2), col0 = (wid >> 1) * 32 + (lane & 3) * 2;
#pragma unroll
    for (int mi = 0; mi < 4; ++mi)
#pragma unroll
        for (int j = 0; j < 4; ++j) {
            int c = col0 + j * 8;
#pragma unroll
            for (int h = 0; h < 2; ++h) {
                int r = row0 + mi * 16 + h * 8;
                *reinterpret_cast<float2*>(Cg + (long)r * ldc + c) =
                    make_float2(acc[mi][j][h * 2], acc[mi][j][h * 2 + 1]);
            }
        }
}

// split store, fp16 (q/k): C(128x128) -> tiled split fp16
__device__ __forceinline__ void epi_split_h(const float acc[4][4][4],
        char* base, long row0, int k0, int nslab, const float* __restrict__ bias)
{
    int tid = threadIdx.x, lane = tid & 31, wid = tid >> 5;
    long tile = row0 >> 7;
    int rw0 = (wid & 1) * 64 + (lane >> 2), cw0 = (wid >> 1) * 32 + (lane & 3) * 2;
#pragma unroll
    for (int mi = 0; mi < 4; ++mi)
#pragma unroll
        for (int j = 0; j < 4; ++j) {
            int c = cw0 + j * 8;
            float b0 = bias[c], b1 = bias[c + 1];
#pragma unroll
            for (int h = 0; h < 2; ++h) {
                int r = rw0 + mi * 16 + h * 8;
                __half2 hh, ll;
                split2h(acc[mi][j][h * 2] + b0, acc[mi][j][h * 2 + 1] + b1, hh, ll);
                size_t off = sbf_off(tile, nslab, r, k0 + c);
                *reinterpret_cast<uint32_t*>(base + off)        = b2u(hh);
                *reinterpret_cast<uint32_t*>(base + (off ^ 64)) = b2u(ll);
            }
        }
}

// transposed split store, bf16 (v^T): element (m,n) -> row rowbase+n, k=k0+m
__device__ __forceinline__ void epi_split_t_b(const float acc[4][4][4],
        char* base, long rowbase, int k0, int nslab, const float* __restrict__ bias)
{
    int tid = threadIdx.x, lane = tid & 31, wid = tid >> 5;
    long tile = rowbase >> 7;
    int rw0 = (wid & 1) * 64 + (lane >> 2), cw0 = (wid >> 1) * 32 + (lane & 3) * 2;
#pragma unroll
    for (int mi = 0; mi < 4; ++mi)
#pragma unroll
        for (int j = 0; j < 4; ++j)
#pragma unroll
            for (int h = 0; h < 2; ++h) {
                int m = rw0 + mi * 16 + h * 8;
#pragma unroll
                for (int e = 0; e < 2; ++e) {
                    int n = cw0 + j * 8 + e;
                    float v = acc[mi][j][h * 2 + e] + bias[n];
                    __nv_bfloat16 hb = __float2bfloat16(v);
                    __nv_bfloat16 lb = __float2bfloat16(v - __bfloat162float(hb));
                    size_t off = sbf_off(tile, nslab, n, k0 + m);
                    *reinterpret_cast<uint16_t*>(base + off)        = b2s(hb);
                    *reinterpret_cast<uint16_t*>(base + (off ^ 64)) = b2s(lb);
                }
            }
}

// transposed single-fp16 store with per-m scale (o^T)
__device__ __forceinline__ void epi_ot(const float acc[4][4][4],
        char* base, long rowbase, int k0, int nslab, const float* __restrict__ rz)
{
    int tid = threadIdx.x, lane = tid & 31, wid = tid >> 5;
    long tile = rowbase >> 7;
    int rw0 = (wid & 1) * 64 + (lane >> 2), cw0 = (wid >> 1) * 32 + (lane & 3) * 2;
#pragma unroll
    for (int mi = 0; mi < 4; ++mi)
#pragma unroll
        for (int j = 0; j < 4; ++j)
#pragma unroll
            for (int h = 0; h < 2; ++h) {
                int m = rw0 + mi * 16 + h * 8;
                float sc = rz[m];
#pragma unroll
                for (int e = 0; e < 2; ++e) {
                    int n = cw0 + j * 8 + e;
                    __half v = __float2half(acc[mi][j][h * 2 + e] * sc);
                    *reinterpret_cast<uint16_t*>(base + h16_off(tile, nslab, n, k0 + m)) = b2s(v);
                }
            }
}

// exp + bf16 split store + deterministic per-row partial sums -> g_zp
__device__ __forceinline__ void epi_attn(const float acc[4][4][4], char* smem,
        char* base, long row0, int k0, float* __restrict__ zp_out)
{
    int tid = threadIdx.x, lane = tid & 31, wid = tid >> 5;
    long tile = row0 >> 7;
    int rw0 = (wid & 1) * 64 + (lane >> 2), cw0 = (wid >> 1) * 32 + (lane & 3) * 2;
    float* zsm = reinterpret_cast<float*>(smem);
    __syncthreads();

    float ex[4][4][4];
#pragma unroll
    for (int mi = 0; mi < 4; ++mi) {
#pragma unroll
        for (int h = 0; h < 2; ++h) {
            float rs = 0.0f;
#pragma unroll
            for (int j = 0; j < 4; ++j) {
                float e0 = __expf(acc[mi][j][h * 2]);
                float e1 = __expf(acc[mi][j][h * 2 + 1]);
                ex[mi][j][h * 2] = e0; ex[mi][j][h * 2 + 1] = e1;
                rs += e0 + e1;
            }
            rs += __shfl_xor_sync(0xffffffffu, rs, 1);
            rs += __shfl_xor_sync(0xffffffffu, rs, 2);
            if ((lane & 3) == 0)
                zsm[(wid >> 1) * 128 + rw0 + mi * 16 + h * 8] = rs;
        }
    }
    __syncthreads();
    if (tid < 128)
        zp_out[tid] = zsm[tid] + zsm[128 + tid] + zsm[256 + tid] + zsm[384 + tid];
#pragma unroll
    for (int mi = 0; mi < 4; ++mi)
#pragma unroll
        for (int j = 0; j < 4; ++j) {
            int c = cw0 + j * 8;
#pragma unroll
            for (int h = 0; h < 2; ++h) {
                int r = rw0 + mi * 16 + h * 8;
                __nv_bfloat162 hh, ll;
                split2b(ex[mi][j][h * 2], ex[mi][j][h * 2 + 1], hh, ll);
                size_t off = sbf_off(tile, 32, r, k0 + c);
                *reinterpret_cast<uint32_t*>(base + off)        = b2u(hh);
                *reinterpret_cast<uint32_t*>(base + (off ^ 64)) = b2u(ll);
            }
        }
}

// ---------------------------------------------------------------------------
// Prep: W conversions fp16 (blocks 0..191) + Wp transpose fp16 (192..1215)
// ---------------------------------------------------------------------------
__global__ void __launch_bounds__(NTHREADS) prep_kernel(
        const float* __restrict__ Wq, const float* __restrict__ Wk,
        const float* __restrict__ Wv, const float* __restrict__ Wp)
{
    int bid = blockIdx.x;
    if (bid < 192) {
        int sel = bid >> 6;
        const float* src = sel == 0 ? Wq : sel == 1 ? Wk : Wv;
        char* dst = g_ws + (size_t)sel * 262144;
        long i = (long)(bid & 63) * NTHREADS + threadIdx.x;
        float4 v = reinterpret_cast<const float4*>(src)[i];
        long e = i * 4;
        int r = (int)(e >> 8), k = (int)(e & 255);
        size_t off = sbf_off(r >> 7, 8, r & 127, k);
        __half2 h0, l0, h1, l1;
        split2h(v.x, v.y, h0, l0);
        split2h(v.z, v.w, h1, l1);
        *reinterpret_cast<uint2*>(dst + off)        = make_uint2(b2u(h0), b2u(h1));
        *reinterpret_cast<uint2*>(dst + (off ^ 64)) = make_uint2(b2u(l0), b2u(l1));
    } else {
        __shared__ float t[32][33];
        int b2 = bid - 192;
        int h = b2 >> 5, n0 = (b2 & 31) * 32;
        int tx = threadIdx.x & 31, ty = threadIdx.x >> 5;
        const float* src = Wp + (long)h * 32768 + (long)n0 * 32;
#pragma unroll
        for (int i = 0; i < 4; ++i) t[ty + i * 8][tx] = src[(ty + i * 8) * 32 + tx];
        __syncthreads();
#pragma unroll
        for (int i = 0; i < 4; ++i) {
            int w = ty + i * 8;
            float v = t[tx][w];
            int p = h * 32 + w, n = n0 + tx;
            __half hb = __float2half(v);
            __half lb = __float2half(v - __half2float(hb));
            size_t off = sbf_off(p >> 7, 32, p & 127, n);
            *reinterpret_cast<uint16_t*>(g_wpts + off)        = b2s(hb);
            *reinterpret_cast<uint16_t*>(g_wpts + (off ^ 64)) = b2s(lb);
        }
    }
}

// x fp32 -> fp16 split tiled
__global__ void __launch_bounds__(NTHREADS) xconv_kernel(const float* __restrict__ src)
{
    long i = (long)blockIdx.x * NTHREADS + threadIdx.x;
    float4 v = reinterpret_cast<const float4*>(src)[i];
    long e = i * 4;
    int r = (int)(e >> 8), k = (int)(e & 255);
    size_t off = sbf_off(r >> 7, 8, r & 127, k);
    __half2 h0, l0, h1, l1;
    split2h(v.x, v.y, h0, l0);
    split2h(v.z, v.w, h1, l1);
    *reinterpret_cast<uint2*>(g_xs + off)        = make_uint2(b2u(h0), b2u(h1));
    *reinterpret_cast<uint2*>(g_xs + (off ^ 64)) = make_uint2(b2u(l0), b2u(l1));
}

// ---------------------------------------------------------------------------
// Stage 1: proj (fp16 3-term). grid (2, 128, 3).
// ---------------------------------------------------------------------------
__global__ void __launch_bounds__(NTHREADS, 2)
proj_kernel(const float* __restrict__ bq, const float* __restrict__ bk,
            const float* __restrict__ bv)
{
    extern __shared__ char smem[];
    int n0 = blockIdx.x * 128; long m0 = (long)blockIdx.y * 128; int sel = blockIdx.z;
    const float* bias = sel == 0 ? bq : sel == 1 ? bk : bv;
    float acc[4][4][4] = {};
    gemm_bulk<8, 1>(g_xs + (m0 >> 7) * 8 * ASLAB,
                    g_ws + (size_t)sel * 262144 + (size_t)(n0 >> 7) * 8 * ASLAB,
                    smem, acc);
    if (sel < 2) {
        char* out = sel == 0 ? g_qs : g_ks;
        epi_split_h(acc, out, m0, n0, 8, bias + n0);
    } else {
        int b = (int)(m0 >> 10), tok0 = (int)(m0 & 1023);
        epi_split_t_b(acc, g_vts, (long)b * 256 + n0, tok0, 32, bias + n0);
    }
}

// ---------------------------------------------------------------------------
// Stage 2: attn_un = exp(q k^T), fp16 3-term. grid (8, 8, 16)
// ---------------------------------------------------------------------------
__global__ void __launch_bounds__(NTHREADS, 2) scores_kernel()
{
    extern __shared__ char smem[];
    int n0 = blockIdx.x * 128, m0 = blockIdx.y * 128, b = blockIdx.z;
    float acc[4][4][4] = {};
    gemm_bulk<8, 1>(g_qs + (size_t)((b * NTOK + m0) >> 7) * 8 * ASLAB,
                    g_ks + (size_t)((b * NTOK + n0) >> 7) * 8 * ASLAB,
                    smem, acc);
    epi_attn(acc, smem, g_attns, (long)b * NTOK + m0, n0,
             g_zp + ((long)b * 8 + blockIdx.x) * NTOK + m0);
}

// ---------------------------------------------------------------------------
// Stage 3: o^T = (attn_un @ v)^T / Z, bf16 3-term. grid (2, 8, 16)
// ---------------------------------------------------------------------------
__global__ void __launch_bounds__(NTHREADS, 2) av_kernel()
{
    extern __shared__ char smem[];
    int c0 = blockIdx.x * 128, tok0 = blockIdx.y * 128, b = blockIdx.z;
    float acc[4][4][4] = {};
    gemm_bulk<32, 0>(g_attns + (size_t)(b * 8 + (tok0 >> 7)) * 32 * ASLAB,
                     g_vts   + (size_t)(b * 2 + (c0 >> 7))   * 32 * ASLAB,
                     smem, acc);
    __syncthreads();
    float* rzs = reinterpret_cast<float*>(smem);
    if (threadIdx.x < 128) {
        float z = 0.0f;
#pragma unroll
        for (int t = 0; t < 8; ++t)
            z += g_zp[((long)b * 8 + t) * NTOK + tok0 + threadIdx.x];
        rzs[threadIdx.x] = 1.0f / z;
    }
    __syncthreads();
    epi_ot(acc, g_ots, (long)b * 256 + c0, tok0, 32, rzs);
}

// ---------------------------------------------------------------------------
// Stage 4: z = Wp^T o, fp16 2-term. grid (2, 8, 16)
// ---------------------------------------------------------------------------
__global__ void __launch_bounds__(NTHREADS, 2) final_kernel(float* __restrict__ z)
{
    extern __shared__ char smem[];
    int c0 = blockIdx.x * 128, p0 = blockIdx.y * 128, b = blockIdx.z;
    float acc[4][4][4] = {};
    gemm_bulk<32, 2>(g_wpts + (size_t)(p0 >> 7) * 32 * ASLAB,
                     g_ots  + (size_t)(b * 2 + (c0 >> 7)) * 32 * BSLAB_HALF,
                     smem, acc);
    epi_f32(acc, z + ((long)b * NTOK + p0) * CDIM + c0, CDIM);
}

// ---------------------------------------------------------------------------
extern "C" void kernel_launch(void* const* d_in, const int* in_sizes, int n_in,
                              void* d_out, int out_size)
{
    const float* x  = (const float*)d_in[0];
    const float* Wq = (const float*)d_in[1];
    const float* bq = (const float*)d_in[2];
    const float* Wk = (const float*)d_in[3];
    const float* bk = (const float*)d_in[4];
    const float* Wv = (const float*)d_in[5];
    const float* bv = (const float*)d_in[6];
    const float* Wp = (const float*)d_in[7];
    float* out = (float*)d_out;

    cudaFuncSetAttribute(proj_kernel,   cudaFuncAttributeMaxDynamicSharedMemorySize, SMEM_3T);
    cudaFuncSetAttribute(scores_kernel, cudaFuncAttributeMaxDynamicSharedMemorySize, SMEM_3T);
    cudaFuncSetAttribute(av_kernel,     cudaFuncAttributeMaxDynamicSharedMemorySize, SMEM_3T);
    cudaFuncSetAttribute(final_kernel,  cudaFuncAttributeMaxDynamicSharedMemorySize, SMEM_2T);

    prep_kernel <<<dim3(1216), NTHREADS>>>(Wq, Wk, Wv, Wp);                // 1
    xconv_kernel<<<dim3(4096), NTHREADS>>>(x);                             // 2
    proj_kernel  <<<dim3(2, 128, 3), NTHREADS, SMEM_3T>>>(bq, bk, bv);     // 3
    scores_kernel<<<dim3(8, 8, 16),  NTHREADS, SMEM_3T>>>();               // 4 <- profiled
    av_kernel    <<<dim3(2, 8, 16),  NTHREADS, SMEM_3T>>>();               // 5
    final_kernel <<<dim3(2, 8, 16),  NTHREADS, SMEM_2T>>>(out);            // 6
}

// round 11
// speedup vs baseline: 3.2389x; 1.0287x over previous
#include <cuda_runtime.h>
#include <cuda_bf16.h>
#include <cuda_fp16.h>
#include <cstdint>

#define BATCH 16
#define NTOK  1024
#define CDIM  256
#define NTHREADS 256
#define NSTAGE 3
#define SLAB_F 16384                    // split slab: 128 rows x 128B
#define SLAB_H 8192                     // single-fp16 slab: 128 rows x 64B
#define SMEM_3T (NSTAGE*2*SLAB_F + 1024)   // 99328
#define SMEM_1T (NSTAGE*2*SLAB_H + 1024)   // 50176

// ---------------------------------------------------------------------------
// Split tiled format: rows in tiles of 128; tile t, k-slab s (32 k) is a
// contiguous 16KB smem image: row r at r*128, 16B chunk cc at (cc^(r&7))*16;
// chunks 0-3 hi, 4-7 lo (addr = hi ^ 64). fp16 pairs or bf16 pairs.
// Single-fp16 format: 8KB slabs, row r at r*64, chunk cc at (cc^((r>>1)&3))*16.
// ---------------------------------------------------------------------------
__device__ __align__(128) char g_xs  [16384*1024];      // x    fp16 split
__device__ __align__(128) char g_wvs [256*1024];        // Wv   fp16 split
__device__ __align__(128) char g_mts [256*1024];        // Mt = (Wq^T Wk)^T layout [e][c], fp16 split
__device__ __align__(128) char g_qms [16384*1024];      // qm = x·M, fp16 split
__device__ __align__(128) char g_vts [16*256*4096];     // v^T  bf16 split
__device__ __align__(128) char g_ots [16*256*2048];     // o^T  fp16 single
__device__ __align__(128) char g_attns[(size_t)16384*4096]; // exp(scores) bf16 split
__device__ __align__(128) char g_wpts[1024*2048];       // Wp^T fp16 single
__device__ float g_zp[BATCH*8*NTOK];
__device__ float g_w[BATCH*NTOK];                       // w_j = x_j . (Wk^T bq)
__device__ float g_beta[256];
__device__ float g_zero[256];                           // zero-initialized

// ---------------------------------------------------------------------------
__device__ __forceinline__ uint32_t smem_u32(const void* p){
    uint32_t a;
    asm("{ .reg .u64 t; cvta.to.shared.u64 t, %1; cvt.u32.u64 %0, t; }" : "=r"(a) : "l"(p));
    return a;
}
__device__ __forceinline__ void ldsm4(uint32_t* r, uint32_t addr){
    asm volatile("ldmatrix.sync.aligned.m8n8.x4.shared.b16 {%0,%1,%2,%3}, [%4];"
        : "=r"(r[0]), "=r"(r[1]), "=r"(r[2]), "=r"(r[3]) : "r"(addr));
}
__device__ __forceinline__ void mma_bf16(float* d, const uint32_t* a, const uint32_t* b){
    asm volatile("mma.sync.aligned.m16n8k16.row.col.f32.bf16.bf16.f32 "
        "{%0,%1,%2,%3}, {%4,%5,%6,%7}, {%8,%9}, {%0,%1,%2,%3};"
        : "+f"(d[0]), "+f"(d[1]), "+f"(d[2]), "+f"(d[3])
        : "r"(a[0]), "r"(a[1]), "r"(a[2]), "r"(a[3]), "r"(b[0]), "r"(b[1]));
}
__device__ __forceinline__ void mma_f16(float* d, const uint32_t* a, const uint32_t* b){
    asm volatile("mma.sync.aligned.m16n8k16.row.col.f32.f16.f16.f32 "
        "{%0,%1,%2,%3}, {%4,%5,%6,%7}, {%8,%9}, {%0,%1,%2,%3};"
        : "+f"(d[0]), "+f"(d[1]), "+f"(d[2]), "+f"(d[3])
        : "r"(a[0]), "r"(a[1]), "r"(a[2]), "r"(a[3]), "r"(b[0]), "r"(b[1]));
}
template<int MODE>   // 0 = bf16, 1 = fp16
__device__ __forceinline__ void mma_any(float* d, const uint32_t* a, const uint32_t* b){
    if (MODE == 0) mma_bf16(d, a, b); else mma_f16(d, a, b);
}
__device__ __forceinline__ void split2b(float v0, float v1,
        __nv_bfloat162& h, __nv_bfloat162& l){
    h = __floats2bfloat162_rn(v0, v1);
    l = __floats2bfloat162_rn(v0 - __low2float(h), v1 - __high2float(h));
}
__device__ __forceinline__ void split2h(float v0, float v1, __half2& h, __half2& l){
    h = __floats2half2_rn(v0, v1);
    l = __floats2half2_rn(v0 - __half2float(__low2half(h)),
                          v1 - __half2float(__high2half(h)));
}
template<class T> __device__ __forceinline__ uint32_t b2u(T v){
    uint32_t u; memcpy(&u, &v, 4); return u;
}
template<class T> __device__ __forceinline__ uint16_t b2s(T v){
    uint16_t u; memcpy(&u, &v, 2); return u;
}

// split format: byte offset of hi element (tile-local row r, k); lo = off ^ 64
__device__ __forceinline__ size_t sbf_off(long tile, int nslab, int r, int k){
    int cc = (k & 31) >> 3;
    return ((size_t)(tile * nslab + (k >> 5)) << 14)
         + (size_t)(r * 128) + (size_t)(((cc ^ (r & 7)) << 4) + (k & 7) * 2);
}
// single-fp16 format
__device__ __forceinline__ size_t h16_off(long tile, int nslab, int r, int k){
    int cc = (k & 31) >> 3;
    return ((size_t)(tile * nslab + (k >> 5)) << 13)
         + (size_t)(r * 64) + (size_t)(((cc ^ ((r >> 1) & 3)) << 4) + (k & 7) * 2);
}

#define MBAR_INIT(mb,c)  asm volatile("mbarrier.init.shared.b64 [%0], %1;" :: "r"(mb), "r"((uint32_t)(c)) : "memory")
#define MBAR_EXPECT(mb,n) asm volatile("mbarrier.arrive.expect_tx.shared.b64 _, [%0], %1;" :: "r"(mb), "r"((uint32_t)(n)) : "memory")
#define BULK_G2S(dst,src,n,mb) asm volatile("cp.async.bulk.shared::cta.global.mbarrier::complete_tx::bytes [%0], [%1], %2, [%3];" :: "r"(dst), "l"(src), "r"((uint32_t)(n)), "r"(mb) : "memory")
#define FENCE_ASYNC() asm volatile("fence.proxy.async.shared::cta;" ::: "memory")

#define MBAR_WAIT(mb, par) do { \
    uint32_t _m = (uint32_t)(mb), _p = (uint32_t)(par), _d; \
    asm volatile("{\n\t.reg .pred p;\n\t" \
        "mbarrier.try_wait.parity.acquire.cta.shared::cta.b64 p, [%1], %2;\n\t" \
        "selp.b32 %0, 1, 0, p;\n\t}" : "=r"(_d) : "r"(_m), "r"(_p) : "memory"); \
    if (!_d) { \
        asm volatile("{\n\t.reg .pred P1;\n\t" \
            "WL_%=:\n\t" \
            "mbarrier.try_wait.parity.acquire.cta.shared::cta.b64 P1, [%0], %1, 0x989680;\n\t" \
            "@P1 bra.uni WD_%=;\n\t" \
            "bra.uni WL_%=;\n\t" \
            "WD_%=:\n\t}" :: "r"(_m), "r"(_p) : "memory"); \
    } \
} while(0)

// ---------------------------------------------------------------------------
// 3-term compute (split A, split B). CTA 128x128, warps 2(M)x4(N).
// ---------------------------------------------------------------------------
template<int MODE>
__device__ __forceinline__ void compute_slab3(char* buf, float acc[4][4][4])
{
    int tid = threadIdx.x, lane = tid & 31, wid = tid >> 5;
    uint32_t sA = smem_u32(buf), sB = sA + SLAB_F;
    int mw = (wid & 1) * 64, nw = (wid >> 1) * 32;
    int arow = lane & 15, ahalf = lane >> 4;
    int brow = (lane & 7) + ((lane >> 4) & 1) * 8, bhalf = (lane >> 3) & 1;

#pragma unroll
    for (int ks = 0; ks < 2; ++ks) {
        uint32_t bh[8], bl[8];
#pragma unroll
        for (int nj = 0; nj < 2; ++nj) {
            int r = nw + nj * 16 + brow;
            int c = ks * 2 + bhalf;
            ldsm4(bh + nj * 4, sB + r * 128 + (((c    ) ^ (r & 7)) << 4));
            ldsm4(bl + nj * 4, sB + r * 128 + (((c + 4) ^ (r & 7)) << 4));
        }
#pragma unroll
        for (int mi = 0; mi < 4; ++mi) {
            int r = mw + mi * 16 + arow;
            int c = ks * 2 + ahalf;
            uint32_t ah[4], al[4];
            ldsm4(ah, sA + r * 128 + (((c    ) ^ (r & 7)) << 4));
            ldsm4(al, sA + r * 128 + (((c + 4) ^ (r & 7)) << 4));
#pragma unroll
            for (int j = 0; j < 4; ++j) {
                const uint32_t* bhf = &bh[(j >> 1) * 4 + (j & 1) * 2];
                const uint32_t* blf = &bl[(j >> 1) * 4 + (j & 1) * 2];
                float* d = acc[mi][j];
                mma_any<MODE>(d, ah, bhf);
                mma_any<MODE>(d, al, bhf);
                mma_any<MODE>(d, ah, blf);
            }
        }
    }
}

// ---------------------------------------------------------------------------
// 1-term fp16 compute (single A, single B; 64B rows).
// ---------------------------------------------------------------------------
__device__ __forceinline__ void compute_slab1(char* buf, float acc[4][4][4])
{
    int tid = threadIdx.x, lane = tid & 31, wid = tid >> 5;
    uint32_t sA = smem_u32(buf), sB = sA + SLAB_H;
    int mw = (wid & 1) * 64, nw = (wid >> 1) * 32;
    int arow = lane & 15, ahalf = lane >> 4;
    int brow = (lane & 7) + ((lane >> 4) & 1) * 8, bhalf = (lane >> 3) & 1;

#pragma unroll
    for (int ks = 0; ks < 2; ++ks) {
        uint32_t bh[8];
#pragma unroll
        for (int nj = 0; nj < 2; ++nj) {
            int r = nw + nj * 16 + brow;
            int c = ks * 2 + bhalf;
            ldsm4(bh + nj * 4, sB + r * 64 + ((c ^ ((r >> 1) & 3)) << 4));
        }
#pragma unroll
        for (int mi = 0; mi < 4; ++mi) {
            int r = mw + mi * 16 + arow;
            int c = ks * 2 + ahalf;
            uint32_t ah[4];
            ldsm4(ah, sA + r * 64 + ((c ^ ((r >> 1) & 3)) << 4));
#pragma unroll
            for (int j = 0; j < 4; ++j)
                mma_f16(acc[mi][j], ah, &bh[(j >> 1) * 4 + (j & 1) * 2]);
        }
    }
}

// ---------------------------------------------------------------------------
// Bulk-copy mainloop. MODE: 0 bf16 3-term, 1 fp16 3-term, 3 fp16 1-term.
// ---------------------------------------------------------------------------
template<int NC, int MODE>
__device__ __forceinline__ void gemm_bulk(const char* __restrict__ A,
                                          const char* __restrict__ B,
                                          char* smem, float acc[4][4][4])
{
    constexpr int SL  = (MODE == 3) ? SLAB_H : SLAB_F;
    constexpr int STG = 2 * SL;
    uint32_t mb = smem_u32(smem + NSTAGE * STG);
    int tid = threadIdx.x;
    if (tid == 0) {
        MBAR_INIT(mb, 1); MBAR_INIT(mb + 8, 1); MBAR_INIT(mb + 16, 1);
        FENCE_ASYNC();
    }
    __syncthreads();
    if (tid == 0) {
#pragma unroll
        for (int s = 0; s < NSTAGE - 1; ++s) {
            uint32_t m = mb + 8 * s;
            uint32_t d = smem_u32(smem + s * STG);
            MBAR_EXPECT(m, STG);
            BULK_G2S(d,      A + (size_t)s * SL, SL, m);
            BULK_G2S(d + SL, B + (size_t)s * SL, SL, m);
        }
    }
#pragma unroll 4
    for (int c = 0; c < NC; ++c) {
        int s = c % NSTAGE;
        MBAR_WAIT(mb + 8 * s, (c / NSTAGE) & 1);
        __syncthreads();
        int nc = c + NSTAGE - 1;
        if (tid == 0 && nc < NC) {
            int sn = nc % NSTAGE;
            uint32_t m = mb + 8 * sn;
            uint32_t d = smem_u32(smem + sn * STG);
            MBAR_EXPECT(m, STG);
            BULK_G2S(d,      A + (size_t)nc * SL, SL, m);
            BULK_G2S(d + SL, B + (size_t)nc * SL, SL, m);
        }
        if (MODE == 3) compute_slab1(smem + s * STG, acc);
        else           compute_slab3<MODE>(smem + s * STG, acc);
    }
}

// ---------------------------------------------------------------------------
// Epilogues. Frag: d0,d1 -> (row=lane>>2, col=(lane&3)*2+e), d2,d3 row+8.
// ---------------------------------------------------------------------------
__device__ __forceinline__ void epi_f32(const float acc[4][4][4],
        float* __restrict__ Cg, int ldc)
{
    int tid = threadIdx.x, lane = tid & 31, wid = tid >> 5;
    int row0 = (wid & 1) * 64 + (lane >> 2), col0 = (wid >> 1) * 32 + (lane & 3) * 2;
#pragma unroll
    for (int mi = 0; mi < 4; ++mi)
#pragma unroll
        for (int j = 0; j < 4; ++j) {
            int c = col0 + j * 8;
#pragma unroll
            for (int h = 0; h < 2; ++h) {
                int r = row0 + mi * 16 + h * 8;
                *reinterpret_cast<float2*>(Cg + (long)r * ldc + c) =
                    make_float2(acc[mi][j][h * 2], acc[mi][j][h * 2 + 1]);
            }
        }
}

// split fp16 store (qm)
__device__ __forceinline__ void epi_split_h(const float acc[4][4][4],
        char* base, long row0, int k0, int nslab, const float* __restrict__ bias)
{
    int tid = threadIdx.x, lane = tid & 31, wid = tid >> 5;
    long tile = row0 >> 7;
    int rw0 = (wid & 1) * 64 + (lane >> 2), cw0 = (wid >> 1) * 32 + (lane & 3) * 2;
#pragma unroll
    for (int mi = 0; mi < 4; ++mi)
#pragma unroll
        for (int j = 0; j < 4; ++j) {
            int c = cw0 + j * 8;
            float b0 = bias[c], b1 = bias[c + 1];
#pragma unroll
            for (int h = 0; h < 2; ++h) {
                int r = rw0 + mi * 16 + h * 8;
                __half2 hh, ll;
                split2h(acc[mi][j][h * 2] + b0, acc[mi][j][h * 2 + 1] + b1, hh, ll);
                size_t off = sbf_off(tile, nslab, r, k0 + c);
                *reinterpret_cast<uint32_t*>(base + off)        = b2u(hh);
                *reinterpret_cast<uint32_t*>(base + (off ^ 64)) = b2u(ll);
            }
        }
}

// transposed bf16 split store (v^T)
__device__ __forceinline__ void epi_split_t_b(const float acc[4][4][4],
        char* base, long rowbase, int k0, int nslab, const float* __restrict__ bias)
{
    int tid = threadIdx.x, lane = tid & 31, wid = tid >> 5;
    long tile = rowbase >> 7;
    int rw0 = (wid & 1) * 64 + (lane >> 2), cw0 = (wid >> 1) * 32 + (lane & 3) * 2;
#pragma unroll
    for (int mi = 0; mi < 4; ++mi)
#pragma unroll
        for (int j = 0; j < 4; ++j)
#pragma unroll
            for (int h = 0; h < 2; ++h) {
                int m = rw0 + mi * 16 + h * 8;
#pragma unroll
                for (int e = 0; e < 2; ++e) {
                    int n = cw0 + j * 8 + e;
                    float v = acc[mi][j][h * 2 + e] + bias[n];
                    __nv_bfloat16 hb = __float2bfloat16(v);
                    __nv_bfloat16 lb = __float2bfloat16(v - __bfloat162float(hb));
                    size_t off = sbf_off(tile, nslab, n, k0 + m);
                    *reinterpret_cast<uint16_t*>(base + off)        = b2s(hb);
                    *reinterpret_cast<uint16_t*>(base + (off ^ 64)) = b2s(lb);
                }
            }
}

// transposed single-fp16 store with per-m scale (o^T)
__device__ __forceinline__ void epi_ot(const float acc[4][4][4],
        char* base, long rowbase, int k0, int nslab, const float* __restrict__ rz)
{
    int tid = threadIdx.x, lane = tid & 31, wid = tid >> 5;
    long tile = rowbase >> 7;
    int rw0 = (wid & 1) * 64 + (lane >> 2), cw0 = (wid >> 1) * 32 + (lane & 3) * 2;
#pragma unroll
    for (int mi = 0; mi < 4; ++mi)
#pragma unroll
        for (int j = 0; j < 4; ++j)
#pragma unroll
            for (int h = 0; h < 2; ++h) {
                int m = rw0 + mi * 16 + h * 8;
                float sc = rz[m];
#pragma unroll
                for (int e = 0; e < 2; ++e) {
                    int n = cw0 + j * 8 + e;
                    __half v = __float2half(acc[mi][j][h * 2 + e] * sc);
                    *reinterpret_cast<uint16_t*>(base + h16_off(tile, nslab, n, k0 + m)) = b2s(v);
                }
            }
}

// exp(acc + w_col) + bf16 split store + per-row partial sums -> g_zp
__device__ __forceinline__ void epi_attn(const float acc[4][4][4], char* smem,
        char* base, long row0, int k0, const float* __restrict__ wcol,
        float* __restrict__ zp_out)
{
    int tid = threadIdx.x, lane = tid & 31, wid = tid >> 5;
    long tile = row0 >> 7;
    int rw0 = (wid & 1) * 64 + (lane >> 2), cw0 = (wid >> 1) * 32 + (lane & 3) * 2;
    float* zsm = reinterpret_cast<float*>(smem);
    __syncthreads();

    float wc[8];
#pragma unroll
    for (int j = 0; j < 4; ++j) {
        wc[j * 2]     = wcol[cw0 + j * 8];
        wc[j * 2 + 1] = wcol[cw0 + j * 8 + 1];
    }

    float ex[4][4][4];
#pragma unroll
    for (int mi = 0; mi < 4; ++mi) {
#pragma unroll
        for (int h = 0; h < 2; ++h) {
            float rs = 0.0f;
#pragma unroll
            for (int j = 0; j < 4; ++j) {
                float e0 = __expf(acc[mi][j][h * 2]     + wc[j * 2]);
                float e1 = __expf(acc[mi][j][h * 2 + 1] + wc[j * 2 + 1]);
                ex[mi][j][h * 2] = e0; ex[mi][j][h * 2 + 1] = e1;
                rs += e0 + e1;
            }
            rs += __shfl_xor_sync(0xffffffffu, rs, 1);
            rs += __shfl_xor_sync(0xffffffffu, rs, 2);
            if ((lane & 3) == 0)
                zsm[(wid >> 1) * 128 + rw0 + mi * 16 + h * 8] = rs;
        }
    }
    __syncthreads();
    if (tid < 128)
        zp_out[tid] = zsm[tid] + zsm[128 + tid] + zsm[256 + tid] + zsm[384 + tid];
#pragma unroll
    for (int mi = 0; mi < 4; ++mi)
#pragma unroll
        for (int j = 0; j < 4; ++j) {
            int c = cw0 + j * 8;
#pragma unroll
            for (int h = 0; h < 2; ++h) {
                int r = rw0 + mi * 16 + h * 8;
                __nv_bfloat162 hh, ll;
                split2b(ex[mi][j][h * 2], ex[mi][j][h * 2 + 1], hh, ll);
                size_t off = sbf_off(tile, 32, r, k0 + c);
                *reinterpret_cast<uint32_t*>(base + off)        = b2u(hh);
                *reinterpret_cast<uint32_t*>(base + (off ^ 64)) = b2u(ll);
            }
        }
}

// ---------------------------------------------------------------------------
// Prep: Wv conv (0..63) | Wp^T single fp16 (64..1087) | Mt tiles (1088..1103)
//       | beta (1104)
// ---------------------------------------------------------------------------
__global__ void __launch_bounds__(NTHREADS) prep_kernel(
        const float* __restrict__ Wq, const float* __restrict__ Wk,
        const float* __restrict__ Wv, const float* __restrict__ Wp,
        const float* __restrict__ bq)
{
    int bid = blockIdx.x, tid = threadIdx.x;
    if (bid < 64) {
        long i = (long)bid * NTHREADS + tid;
        float4 v = reinterpret_cast<const float4*>(Wv)[i];
        long e = i * 4;
        int r = (int)(e >> 8), k = (int)(e & 255);
        size_t off = sbf_off(r >> 7, 8, r & 127, k);
        __half2 h0, l0, h1, l1;
        split2h(v.x, v.y, h0, l0);
        split2h(v.z, v.w, h1, l1);
        *reinterpret_cast<uint2*>(g_wvs + off)        = make_uint2(b2u(h0), b2u(h1));
        *reinterpret_cast<uint2*>(g_wvs + (off ^ 64)) = make_uint2(b2u(l0), b2u(l1));
    } else if (bid < 1088) {
        __shared__ float t[32][33];
        int b2 = bid - 64;
        int h = b2 >> 5, n0 = (b2 & 31) * 32;
        int tx = tid & 31, ty = tid >> 5;
        const float* src = Wp + (long)h * 32768 + (long)n0 * 32;
#pragma unroll
        for (int i = 0; i < 4; ++i) t[ty + i * 8][tx] = src[(ty + i * 8) * 32 + tx];
        __syncthreads();
#pragma unroll
        for (int i = 0; i < 4; ++i) {
            int w = ty + i * 8;
            int p = h * 32 + w, n = n0 + tx;
            __half hb = __float2half(t[tx][w]);
            *reinterpret_cast<uint16_t*>(g_wpts + h16_off(p >> 7, 32, p & 127, n)) = b2s(hb);
        }
    } else if (bid < 1104) {
        // Mt[e][c] = sum_d Wk[d][e] * Wq[d][c], 64x64 tile, fp32 accum
        __shared__ float As[32][64], Bs[32][64];
        int mt = bid - 1088;
        int e0 = (mt >> 2) * 64, c0 = (mt & 3) * 64;
        int tx = tid & 15, ty = tid >> 4;
        float acc[4][4] = {};
        for (int k0 = 0; k0 < 256; k0 += 32) {
            for (int i = tid; i < 2048; i += NTHREADS) {
                int dd = i >> 6, ee = i & 63;
                As[dd][ee] = Wk[(long)(k0 + dd) * 256 + e0 + ee];
                Bs[dd][ee] = Wq[(long)(k0 + dd) * 256 + c0 + ee];
            }
            __syncthreads();
#pragma unroll 8
            for (int dd = 0; dd < 32; ++dd) {
                float a[4], b[4];
#pragma unroll
                for (int i = 0; i < 4; ++i) { a[i] = As[dd][ty * 4 + i]; b[i] = Bs[dd][tx * 4 + i]; }
#pragma unroll
                for (int i = 0; i < 4; ++i)
#pragma unroll
                    for (int j = 0; j < 4; ++j) acc[i][j] += a[i] * b[j];
            }
            __syncthreads();
        }
#pragma unroll
        for (int i = 0; i < 4; ++i)
#pragma unroll
            for (int j = 0; j < 4; ++j) {
                int e = e0 + ty * 4 + i, c = c0 + tx * 4 + j;
                __half hb = __float2half(acc[i][j]);
                __half lb = __float2half(acc[i][j] - __half2float(hb));
                size_t off = sbf_off(e >> 7, 8, e & 127, c);
                *reinterpret_cast<uint16_t*>(g_mts + off)        = b2s(hb);
                *reinterpret_cast<uint16_t*>(g_mts + (off ^ 64)) = b2s(lb);
            }
    } else {
        // beta_c = sum_d Wk[d][c] * bq[d]
        int c = tid;
        float acc = 0.0f;
        for (int d = 0; d < 256; ++d) acc += Wk[(long)d * 256 + c] * bq[d];
        g_beta[c] = acc;
    }
}

// x conv (0..4095) + w vector (4096..6143, 8 rows/block)
__global__ void __launch_bounds__(NTHREADS) xconv_kernel(const float* __restrict__ src)
{
    int bid = blockIdx.x, tid = threadIdx.x;
    if (bid < 4096) {
        long i = (long)bid * NTHREADS + tid;
        float4 v = reinterpret_cast<const float4*>(src)[i];
        long e = i * 4;
        int r = (int)(e >> 8), k = (int)(e & 255);
        size_t off = sbf_off(r >> 7, 8, r & 127, k);
        __half2 h0, l0, h1, l1;
        split2h(v.x, v.y, h0, l0);
        split2h(v.z, v.w, h1, l1);
        *reinterpret_cast<uint2*>(g_xs + off)        = make_uint2(b2u(h0), b2u(h1));
        *reinterpret_cast<uint2*>(g_xs + (off ^ 64)) = make_uint2(b2u(l0), b2u(l1));
    } else {
        int row = (bid - 4096) * 8 + (tid >> 5);
        int lane = tid & 31;
        float p = 0.0f;
#pragma unroll
        for (int e = 0; e < 8; ++e)
            p += src[(long)row * 256 + lane + e * 32] * g_beta[lane + e * 32];
#pragma unroll
        for (int o = 16; o; o >>= 1) p += __shfl_xor_sync(0xffffffffu, p, o);
        if (!lane) g_w[row] = p;
    }
}

// ---------------------------------------------------------------------------
// Stage 1: proj (fp16 3-term). grid (2, 128, 2): sel0 qm = x.Mt^T, sel1 v.
// ---------------------------------------------------------------------------
__global__ void __launch_bounds__(NTHREADS, 2)
proj_kernel(const float* __restrict__ bv)
{
    extern __shared__ char smem[];
    int n0 = blockIdx.x * 128; long m0 = (long)blockIdx.y * 128; int sel = blockIdx.z;
    const char* B = (sel == 0)
        ? g_mts + (size_t)(n0 >> 7) * 8 * SLAB_F
        : g_wvs + (size_t)(n0 >> 7) * 8 * SLAB_F;
    float acc[4][4][4] = {};
    gemm_bulk<8, 1>(g_xs + (m0 >> 7) * 8 * SLAB_F, B, smem, acc);
    if (sel == 0) {
        epi_split_h(acc, g_qms, m0, n0, 8, g_zero + n0);
    } else {
        int b = (int)(m0 >> 10), tok0 = (int)(m0 & 1023);
        epi_split_t_b(acc, g_vts, (long)b * 256 + n0, tok0, 32, bv + n0);
    }
}

// ---------------------------------------------------------------------------
// Stage 2: attn_un = exp(qm x^T + w_j), fp16 3-term. grid (8, 8, 16)
// ---------------------------------------------------------------------------
__global__ void __launch_bounds__(NTHREADS, 2) scores_kernel()
{
    extern __shared__ char smem[];
    int n0 = blockIdx.x * 128, m0 = blockIdx.y * 128, b = blockIdx.z;
    float acc[4][4][4] = {};
    gemm_bulk<8, 1>(g_qms + (size_t)((b * NTOK + m0) >> 7) * 8 * SLAB_F,
                    g_xs  + (size_t)((b * NTOK + n0) >> 7) * 8 * SLAB_F,
                    smem, acc);
    epi_attn(acc, smem, g_attns, (long)b * NTOK + m0, n0,
             g_w + (long)b * NTOK + n0,
             g_zp + ((long)b * 8 + blockIdx.x) * NTOK + m0);
}

// ---------------------------------------------------------------------------
// Stage 3: o^T = (attn_un @ v)^T / Z, bf16 3-term. grid (2, 8, 16)
// ---------------------------------------------------------------------------
__global__ void __launch_bounds__(NTHREADS, 2) av_kernel()
{
    extern __shared__ char smem[];
    int c0 = blockIdx.x * 128, tok0 = blockIdx.y * 128, b = blockIdx.z;
    float acc[4][4][4] = {};
    gemm_bulk<32, 0>(g_attns + (size_t)(b * 8 + (tok0 >> 7)) * 32 * SLAB_F,
                     g_vts   + (size_t)(b * 2 + (c0 >> 7))   * 32 * SLAB_F,
                     smem, acc);
    __syncthreads();
    float* rzs = reinterpret_cast<float*>(smem);
    if (threadIdx.x < 128) {
        float z = 0.0f;
#pragma unroll
        for (int t = 0; t < 8; ++t)
            z += g_zp[((long)b * 8 + t) * NTOK + tok0 + threadIdx.x];
        rzs[threadIdx.x] = 1.0f / z;
    }
    __syncthreads();
    epi_ot(acc, g_ots, (long)b * 256 + c0, tok0, 32, rzs);
}

// ---------------------------------------------------------------------------
// Stage 4: z = Wp^T o, fp16 1-term. grid (2, 8, 16)
// ---------------------------------------------------------------------------
__global__ void __launch_bounds__(NTHREADS, 2) final_kernel(float* __restrict__ z)
{
    extern __shared__ char smem[];
    int c0 = blockIdx.x * 128, p0 = blockIdx.y * 128, b = blockIdx.z;
    float acc[4][4][4] = {};
    gemm_bulk<32, 3>(g_wpts + (size_t)(p0 >> 7) * 32 * SLAB_H,
                     g_ots  + (size_t)(b * 2 + (c0 >> 7)) * 32 * SLAB_H,
                     smem, acc);
    epi_f32(acc, z + ((long)b * NTOK + p0) * CDIM + c0, CDIM);
}

// ---------------------------------------------------------------------------
extern "C" void kernel_launch(void* const* d_in, const int* in_sizes, int n_in,
                              void* d_out, int out_size)
{
    const float* x  = (const float*)d_in[0];
    const float* Wq = (const float*)d_in[1];
    const float* bq = (const float*)d_in[2];
    const float* Wk = (const float*)d_in[3];
    const float* Wv = (const float*)d_in[5];
    const float* bv = (const float*)d_in[6];
    const float* Wp = (const float*)d_in[7];
    float* out = (float*)d_out;

    cudaFuncSetAttribute(proj_kernel,   cudaFuncAttributeMaxDynamicSharedMemorySize, SMEM_3T);
    cudaFuncSetAttribute(scores_kernel, cudaFuncAttributeMaxDynamicSharedMemorySize, SMEM_3T);
    cudaFuncSetAttribute(av_kernel,     cudaFuncAttributeMaxDynamicSharedMemorySize, SMEM_3T);
    cudaFuncSetAttribute(final_kernel,  cudaFuncAttributeMaxDynamicSharedMemorySize, SMEM_1T);

    prep_kernel <<<dim3(1105), NTHREADS>>>(Wq, Wk, Wv, Wp, bq);            // 1
    xconv_kernel<<<dim3(6144), NTHREADS>>>(x);                             // 2
    proj_kernel  <<<dim3(2, 128, 2), NTHREADS, SMEM_3T>>>(bv);             // 3
    scores_kernel<<<dim3(8, 8, 16),  NTHREADS, SMEM_3T>>>();               // 4 <- profiled
    av_kernel    <<<dim3(2, 8, 16),  NTHREADS, SMEM_3T>>>();               // 5
    final_kernel <<<dim3(2, 8, 16),  NTHREADS, SMEM_1T>>>(out);            // 6
}

// round 12
// speedup vs baseline: 3.4682x; 1.0708x over previous
#include <cuda_runtime.h>
#include <cuda_bf16.h>
#include <cuda_fp16.h>
#include <cstdint>

#define BATCH 16
#define NTOK  1024
#define CDIM  256
#define NTHREADS 256
#define NSTAGE 3
#define SLAB_F 16384                    // split slab: 128 rows x 128B
#define SLAB_H 8192                     // single-fp16 slab: 128 rows x 64B
#define SMEM_3T (NSTAGE*2*SLAB_F + 4096)   // mainloop 96KB + zsm/mbar
#define SMEM_1T (NSTAGE*2*SLAB_H + 1024)

// ---------------------------------------------------------------------------
// Split tiled format: rows in tiles of 128; tile t, k-slab s (32 k) is a
// contiguous 16KB smem image: row r at r*128, 16B chunk cc at (cc^(r&7))*16;
// chunks 0-3 hi, 4-7 lo (addr = hi ^ 64). fp16 pairs or bf16 pairs.
// Single-fp16 format: 8KB slabs, row r at r*64, chunk cc at (cc^((r>>1)&3))*16.
// ---------------------------------------------------------------------------
__device__ __align__(128) char g_xs  [16384*1024];      // x    fp16 split
__device__ __align__(128) char g_wvs [256*1024];        // Wv   fp16 split
__device__ __align__(128) char g_mts [256*1024];        // Mt = (Wq^T Wk)^T [e][c], fp16 split
__device__ __align__(128) char g_qms [16384*1024];      // qm = x·M, fp16 split
__device__ __align__(128) char g_vts [16*256*4096];     // v^T  bf16 split
__device__ __align__(128) char g_ots [16*256*2048];     // o^T  fp16 single
__device__ __align__(128) char g_attns[(size_t)16384*4096]; // exp(scores) bf16 split
__device__ __align__(128) char g_wpts[1024*2048];       // Wp^T fp16 single
__device__ float g_zp[BATCH*8*NTOK];
__device__ float g_w[BATCH*NTOK];                       // w_j = x_j . (Wk^T bq)
__device__ float g_beta[256];
__device__ float g_zero[256];

// ---------------------------------------------------------------------------
__device__ __forceinline__ uint32_t smem_u32(const void* p){
    uint32_t a;
    asm("{ .reg .u64 t; cvta.to.shared.u64 t, %1; cvt.u32.u64 %0, t; }" : "=r"(a) : "l"(p));
    return a;
}
__device__ __forceinline__ void ldsm4(uint32_t* r, uint32_t addr){
    asm volatile("ldmatrix.sync.aligned.m8n8.x4.shared.b16 {%0,%1,%2,%3}, [%4];"
        : "=r"(r[0]), "=r"(r[1]), "=r"(r[2]), "=r"(r[3]) : "r"(addr));
}
__device__ __forceinline__ void mma_bf16(float* d, const uint32_t* a, const uint32_t* b){
    asm volatile("mma.sync.aligned.m16n8k16.row.col.f32.bf16.bf16.f32 "
        "{%0,%1,%2,%3}, {%4,%5,%6,%7}, {%8,%9}, {%0,%1,%2,%3};"
        : "+f"(d[0]), "+f"(d[1]), "+f"(d[2]), "+f"(d[3])
        : "r"(a[0]), "r"(a[1]), "r"(a[2]), "r"(a[3]), "r"(b[0]), "r"(b[1]));
}
__device__ __forceinline__ void mma_f16(float* d, const uint32_t* a, const uint32_t* b){
    asm volatile("mma.sync.aligned.m16n8k16.row.col.f32.f16.f16.f32 "
        "{%0,%1,%2,%3}, {%4,%5,%6,%7}, {%8,%9}, {%0,%1,%2,%3};"
        : "+f"(d[0]), "+f"(d[1]), "+f"(d[2]), "+f"(d[3])
        : "r"(a[0]), "r"(a[1]), "r"(a[2]), "r"(a[3]), "r"(b[0]), "r"(b[1]));
}
template<int MODE>
__device__ __forceinline__ void mma_any(float* d, const uint32_t* a, const uint32_t* b){
    if (MODE == 0) mma_bf16(d, a, b); else mma_f16(d, a, b);
}
__device__ __forceinline__ void split2b(float v0, float v1,
        __nv_bfloat162& h, __nv_bfloat162& l){
    h = __floats2bfloat162_rn(v0, v1);
    l = __floats2bfloat162_rn(v0 - __low2float(h), v1 - __high2float(h));
}
__device__ __forceinline__ void split2h(float v0, float v1, __half2& h, __half2& l){
    h = __floats2half2_rn(v0, v1);
    l = __floats2half2_rn(v0 - __half2float(__low2half(h)),
                          v1 - __half2float(__high2half(h)));
}
template<class T> __device__ __forceinline__ uint32_t b2u(T v){
    uint32_t u; memcpy(&u, &v, 4); return u;
}
template<class T> __device__ __forceinline__ uint16_t b2s(T v){
    uint16_t u; memcpy(&u, &v, 2); return u;
}

// global tiled-format offsets (for producers)
__device__ __forceinline__ size_t sbf_off(long tile, int nslab, int r, int k){
    int cc = (k & 31) >> 3;
    return ((size_t)(tile * nslab + (k >> 5)) << 14)
         + (size_t)(r * 128) + (size_t)(((cc ^ (r & 7)) << 4) + (k & 7) * 2);
}
__device__ __forceinline__ size_t h16_off(long tile, int nslab, int r, int k){
    int cc = (k & 31) >> 3;
    return ((size_t)(tile * nslab + (k >> 5)) << 13)
         + (size_t)(r * 64) + (size_t)(((cc ^ ((r >> 1) & 3)) << 4) + (k & 7) * 2);
}
// local (within 4-slab stage region) offsets
__device__ __forceinline__ int loc_f(int r, int k){   // split, k 0..127
    int cc = (k & 31) >> 3;
    return ((k >> 5) << 14) + r * 128 + ((cc ^ (r & 7)) << 4) + (k & 7) * 2;
}
__device__ __forceinline__ int loc_h(int r, int k){   // single fp16, k 0..127
    int cc = (k & 31) >> 3;
    return ((k >> 5) << 13) + r * 64 + ((cc ^ ((r >> 1) & 3)) << 4) + (k & 7) * 2;
}

#define MBAR_INIT(mb,c)  asm volatile("mbarrier.init.shared.b64 [%0], %1;" :: "r"(mb), "r"((uint32_t)(c)) : "memory")
#define MBAR_EXPECT(mb,n) asm volatile("mbarrier.arrive.expect_tx.shared.b64 _, [%0], %1;" :: "r"(mb), "r"((uint32_t)(n)) : "memory")
#define BULK_G2S(dst,src,n,mb) asm volatile("cp.async.bulk.shared::cta.global.mbarrier::complete_tx::bytes [%0], [%1], %2, [%3];" :: "r"(dst), "l"(src), "r"((uint32_t)(n)), "r"(mb) : "memory")
#define BULK_S2G(dst,src,n) asm volatile("cp.async.bulk.global.shared::cta.bulk_group [%0], [%1], %2;" :: "l"(dst), "r"(src), "r"((uint32_t)(n)) : "memory")
#define BULK_COMMIT() asm volatile("cp.async.bulk.commit_group;" ::: "memory")
#define BULK_WAIT0()  asm volatile("cp.async.bulk.wait_group 0;" ::: "memory")
#define FENCE_ASYNC() asm volatile("fence.proxy.async.shared::cta;" ::: "memory")

#define MBAR_WAIT(mb, par) do { \
    uint32_t _m = (uint32_t)(mb), _p = (uint32_t)(par), _d; \
    asm volatile("{\n\t.reg .pred p;\n\t" \
        "mbarrier.try_wait.parity.acquire.cta.shared::cta.b64 p, [%1], %2;\n\t" \
        "selp.b32 %0, 1, 0, p;\n\t}" : "=r"(_d) : "r"(_m), "r"(_p) : "memory"); \
    if (!_d) { \
        asm volatile("{\n\t.reg .pred P1;\n\t" \
            "WL_%=:\n\t" \
            "mbarrier.try_wait.parity.acquire.cta.shared::cta.b64 P1, [%0], %1, 0x989680;\n\t" \
            "@P1 bra.uni WD_%=;\n\t" \
            "bra.uni WL_%=;\n\t" \
            "WD_%=:\n\t}" :: "r"(_m), "r"(_p) : "memory"); \
    } \
} while(0)

// ---------------------------------------------------------------------------
// 3-term compute (split A, split B). CTA 128x128, warps 2(M)x4(N).
// ---------------------------------------------------------------------------
template<int MODE>
__device__ __forceinline__ void compute_slab3(char* buf, float acc[4][4][4])
{
    int tid = threadIdx.x, lane = tid & 31, wid = tid >> 5;
    uint32_t sA = smem_u32(buf), sB = sA + SLAB_F;
    int mw = (wid & 1) * 64, nw = (wid >> 1) * 32;
    int arow = lane & 15, ahalf = lane >> 4;
    int brow = (lane & 7) + ((lane >> 4) & 1) * 8, bhalf = (lane >> 3) & 1;

#pragma unroll
    for (int ks = 0; ks < 2; ++ks) {
        uint32_t bh[8], bl[8];
#pragma unroll
        for (int nj = 0; nj < 2; ++nj) {
            int r = nw + nj * 16 + brow;
            int c = ks * 2 + bhalf;
            ldsm4(bh + nj * 4, sB + r * 128 + (((c    ) ^ (r & 7)) << 4));
            ldsm4(bl + nj * 4, sB + r * 128 + (((c + 4) ^ (r & 7)) << 4));
        }
#pragma unroll
        for (int mi = 0; mi < 4; ++mi) {
            int r = mw + mi * 16 + arow;
            int c = ks * 2 + ahalf;
            uint32_t ah[4], al[4];
            ldsm4(ah, sA + r * 128 + (((c    ) ^ (r & 7)) << 4));
            ldsm4(al, sA + r * 128 + (((c + 4) ^ (r & 7)) << 4));
#pragma unroll
            for (int j = 0; j < 4; ++j) {
                const uint32_t* bhf = &bh[(j >> 1) * 4 + (j & 1) * 2];
                const uint32_t* blf = &bl[(j >> 1) * 4 + (j & 1) * 2];
                float* d = acc[mi][j];
                mma_any<MODE>(d, ah, bhf);
                mma_any<MODE>(d, al, bhf);
                mma_any<MODE>(d, ah, blf);
            }
        }
    }
}

// ---------------------------------------------------------------------------
// 1-term fp16 compute (single A, single B; 64B rows).
// ---------------------------------------------------------------------------
__device__ __forceinline__ void compute_slab1(char* buf, float acc[4][4][4])
{
    int tid = threadIdx.x, lane = tid & 31, wid = tid >> 5;
    uint32_t sA = smem_u32(buf), sB = sA + SLAB_H;
    int mw = (wid & 1) * 64, nw = (wid >> 1) * 32;
    int arow = lane & 15, ahalf = lane >> 4;
    int brow = (lane & 7) + ((lane >> 4) & 1) * 8, bhalf = (lane >> 3) & 1;

#pragma unroll
    for (int ks = 0; ks < 2; ++ks) {
        uint32_t bh[8];
#pragma unroll
        for (int nj = 0; nj < 2; ++nj) {
            int r = nw + nj * 16 + brow;
            int c = ks * 2 + bhalf;
            ldsm4(bh + nj * 4, sB + r * 64 + ((c ^ ((r >> 1) & 3)) << 4));
        }
#pragma unroll
        for (int mi = 0; mi < 4; ++mi) {
            int r = mw + mi * 16 + arow;
            int c = ks * 2 + ahalf;
            uint32_t ah[4];
            ldsm4(ah, sA + r * 64 + ((c ^ ((r >> 1) & 3)) << 4));
#pragma unroll
            for (int j = 0; j < 4; ++j)
                mma_f16(acc[mi][j], ah, &bh[(j >> 1) * 4 + (j & 1) * 2]);
        }
    }
}

// ---------------------------------------------------------------------------
// Bulk-copy mainloop. MODE: 0 bf16 3-term, 1 fp16 3-term, 3 fp16 1-term.
// ---------------------------------------------------------------------------
template<int NC, int MODE>
__device__ __forceinline__ void gemm_bulk(const char* __restrict__ A,
                                          const char* __restrict__ B,
                                          char* smem, float acc[4][4][4])
{
    constexpr int SL  = (MODE == 3) ? SLAB_H : SLAB_F;
    constexpr int STG = 2 * SL;
    uint32_t mb = smem_u32(smem + NSTAGE * STG);
    int tid = threadIdx.x;
    if (tid == 0) {
        MBAR_INIT(mb, 1); MBAR_INIT(mb + 8, 1); MBAR_INIT(mb + 16, 1);
        FENCE_ASYNC();
    }
    __syncthreads();
    if (tid == 0) {
#pragma unroll
        for (int s = 0; s < NSTAGE - 1; ++s) {
            uint32_t m = mb + 8 * s;
            uint32_t d = smem_u32(smem + s * STG);
            MBAR_EXPECT(m, STG);
            BULK_G2S(d,      A + (size_t)s * SL, SL, m);
            BULK_G2S(d + SL, B + (size_t)s * SL, SL, m);
        }
    }
#pragma unroll 4
    for (int c = 0; c < NC; ++c) {
        int s = c % NSTAGE;
        MBAR_WAIT(mb + 8 * s, (c / NSTAGE) & 1);
        __syncthreads();
        int nc = c + NSTAGE - 1;
        if (tid == 0 && nc < NC) {
            int sn = nc % NSTAGE;
            uint32_t m = mb + 8 * sn;
            uint32_t d = smem_u32(smem + sn * STG);
            MBAR_EXPECT(m, STG);
            BULK_G2S(d,      A + (size_t)nc * SL, SL, m);
            BULK_G2S(d + SL, B + (size_t)nc * SL, SL, m);
        }
        if (MODE == 3) compute_slab1(smem + s * STG, acc);
        else           compute_slab3<MODE>(smem + s * STG, acc);
    }
}

// drain a staged region to global
__device__ __forceinline__ void stage_drain(char* smem, char* dst, int bytes)
{
    __syncthreads();
    if (threadIdx.x == 0) {
        FENCE_ASYNC();
#pragma unroll
        for (int sl = 0; sl < 4; ++sl)
            BULK_S2G(dst + sl * (bytes >> 2), smem_u32(smem + sl * (bytes >> 2)), bytes >> 2);
        BULK_COMMIT();
        BULK_WAIT0();
    }
}

// ---------------------------------------------------------------------------
// Epilogues. Frag: d0,d1 -> (row=lane>>2, col=(lane&3)*2+e), d2,d3 row+8.
// All staged epilogues: write smem image of the CTA's contiguous 4-slab
// output region, then bulk S2G.
// ---------------------------------------------------------------------------
__device__ __forceinline__ void epi_f32(const float acc[4][4][4],
        float* __restrict__ Cg, int ldc)
{
    int tid = threadIdx.x, lane = tid & 31, wid = tid >> 5;
    int row0 = (wid & 1) * 64 + (lane >> 2), col0 = (wid >> 1) * 32 + (lane & 3) * 2;
#pragma unroll
    for (int mi = 0; mi < 4; ++mi)
#pragma unroll
        for (int j = 0; j < 4; ++j) {
            int c = col0 + j * 8;
#pragma unroll
            for (int h = 0; h < 2; ++h) {
                int r = row0 + mi * 16 + h * 8;
                *reinterpret_cast<float2*>(Cg + (long)r * ldc + c) =
                    make_float2(acc[mi][j][h * 2], acc[mi][j][h * 2 + 1]);
            }
        }
}

// qm: fp16 split, normal orientation. dst = 64KB region base.
__device__ __forceinline__ void epi_split_h(const float acc[4][4][4],
        char* smem, char* dst, const float* __restrict__ bias)
{
    int tid = threadIdx.x, lane = tid & 31, wid = tid >> 5;
    int rw0 = (wid & 1) * 64 + (lane >> 2), cw0 = (wid >> 1) * 32 + (lane & 3) * 2;
    __syncthreads();
#pragma unroll
    for (int mi = 0; mi < 4; ++mi)
#pragma unroll
        for (int j = 0; j < 4; ++j) {
            int c = cw0 + j * 8;
            float b0 = bias[c], b1 = bias[c + 1];
#pragma unroll
            for (int h = 0; h < 2; ++h) {
                int r = rw0 + mi * 16 + h * 8;
                __half2 hh, ll;
                split2h(acc[mi][j][h * 2] + b0, acc[mi][j][h * 2 + 1] + b1, hh, ll);
                int off = loc_f(r, c);
                *reinterpret_cast<uint32_t*>(smem + off)        = b2u(hh);
                *reinterpret_cast<uint32_t*>(smem + (off ^ 64)) = b2u(ll);
            }
        }
    stage_drain(smem, dst, 4 * SLAB_F);
}

// v^T: bf16 split transposed. dst = 64KB region base (rows = c, k = tok).
__device__ __forceinline__ void epi_split_t_b(const float acc[4][4][4],
        char* smem, char* dst, const float* __restrict__ bias)
{
    int tid = threadIdx.x, lane = tid & 31, wid = tid >> 5;
    int rw0 = (wid & 1) * 64 + (lane >> 2), cw0 = (wid >> 1) * 32 + (lane & 3) * 2;
    __syncthreads();
#pragma unroll
    for (int mi = 0; mi < 4; ++mi)
#pragma unroll
        for (int j = 0; j < 4; ++j)
#pragma unroll
            for (int h = 0; h < 2; ++h) {
                int m = rw0 + mi * 16 + h * 8;
#pragma unroll
                for (int e = 0; e < 2; ++e) {
                    int n = cw0 + j * 8 + e;
                    float v = acc[mi][j][h * 2 + e] + bias[n];
                    __nv_bfloat16 hb = __float2bfloat16(v);
                    __nv_bfloat16 lb = __float2bfloat16(v - __bfloat162float(hb));
                    int off = loc_f(n, m);
                    *reinterpret_cast<uint16_t*>(smem + off)        = b2s(hb);
                    *reinterpret_cast<uint16_t*>(smem + (off ^ 64)) = b2s(lb);
                }
            }
    stage_drain(smem, dst, 4 * SLAB_F);
}

// o^T: single fp16 transposed with per-m scale. dst = 32KB region base.
__device__ __forceinline__ void epi_ot(const float acc[4][4][4],
        char* smem, char* dst, const float* __restrict__ rz)
{
    int tid = threadIdx.x, lane = tid & 31, wid = tid >> 5;
    int rw0 = (wid & 1) * 64 + (lane >> 2), cw0 = (wid >> 1) * 32 + (lane & 3) * 2;
#pragma unroll
    for (int mi = 0; mi < 4; ++mi)
#pragma unroll
        for (int j = 0; j < 4; ++j)
#pragma unroll
            for (int h = 0; h < 2; ++h) {
                int m = rw0 + mi * 16 + h * 8;
                float sc = rz[m];
#pragma unroll
                for (int e = 0; e < 2; ++e) {
                    int n = cw0 + j * 8 + e;
                    __half v = __float2half(acc[mi][j][h * 2 + e] * sc);
                    *reinterpret_cast<uint16_t*>(smem + loc_h(n, m)) = b2s(v);
                }
            }
    stage_drain(smem, dst, 4 * SLAB_H);
}

// attn: exp(acc + w_col), bf16 split normal + per-row partial sums.
// smem: stage 64KB at base, zsm at +64KB. dst = 64KB region base.
__device__ __forceinline__ void epi_attn(const float acc[4][4][4], char* smem,
        char* dst, const float* __restrict__ wcol, float* __restrict__ zp_out)
{
    int tid = threadIdx.x, lane = tid & 31, wid = tid >> 5;
    int rw0 = (wid & 1) * 64 + (lane >> 2), cw0 = (wid >> 1) * 32 + (lane & 3) * 2;
    float* zsm = reinterpret_cast<float*>(smem + 4 * SLAB_F);
    __syncthreads();

    float wc[8];
#pragma unroll
    for (int j = 0; j < 4; ++j) {
        wc[j * 2]     = wcol[cw0 + j * 8];
        wc[j * 2 + 1] = wcol[cw0 + j * 8 + 1];
    }

#pragma unroll
    for (int mi = 0; mi < 4; ++mi) {
#pragma unroll
        for (int h = 0; h < 2; ++h) {
            int r = rw0 + mi * 16 + h * 8;
            float rs = 0.0f;
#pragma unroll
            for (int j = 0; j < 4; ++j) {
                int c = cw0 + j * 8;
                float e0 = __expf(acc[mi][j][h * 2]     + wc[j * 2]);
                float e1 = __expf(acc[mi][j][h * 2 + 1] + wc[j * 2 + 1]);
                rs += e0 + e1;
                __nv_bfloat162 hh, ll;
                split2b(e0, e1, hh, ll);
                int off = loc_f(r, c);
                *reinterpret_cast<uint32_t*>(smem + off)        = b2u(hh);
                *reinterpret_cast<uint32_t*>(smem + (off ^ 64)) = b2u(ll);
            }
            rs += __shfl_xor_sync(0xffffffffu, rs, 1);
            rs += __shfl_xor_sync(0xffffffffu, rs, 2);
            if ((lane & 3) == 0)
                zsm[(wid >> 1) * 128 + r] = rs;
        }
    }
    __syncthreads();
    if (tid < 128)
        zp_out[tid] = zsm[tid] + zsm[128 + tid] + zsm[256 + tid] + zsm[384 + tid];
    if (tid == 0) {
        FENCE_ASYNC();
#pragma unroll
        for (int sl = 0; sl < 4; ++sl)
            BULK_S2G(dst + sl * SLAB_F, smem_u32(smem + sl * SLAB_F), SLAB_F);
        BULK_COMMIT();
        BULK_WAIT0();
    }
}

// ---------------------------------------------------------------------------
// Prep: Wv conv (0..63) | Wp^T single fp16 (64..1087) | Mt tiles (1088..1103)
//       | beta (1104)
// ---------------------------------------------------------------------------
__global__ void __launch_bounds__(NTHREADS) prep_kernel(
        const float* __restrict__ Wq, const float* __restrict__ Wk,
        const float* __restrict__ Wv, const float* __restrict__ Wp,
        const float* __restrict__ bq)
{
    int bid = blockIdx.x, tid = threadIdx.x;
    if (bid < 64) {
        long i = (long)bid * NTHREADS + tid;
        float4 v = reinterpret_cast<const float4*>(Wv)[i];
        long e = i * 4;
        int r = (int)(e >> 8), k = (int)(e & 255);
        size_t off = sbf_off(r >> 7, 8, r & 127, k);
        __half2 h0, l0, h1, l1;
        split2h(v.x, v.y, h0, l0);
        split2h(v.z, v.w, h1, l1);
        *reinterpret_cast<uint2*>(g_wvs + off)        = make_uint2(b2u(h0), b2u(h1));
        *reinterpret_cast<uint2*>(g_wvs + (off ^ 64)) = make_uint2(b2u(l0), b2u(l1));
    } else if (bid < 1088) {
        __shared__ float t[32][33];
        int b2 = bid - 64;
        int h = b2 >> 5, n0 = (b2 & 31) * 32;
        int tx = tid & 31, ty = tid >> 5;
        const float* src = Wp + (long)h * 32768 + (long)n0 * 32;
#pragma unroll
        for (int i = 0; i < 4; ++i) t[ty + i * 8][tx] = src[(ty + i * 8) * 32 + tx];
        __syncthreads();
#pragma unroll
        for (int i = 0; i < 4; ++i) {
            int w = ty + i * 8;
            int p = h * 32 + w, n = n0 + tx;
            __half hb = __float2half(t[tx][w]);
            *reinterpret_cast<uint16_t*>(g_wpts + h16_off(p >> 7, 32, p & 127, n)) = b2s(hb);
        }
    } else if (bid < 1104) {
        __shared__ float As[32][64], Bs[32][64];
        int mt = bid - 1088;
        int e0 = (mt >> 2) * 64, c0 = (mt & 3) * 64;
        int tx = tid & 15, ty = tid >> 4;
        float acc[4][4] = {};
        for (int k0 = 0; k0 < 256; k0 += 32) {
            for (int i = tid; i < 2048; i += NTHREADS) {
                int dd = i >> 6, ee = i & 63;
                As[dd][ee] = Wk[(long)(k0 + dd) * 256 + e0 + ee];
                Bs[dd][ee] = Wq[(long)(k0 + dd) * 256 + c0 + ee];
            }
            __syncthreads();
#pragma unroll 8
            for (int dd = 0; dd < 32; ++dd) {
                float a[4], b[4];
#pragma unroll
                for (int i = 0; i < 4; ++i) { a[i] = As[dd][ty * 4 + i]; b[i] = Bs[dd][tx * 4 + i]; }
#pragma unroll
                for (int i = 0; i < 4; ++i)
#pragma unroll
                    for (int j = 0; j < 4; ++j) acc[i][j] += a[i] * b[j];
            }
            __syncthreads();
        }
#pragma unroll
        for (int i = 0; i < 4; ++i)
#pragma unroll
            for (int j = 0; j < 4; ++j) {
                int e = e0 + ty * 4 + i, c = c0 + tx * 4 + j;
                __half hb = __float2half(acc[i][j]);
                __half lb = __float2half(acc[i][j] - __half2float(hb));
                size_t off = sbf_off(e >> 7, 8, e & 127, c);
                *reinterpret_cast<uint16_t*>(g_mts + off)        = b2s(hb);
                *reinterpret_cast<uint16_t*>(g_mts + (off ^ 64)) = b2s(lb);
            }
    } else {
        int c = tid;
        float acc = 0.0f;
        for (int d = 0; d < 256; ++d) acc += Wk[(long)d * 256 + c] * bq[d];
        g_beta[c] = acc;
    }
}

// x conv (0..4095) + w vector (4096..6143)
__global__ void __launch_bounds__(NTHREADS) xconv_kernel(const float* __restrict__ src)
{
    int bid = blockIdx.x, tid = threadIdx.x;
    if (bid < 4096) {
        long i = (long)bid * NTHREADS + tid;
        float4 v = reinterpret_cast<const float4*>(src)[i];
        long e = i * 4;
        int r = (int)(e >> 8), k = (int)(e & 255);
        size_t off = sbf_off(r >> 7, 8, r & 127, k);
        __half2 h0, l0, h1, l1;
        split2h(v.x, v.y, h0, l0);
        split2h(v.z, v.w, h1, l1);
        *reinterpret_cast<uint2*>(g_xs + off)        = make_uint2(b2u(h0), b2u(h1));
        *reinterpret_cast<uint2*>(g_xs + (off ^ 64)) = make_uint2(b2u(l0), b2u(l1));
    } else {
        int row = (bid - 4096) * 8 + (tid >> 5);
        int lane = tid & 31;
        float p = 0.0f;
#pragma unroll
        for (int e = 0; e < 8; ++e)
            p += src[(long)row * 256 + lane + e * 32] * g_beta[lane + e * 32];
#pragma unroll
        for (int o = 16; o; o >>= 1) p += __shfl_xor_sync(0xffffffffu, p, o);
        if (!lane) g_w[row] = p;
    }
}

// ---------------------------------------------------------------------------
// Stage 1: proj (fp16 3-term). grid (2, 128, 2): sel0 qm, sel1 v.
// ---------------------------------------------------------------------------
__global__ void __launch_bounds__(NTHREADS, 2)
proj_kernel(const float* __restrict__ bv)
{
    extern __shared__ char smem[];
    int n0 = blockIdx.x * 128; long m0 = (long)blockIdx.y * 128; int sel = blockIdx.z;
    const char* B = (sel == 0)
        ? g_mts + (size_t)(n0 >> 7) * 8 * SLAB_F
        : g_wvs + (size_t)(n0 >> 7) * 8 * SLAB_F;
    float acc[4][4][4] = {};
    gemm_bulk<8, 1>(g_xs + (m0 >> 7) * 8 * SLAB_F, B, smem, acc);
    if (sel == 0) {
        char* dst = g_qms + ((size_t)(m0 >> 7) * 8 + (n0 >> 5)) * SLAB_F;
        epi_split_h(acc, smem, dst, g_zero + n0);
    } else {
        int b = (int)(m0 >> 10), tok0 = (int)(m0 & 1023);
        char* dst = g_vts + ((size_t)(b * 2 + (n0 >> 7)) * 32 + (tok0 >> 5)) * SLAB_F;
        epi_split_t_b(acc, smem, dst, bv + n0);
    }
}

// ---------------------------------------------------------------------------
// Stage 2: attn_un = exp(qm x^T + w_j), fp16 3-term. grid (8, 8, 16)
// ---------------------------------------------------------------------------
__global__ void __launch_bounds__(NTHREADS, 2) scores_kernel()
{
    extern __shared__ char smem[];
    int n0 = blockIdx.x * 128, m0 = blockIdx.y * 128, b = blockIdx.z;
    float acc[4][4][4] = {};
    gemm_bulk<8, 1>(g_qms + (size_t)((b * NTOK + m0) >> 7) * 8 * SLAB_F,
                    g_xs  + (size_t)((b * NTOK + n0) >> 7) * 8 * SLAB_F,
                    smem, acc);
    char* dst = g_attns + ((size_t)((b * NTOK + m0) >> 7) * 32 + (n0 >> 5)) * SLAB_F;
    epi_attn(acc, smem, dst, g_w + (long)b * NTOK + n0,
             g_zp + ((long)b * 8 + blockIdx.x) * NTOK + m0);
}

// ---------------------------------------------------------------------------
// Stage 3: o^T = (attn_un @ v)^T / Z, bf16 3-term. grid (2, 8, 16)
// ---------------------------------------------------------------------------
__global__ void __launch_bounds__(NTHREADS, 2) av_kernel()
{
    extern __shared__ char smem[];
    int c0 = blockIdx.x * 128, tok0 = blockIdx.y * 128, b = blockIdx.z;
    float acc[4][4][4] = {};
    gemm_bulk<32, 0>(g_attns + (size_t)(b * 8 + (tok0 >> 7)) * 32 * SLAB_F,
                     g_vts   + (size_t)(b * 2 + (c0 >> 7))   * 32 * SLAB_F,
                     smem, acc);
    __syncthreads();
    float* rzs = reinterpret_cast<float*>(smem + 4 * SLAB_H);   // above 32KB stage
    if (threadIdx.x < 128) {
        float z = 0.0f;
#pragma unroll
        for (int t = 0; t < 8; ++t)
            z += g_zp[((long)b * 8 + t) * NTOK + tok0 + threadIdx.x];
        rzs[threadIdx.x] = 1.0f / z;
    }
    __syncthreads();
    char* dst = g_ots + ((size_t)(b * 2 + (c0 >> 7)) * 32 + (tok0 >> 5)) * SLAB_H;
    epi_ot(acc, smem, dst, rzs);
}

// ---------------------------------------------------------------------------
// Stage 4: z = Wp^T o, fp16 1-term. grid (2, 8, 16)
// ---------------------------------------------------------------------------
__global__ void __launch_bounds__(NTHREADS, 2) final_kernel(float* __restrict__ z)
{
    extern __shared__ char smem[];
    int c0 = blockIdx.x * 128, p0 = blockIdx.y * 128, b = blockIdx.z;
    float acc[4][4][4] = {};
    gemm_bulk<32, 3>(g_wpts + (size_t)(p0 >> 7) * 32 * SLAB_H,
                     g_ots  + (size_t)(b * 2 + (c0 >> 7)) * 32 * SLAB_H,
                     smem, acc);
    epi_f32(acc, z + ((long)b * NTOK + p0) * CDIM + c0, CDIM);
}

// ---------------------------------------------------------------------------
extern "C" void kernel_launch(void* const* d_in, const int* in_sizes, int n_in,
                              void* d_out, int out_size)
{
    const float* x  = (const float*)d_in[0];
    const float* Wq = (const float*)d_in[1];
    const float* bq = (const float*)d_in[2];
    const float* Wk = (const float*)d_in[3];
    const float* Wv = (const float*)d_in[5];
    const float* bv = (const float*)d_in[6];
    const float* Wp = (const float*)d_in[7];
    float* out = (float*)d_out;

    cudaFuncSetAttribute(proj_kernel,   cudaFuncAttributeMaxDynamicSharedMemorySize, SMEM_3T);
    cudaFuncSetAttribute(scores_kernel, cudaFuncAttributeMaxDynamicSharedMemorySize, SMEM_3T);
    cudaFuncSetAttribute(av_kernel,     cudaFuncAttributeMaxDynamicSharedMemorySize, SMEM_3T);
    cudaFuncSetAttribute(final_kernel,  cudaFuncAttributeMaxDynamicSharedMemorySize, SMEM_1T);

    prep_kernel <<<dim3(1105), NTHREADS>>>(Wq, Wk, Wv, Wp, bq);            // 1
    xconv_kernel<<<dim3(6144), NTHREADS>>>(x);                             // 2
    proj_kernel  <<<dim3(2, 128, 2), NTHREADS, SMEM_3T>>>(bv);             // 3
    scores_kernel<<<dim3(8, 8, 16),  NTHREADS, SMEM_3T>>>();               // 4 <- profiled
    av_kernel    <<<dim3(2, 8, 16),  NTHREADS, SMEM_3T>>>();               // 5
    final_kernel <<<dim3(2, 8, 16),  NTHREADS, SMEM_1T>>>(out);            // 6
}

// round 13
// speedup vs baseline: 4.1129x; 1.1859x over previous
#include <cuda_runtime.h>
#include <cuda_bf16.h>
#include <cuda_fp16.h>
#include <cstdint>

#define BATCH 16
#define NTOK  1024
#define CDIM  256
#define NTHREADS 256
#define NSTAGE 3
#define SLAB_F 16384                    // split slab: 128 rows x 128B
#define SLAB_H 8192                     // single-fp16 slab: 128 rows x 64B
#define SMEM_3T (NSTAGE*2*SLAB_F + 4096)   // 100352: ring 96KB + zsm/mbar
#define SMEM_AV (NSTAGE*2*SLAB_H + 4096)   // 53248: ring 48KB + mbar + ss
#define SMEM_1T (NSTAGE*2*SLAB_H + 1024)

// ---------------------------------------------------------------------------
// Split tiled format: rows in tiles of 128; tile t, k-slab s (32 k) is a
// contiguous 16KB smem image: row r at r*128, chunk cc at (cc^(r&7))*16;
// chunks 0-3 hi, 4-7 lo (addr = hi ^ 64). fp16 pairs.
// Single-fp16 format: 8KB slabs, row r at r*64, chunk cc at (cc^((r>>1)&3))*16.
// ---------------------------------------------------------------------------
__device__ __align__(128) char g_xs  [16384*1024];      // x    fp16 split
__device__ __align__(128) char g_wvs [256*1024];        // Wv   fp16 split
__device__ __align__(128) char g_mts [256*1024];        // Mt = (Wq^T Wk)^T [e][c], fp16 split
__device__ __align__(128) char g_qms [16384*1024];      // qm = x·M, fp16 split
__device__ __align__(128) char g_vts [16*256*2048];     // v^T  fp16 single
__device__ __align__(128) char g_ots [16*256*2048];     // o^T  fp16 single
__device__ __align__(128) char g_attns[(size_t)16384*2048]; // attn_norm fp16 single
__device__ __align__(128) char g_wpts[1024*2048];       // Wp^T fp16 single
__device__ float g_zp[BATCH*8*NTOK];                    // per (b, n-tile, tok) exp sums
__device__ float g_w[BATCH*NTOK];                       // w_j = x_j . (Wk^T bq)
__device__ float g_beta[256];
__device__ float g_zero[256];

// ---------------------------------------------------------------------------
__device__ __forceinline__ uint32_t smem_u32(const void* p){
    uint32_t a;
    asm("{ .reg .u64 t; cvta.to.shared.u64 t, %1; cvt.u32.u64 %0, t; }" : "=r"(a) : "l"(p));
    return a;
}
__device__ __forceinline__ void ldsm4(uint32_t* r, uint32_t addr){
    asm volatile("ldmatrix.sync.aligned.m8n8.x4.shared.b16 {%0,%1,%2,%3}, [%4];"
        : "=r"(r[0]), "=r"(r[1]), "=r"(r[2]), "=r"(r[3]) : "r"(addr));
}
__device__ __forceinline__ void mma_f16(float* d, const uint32_t* a, const uint32_t* b){
    asm volatile("mma.sync.aligned.m16n8k16.row.col.f32.f16.f16.f32 "
        "{%0,%1,%2,%3}, {%4,%5,%6,%7}, {%8,%9}, {%0,%1,%2,%3};"
        : "+f"(d[0]), "+f"(d[1]), "+f"(d[2]), "+f"(d[3])
        : "r"(a[0]), "r"(a[1]), "r"(a[2]), "r"(a[3]), "r"(b[0]), "r"(b[1]));
}
__device__ __forceinline__ void split2h(float v0, float v1, __half2& h, __half2& l){
    h = __floats2half2_rn(v0, v1);
    l = __floats2half2_rn(v0 - __half2float(__low2half(h)),
                          v1 - __half2float(__high2half(h)));
}
template<class T> __device__ __forceinline__ uint32_t b2u(T v){
    uint32_t u; memcpy(&u, &v, 4); return u;
}
template<class T> __device__ __forceinline__ uint16_t b2s(T v){
    uint16_t u; memcpy(&u, &v, 2); return u;
}
__device__ __forceinline__ uint32_t h2mul(uint32_t a, uint32_t s){
    __half2 x, y; memcpy(&x, &a, 4); memcpy(&y, &s, 4);
    __half2 r = __hmul2(x, y); uint32_t u; memcpy(&u, &r, 4); return u;
}

// global tiled-format offsets (producers)
__device__ __forceinline__ size_t sbf_off(long tile, int nslab, int r, int k){
    int cc = (k & 31) >> 3;
    return ((size_t)(tile * nslab + (k >> 5)) << 14)
         + (size_t)(r * 128) + (size_t)(((cc ^ (r & 7)) << 4) + (k & 7) * 2);
}
__device__ __forceinline__ size_t h16_off(long tile, int nslab, int r, int k){
    int cc = (k & 31) >> 3;
    return ((size_t)(tile * nslab + (k >> 5)) << 13)
         + (size_t)(r * 64) + (size_t)(((cc ^ ((r >> 1) & 3)) << 4) + (k & 7) * 2);
}
// local (within stage region) offsets
__device__ __forceinline__ int loc_f(int r, int k){
    int cc = (k & 31) >> 3;
    return ((k >> 5) << 14) + r * 128 + ((cc ^ (r & 7)) << 4) + (k & 7) * 2;
}
__device__ __forceinline__ int loc_h(int r, int k){
    int cc = (k & 31) >> 3;
    return ((k >> 5) << 13) + r * 64 + ((cc ^ ((r >> 1) & 3)) << 4) + (k & 7) * 2;
}

#define MBAR_INIT(mb,c)  asm volatile("mbarrier.init.shared.b64 [%0], %1;" :: "r"(mb), "r"((uint32_t)(c)) : "memory")
#define MBAR_EXPECT(mb,n) asm volatile("mbarrier.arrive.expect_tx.shared.b64 _, [%0], %1;" :: "r"(mb), "r"((uint32_t)(n)) : "memory")
#define BULK_G2S(dst,src,n,mb) asm volatile("cp.async.bulk.shared::cta.global.mbarrier::complete_tx::bytes [%0], [%1], %2, [%3];" :: "r"(dst), "l"(src), "r"((uint32_t)(n)), "r"(mb) : "memory")
#define BULK_S2G(dst,src,n) asm volatile("cp.async.bulk.global.shared::cta.bulk_group [%0], [%1], %2;" :: "l"(dst), "r"(src), "r"((uint32_t)(n)) : "memory")
#define BULK_COMMIT() asm volatile("cp.async.bulk.commit_group;" ::: "memory")
#define BULK_WAIT0()  asm volatile("cp.async.bulk.wait_group 0;" ::: "memory")
#define FENCE_ASYNC() asm volatile("fence.proxy.async.shared::cta;" ::: "memory")

#define MBAR_WAIT(mb, par) do { \
    uint32_t _m = (uint32_t)(mb), _p = (uint32_t)(par), _d; \
    asm volatile("{\n\t.reg .pred p;\n\t" \
        "mbarrier.try_wait.parity.acquire.cta.shared::cta.b64 p, [%1], %2;\n\t" \
        "selp.b32 %0, 1, 0, p;\n\t}" : "=r"(_d) : "r"(_m), "r"(_p) : "memory"); \
    if (!_d) { \
        asm volatile("{\n\t.reg .pred P1;\n\t" \
            "WL_%=:\n\t" \
            "mbarrier.try_wait.parity.acquire.cta.shared::cta.b64 P1, [%0], %1, 0x989680;\n\t" \
            "@P1 bra.uni WD_%=;\n\t" \
            "bra.uni WL_%=;\n\t" \
            "WD_%=:\n\t}" :: "r"(_m), "r"(_p) : "memory"); \
    } \
} while(0)

// ---------------------------------------------------------------------------
// 3-term fp16 compute (split A, split B). CTA 128x128, warps 2(M)x4(N).
// ---------------------------------------------------------------------------
__device__ __forceinline__ void compute_slab3(char* buf, float acc[4][4][4])
{
    int tid = threadIdx.x, lane = tid & 31, wid = tid >> 5;
    uint32_t sA = smem_u32(buf), sB = sA + SLAB_F;
    int mw = (wid & 1) * 64, nw = (wid >> 1) * 32;
    int arow = lane & 15, ahalf = lane >> 4;
    int brow = (lane & 7) + ((lane >> 4) & 1) * 8, bhalf = (lane >> 3) & 1;

#pragma unroll
    for (int ks = 0; ks < 2; ++ks) {
        uint32_t bh[8], bl[8];
#pragma unroll
        for (int nj = 0; nj < 2; ++nj) {
            int r = nw + nj * 16 + brow;
            int c = ks * 2 + bhalf;
            ldsm4(bh + nj * 4, sB + r * 128 + (((c    ) ^ (r & 7)) << 4));
            ldsm4(bl + nj * 4, sB + r * 128 + (((c + 4) ^ (r & 7)) << 4));
        }
#pragma unroll
        for (int mi = 0; mi < 4; ++mi) {
            int r = mw + mi * 16 + arow;
            int c = ks * 2 + ahalf;
            uint32_t ah[4], al[4];
            ldsm4(ah, sA + r * 128 + (((c    ) ^ (r & 7)) << 4));
            ldsm4(al, sA + r * 128 + (((c + 4) ^ (r & 7)) << 4));
#pragma unroll
            for (int j = 0; j < 4; ++j) {
                const uint32_t* bhf = &bh[(j >> 1) * 4 + (j & 1) * 2];
                const uint32_t* blf = &bl[(j >> 1) * 4 + (j & 1) * 2];
                float* d = acc[mi][j];
                mma_f16(d, ah, bhf);
                mma_f16(d, al, bhf);
                mma_f16(d, ah, blf);
            }
        }
    }
}

// ---------------------------------------------------------------------------
// 1-term fp16 compute (single A, single B; 64B rows). Optional A-frag scale.
// ---------------------------------------------------------------------------
template<bool SCALE>
__device__ __forceinline__ void compute_slab1(char* buf, float acc[4][4][4],
        const __half* __restrict__ ss)
{
    int tid = threadIdx.x, lane = tid & 31, wid = tid >> 5;
    uint32_t sA = smem_u32(buf), sB = sA + SLAB_H;
    int mw = (wid & 1) * 64, nw = (wid >> 1) * 32;
    int arow = lane & 15, ahalf = lane >> 4;
    int brow = (lane & 7) + ((lane >> 4) & 1) * 8, bhalf = (lane >> 3) & 1;
    int r0 = lane >> 2;

    uint32_t sv0[4], sv1[4];
    if (SCALE) {
#pragma unroll
        for (int mi = 0; mi < 4; ++mi) {
            int rr = mw + mi * 16 + r0;
            sv0[mi] = b2u(__half2half2(ss[rr]));
            sv1[mi] = b2u(__half2half2(ss[rr + 8]));
        }
    }

#pragma unroll
    for (int ks = 0; ks < 2; ++ks) {
        uint32_t bh[8];
#pragma unroll
        for (int nj = 0; nj < 2; ++nj) {
            int r = nw + nj * 16 + brow;
            int c = ks * 2 + bhalf;
            ldsm4(bh + nj * 4, sB + r * 64 + ((c ^ ((r >> 1) & 3)) << 4));
        }
#pragma unroll
        for (int mi = 0; mi < 4; ++mi) {
            int r = mw + mi * 16 + arow;
            int c = ks * 2 + ahalf;
            uint32_t ah[4];
            ldsm4(ah, sA + r * 64 + ((c ^ ((r >> 1) & 3)) << 4));
            if (SCALE) {
                ah[0] = h2mul(ah[0], sv0[mi]);
                ah[2] = h2mul(ah[2], sv0[mi]);
                ah[1] = h2mul(ah[1], sv1[mi]);
                ah[3] = h2mul(ah[3], sv1[mi]);
            }
#pragma unroll
            for (int j = 0; j < 4; ++j)
                mma_f16(acc[mi][j], ah, &bh[(j >> 1) * 4 + (j & 1) * 2]);
        }
    }
}

// ---------------------------------------------------------------------------
// Bulk-copy mainloops.
// ---------------------------------------------------------------------------
template<int NC, int MODE>   // MODE 1: fp16 3-term split; MODE 3: fp16 1-term
__device__ __forceinline__ void gemm_bulk(const char* __restrict__ A,
                                          const char* __restrict__ B,
                                          char* smem, float acc[4][4][4],
                                          const __half* __restrict__ ss = nullptr)
{
    constexpr int SL  = (MODE == 3) ? SLAB_H : SLAB_F;
    constexpr int STG = 2 * SL;
    uint32_t mb = smem_u32(smem + NSTAGE * STG);
    int tid = threadIdx.x;
    if (tid == 0) {
        MBAR_INIT(mb, 1); MBAR_INIT(mb + 8, 1); MBAR_INIT(mb + 16, 1);
        FENCE_ASYNC();
    }
    __syncthreads();
    if (tid == 0) {
#pragma unroll
        for (int s = 0; s < NSTAGE - 1; ++s) {
            uint32_t m = mb + 8 * s;
            uint32_t d = smem_u32(smem + s * STG);
            MBAR_EXPECT(m, STG);
            BULK_G2S(d,      A + (size_t)s * SL, SL, m);
            BULK_G2S(d + SL, B + (size_t)s * SL, SL, m);
        }
    }
#pragma unroll 4
    for (int c = 0; c < NC; ++c) {
        int s = c % NSTAGE;
        MBAR_WAIT(mb + 8 * s, (c / NSTAGE) & 1);
        __syncthreads();
        int nc = c + NSTAGE - 1;
        if (tid == 0 && nc < NC) {
            int sn = nc % NSTAGE;
            uint32_t m = mb + 8 * sn;
            uint32_t d = smem_u32(smem + sn * STG);
            MBAR_EXPECT(m, STG);
            BULK_G2S(d,      A + (size_t)nc * SL, SL, m);
            BULK_G2S(d + SL, B + (size_t)nc * SL, SL, m);
        }
        if (MODE == 3) {
            if (ss) compute_slab1<true >(smem + s * STG, acc, ss + (c >> 2) * 128);
            else    compute_slab1<false>(smem + s * STG, acc, nullptr);
        } else {
            compute_slab3(smem + s * STG, acc);
        }
    }
}

// drain a staged 4-slab region to global
template<int SL>
__device__ __forceinline__ void stage_drain(char* smem, char* dst)
{
    __syncthreads();
    if (threadIdx.x == 0) {
        FENCE_ASYNC();
#pragma unroll
        for (int sl = 0; sl < 4; ++sl)
            BULK_S2G(dst + sl * SL, smem_u32(smem + sl * SL), SL);
        BULK_COMMIT();
        BULK_WAIT0();
    }
}

// ---------------------------------------------------------------------------
// Epilogues. Frag: d0,d1 -> (row=lane>>2, col=(lane&3)*2+e), d2,d3 row+8.
// ---------------------------------------------------------------------------
__device__ __forceinline__ void epi_f32(const float acc[4][4][4],
        float* __restrict__ Cg, int ldc)
{
    int tid = threadIdx.x, lane = tid & 31, wid = tid >> 5;
    int row0 = (wid & 1) * 64 + (lane >> 2), col0 = (wid >> 1) * 32 + (lane & 3) * 2;
#pragma unroll
    for (int mi = 0; mi < 4; ++mi)
#pragma unroll
        for (int j = 0; j < 4; ++j) {
            int c = col0 + j * 8;
#pragma unroll
            for (int h = 0; h < 2; ++h) {
                int r = row0 + mi * 16 + h * 8;
                *reinterpret_cast<float2*>(Cg + (long)r * ldc + c) =
                    make_float2(acc[mi][j][h * 2], acc[mi][j][h * 2 + 1]);
            }
        }
}

// qm: fp16 split normal; 64KB stage.
__device__ __forceinline__ void epi_split_h(const float acc[4][4][4],
        char* smem, char* dst, const float* __restrict__ bias)
{
    int tid = threadIdx.x, lane = tid & 31, wid = tid >> 5;
    int rw0 = (wid & 1) * 64 + (lane >> 2), cw0 = (wid >> 1) * 32 + (lane & 3) * 2;
    __syncthreads();
#pragma unroll
    for (int mi = 0; mi < 4; ++mi)
#pragma unroll
        for (int j = 0; j < 4; ++j) {
            int c = cw0 + j * 8;
            float b0 = bias[c], b1 = bias[c + 1];
#pragma unroll
            for (int h = 0; h < 2; ++h) {
                int r = rw0 + mi * 16 + h * 8;
                __half2 hh, ll;
                split2h(acc[mi][j][h * 2] + b0, acc[mi][j][h * 2 + 1] + b1, hh, ll);
                int off = loc_f(r, c);
                *reinterpret_cast<uint32_t*>(smem + off)        = b2u(hh);
                *reinterpret_cast<uint32_t*>(smem + (off ^ 64)) = b2u(ll);
            }
        }
    stage_drain<SLAB_F>(smem, dst);
}

// transposed single-fp16 (v^T with bias, o^T without); 32KB stage.
__device__ __forceinline__ void epi_t_h16(const float acc[4][4][4],
        char* smem, char* dst, const float* __restrict__ bias)
{
    int tid = threadIdx.x, lane = tid & 31, wid = tid >> 5;
    int rw0 = (wid & 1) * 64 + (lane >> 2), cw0 = (wid >> 1) * 32 + (lane & 3) * 2;
    __syncthreads();
#pragma unroll
    for (int mi = 0; mi < 4; ++mi)
#pragma unroll
        for (int j = 0; j < 4; ++j)
#pragma unroll
            for (int h = 0; h < 2; ++h) {
                int m = rw0 + mi * 16 + h * 8;
#pragma unroll
                for (int e = 0; e < 2; ++e) {
                    int n = cw0 + j * 8 + e;
                    float v = acc[mi][j][h * 2 + e] + (bias ? bias[n] : 0.0f);
                    *reinterpret_cast<uint16_t*>(smem + loc_h(n, m)) = b2s(__float2half(v));
                }
            }
    stage_drain<SLAB_H>(smem, dst);
}

// attn: exp(acc + w_col), per-tile normalize, single fp16 + partial sums.
__device__ __forceinline__ void epi_attn(const float acc[4][4][4], char* smem,
        char* dst, const float* __restrict__ wcol, float* __restrict__ zp_out)
{
    int tid = threadIdx.x, lane = tid & 31, wid = tid >> 5;
    int rw0 = (wid & 1) * 64 + (lane >> 2), cw0 = (wid >> 1) * 32 + (lane & 3) * 2;
    float* zsm = reinterpret_cast<float*>(smem + 4 * SLAB_H);   // above 32KB stage
    __syncthreads();

    float wc[8];
#pragma unroll
    for (int j = 0; j < 4; ++j) {
        wc[j * 2]     = wcol[cw0 + j * 8];
        wc[j * 2 + 1] = wcol[cw0 + j * 8 + 1];
    }

    float ex[4][4][4];
#pragma unroll
    for (int mi = 0; mi < 4; ++mi) {
#pragma unroll
        for (int h = 0; h < 2; ++h) {
            int r = rw0 + mi * 16 + h * 8;
            float rs = 0.0f;
#pragma unroll
            for (int j = 0; j < 4; ++j) {
                float e0 = __expf(acc[mi][j][h * 2]     + wc[j * 2]);
                float e1 = __expf(acc[mi][j][h * 2 + 1] + wc[j * 2 + 1]);
                ex[mi][j][h * 2] = e0; ex[mi][j][h * 2 + 1] = e1;
                rs += e0 + e1;
            }
            rs += __shfl_xor_sync(0xffffffffu, rs, 1);
            rs += __shfl_xor_sync(0xffffffffu, rs, 2);
            if ((lane & 3) == 0)
                zsm[(wid >> 1) * 128 + r] = rs;
        }
    }
    __syncthreads();
    if (tid < 128)
        zp_out[tid] = zsm[tid] + zsm[128 + tid] + zsm[256 + tid] + zsm[384 + tid];
#pragma unroll
    for (int mi = 0; mi < 4; ++mi)
#pragma unroll
        for (int h = 0; h < 2; ++h) {
            int r = rw0 + mi * 16 + h * 8;
            float inv = 1.0f / (zsm[r] + zsm[128 + r] + zsm[256 + r] + zsm[384 + r]);
#pragma unroll
            for (int j = 0; j < 4; ++j) {
                int c = cw0 + j * 8;
                __half2 hv = __floats2half2_rn(ex[mi][j][h * 2] * inv,
                                               ex[mi][j][h * 2 + 1] * inv);
                *reinterpret_cast<uint32_t*>(smem + loc_h(r, c)) = b2u(hv);
            }
        }
    stage_drain<SLAB_H>(smem, dst);
}

// ---------------------------------------------------------------------------
// Prep: Wv conv (0..63) | Wp^T single fp16 (64..1087) | Mt tiles (1088..1103)
//       | beta (1104)
// ---------------------------------------------------------------------------
__global__ void __launch_bounds__(NTHREADS) prep_kernel(
        const float* __restrict__ Wq, const float* __restrict__ Wk,
        const float* __restrict__ Wv, const float* __restrict__ Wp,
        const float* __restrict__ bq)
{
    int bid = blockIdx.x, tid = threadIdx.x;
    if (bid < 64) {
        long i = (long)bid * NTHREADS + tid;
        float4 v = reinterpret_cast<const float4*>(Wv)[i];
        long e = i * 4;
        int r = (int)(e >> 8), k = (int)(e & 255);
        size_t off = sbf_off(r >> 7, 8, r & 127, k);
        __half2 h0, l0, h1, l1;
        split2h(v.x, v.y, h0, l0);
        split2h(v.z, v.w, h1, l1);
        *reinterpret_cast<uint2*>(g_wvs + off)        = make_uint2(b2u(h0), b2u(h1));
        *reinterpret_cast<uint2*>(g_wvs + (off ^ 64)) = make_uint2(b2u(l0), b2u(l1));
    } else if (bid < 1088) {
        __shared__ float t[32][33];
        int b2 = bid - 64;
        int h = b2 >> 5, n0 = (b2 & 31) * 32;
        int tx = tid & 31, ty = tid >> 5;
        const float* src = Wp + (long)h * 32768 + (long)n0 * 32;
#pragma unroll
        for (int i = 0; i < 4; ++i) t[ty + i * 8][tx] = src[(ty + i * 8) * 32 + tx];
        __syncthreads();
#pragma unroll
        for (int i = 0; i < 4; ++i) {
            int w = ty + i * 8;
            int p = h * 32 + w, n = n0 + tx;
            *reinterpret_cast<uint16_t*>(g_wpts + h16_off(p >> 7, 32, p & 127, n)) =
                b2s(__float2half(t[tx][w]));
        }
    } else if (bid < 1104) {
        __shared__ float As[32][64], Bs[32][64];
        int mt = bid - 1088;
        int e0 = (mt >> 2) * 64, c0 = (mt & 3) * 64;
        int tx = tid & 15, ty = tid >> 4;
        float acc[4][4] = {};
        for (int k0 = 0; k0 < 256; k0 += 32) {
            for (int i = tid; i < 2048; i += NTHREADS) {
                int dd = i >> 6, ee = i & 63;
                As[dd][ee] = Wk[(long)(k0 + dd) * 256 + e0 + ee];
                Bs[dd][ee] = Wq[(long)(k0 + dd) * 256 + c0 + ee];
            }
            __syncthreads();
#pragma unroll 8
            for (int dd = 0; dd < 32; ++dd) {
                float a[4], b[4];
#pragma unroll
                for (int i = 0; i < 4; ++i) { a[i] = As[dd][ty * 4 + i]; b[i] = Bs[dd][tx * 4 + i]; }
#pragma unroll
                for (int i = 0; i < 4; ++i)
#pragma unroll
                    for (int j = 0; j < 4; ++j) acc[i][j] += a[i] * b[j];
            }
            __syncthreads();
        }
#pragma unroll
        for (int i = 0; i < 4; ++i)
#pragma unroll
            for (int j = 0; j < 4; ++j) {
                int e = e0 + ty * 4 + i, c = c0 + tx * 4 + j;
                __half hb = __float2half(acc[i][j]);
                __half lb = __float2half(acc[i][j] - __half2float(hb));
                size_t off = sbf_off(e >> 7, 8, e & 127, c);
                *reinterpret_cast<uint16_t*>(g_mts + off)        = b2s(hb);
                *reinterpret_cast<uint16_t*>(g_mts + (off ^ 64)) = b2s(lb);
            }
    } else {
        int c = tid;
        float acc = 0.0f;
        for (int d = 0; d < 256; ++d) acc += Wk[(long)d * 256 + c] * bq[d];
        g_beta[c] = acc;
    }
}

// x conv (0..4095) + w vector (4096..6143)
__global__ void __launch_bounds__(NTHREADS) xconv_kernel(const float* __restrict__ src)
{
    int bid = blockIdx.x, tid = threadIdx.x;
    if (bid < 4096) {
        long i = (long)bid * NTHREADS + tid;
        float4 v = reinterpret_cast<const float4*>(src)[i];
        long e = i * 4;
        int r = (int)(e >> 8), k = (int)(e & 255);
        size_t off = sbf_off(r >> 7, 8, r & 127, k);
        __half2 h0, l0, h1, l1;
        split2h(v.x, v.y, h0, l0);
        split2h(v.z, v.w, h1, l1);
        *reinterpret_cast<uint2*>(g_xs + off)        = make_uint2(b2u(h0), b2u(h1));
        *reinterpret_cast<uint2*>(g_xs + (off ^ 64)) = make_uint2(b2u(l0), b2u(l1));
    } else {
        int row = (bid - 4096) * 8 + (tid >> 5);
        int lane = tid & 31;
        float p = 0.0f;
#pragma unroll
        for (int e = 0; e < 8; ++e)
            p += src[(long)row * 256 + lane + e * 32] * g_beta[lane + e * 32];
#pragma unroll
        for (int o = 16; o; o >>= 1) p += __shfl_xor_sync(0xffffffffu, p, o);
        if (!lane) g_w[row] = p;
    }
}

// ---------------------------------------------------------------------------
// Stage 1: proj (fp16 3-term). grid (2, 128, 2): sel0 qm, sel1 v (single fp16).
// ---------------------------------------------------------------------------
__global__ void __launch_bounds__(NTHREADS, 2)
proj_kernel(const float* __restrict__ bv)
{
    extern __shared__ char smem[];
    int n0 = blockIdx.x * 128; long m0 = (long)blockIdx.y * 128; int sel = blockIdx.z;
    const char* B = (sel == 0)
        ? g_mts + (size_t)(n0 >> 7) * 8 * SLAB_F
        : g_wvs + (size_t)(n0 >> 7) * 8 * SLAB_F;
    float acc[4][4][4] = {};
    gemm_bulk<8, 1>(g_xs + (m0 >> 7) * 8 * SLAB_F, B, smem, acc);
    if (sel == 0) {
        char* dst = g_qms + ((size_t)(m0 >> 7) * 8 + (n0 >> 5)) * SLAB_F;
        epi_split_h(acc, smem, dst, g_zero + n0);
    } else {
        int b = (int)(m0 >> 10), tok0 = (int)(m0 & 1023);
        char* dst = g_vts + ((size_t)(b * 2 + (n0 >> 7)) * 32 + (tok0 >> 5)) * SLAB_H;
        epi_t_h16(acc, smem, dst, bv + n0);
    }
}

// ---------------------------------------------------------------------------
// Stage 2: attn_norm = exp(qm x^T + w_j)/zp_tile, fp16 3-term. grid (8, 8, 16)
// ---------------------------------------------------------------------------
__global__ void __launch_bounds__(NTHREADS, 2) scores_kernel()
{
    extern __shared__ char smem[];
    int n0 = blockIdx.x * 128, m0 = blockIdx.y * 128, b = blockIdx.z;
    float acc[4][4][4] = {};
    gemm_bulk<8, 1>(g_qms + (size_t)((b * NTOK + m0) >> 7) * 8 * SLAB_F,
                    g_xs  + (size_t)((b * NTOK + n0) >> 7) * 8 * SLAB_F,
                    smem, acc);
    char* dst = g_attns + ((size_t)((b * NTOK + m0) >> 7) * 32 + (n0 >> 5)) * SLAB_H;
    epi_attn(acc, smem, dst, g_w + (long)b * NTOK + n0,
             g_zp + ((long)b * 8 + blockIdx.x) * NTOK + m0);
}

// ---------------------------------------------------------------------------
// Stage 3: o^T, fp16 1-term with per-tile A rescale. grid (2, 8, 16)
// ---------------------------------------------------------------------------
__global__ void __launch_bounds__(NTHREADS, 2) av_kernel()
{
    extern __shared__ char smem[];
    int c0 = blockIdx.x * 128, tok0 = blockIdx.y * 128, b = blockIdx.z;
    __half* ss = reinterpret_cast<__half*>(smem + NSTAGE * 2 * SLAB_H + 64);
    if (threadIdx.x < 128) {
        float z[8], Z = 0.0f;
#pragma unroll
        for (int t = 0; t < 8; ++t) {
            z[t] = g_zp[((long)b * 8 + t) * NTOK + tok0 + threadIdx.x];
            Z += z[t];
        }
        float invZ = 1.0f / Z;
#pragma unroll
        for (int t = 0; t < 8; ++t)
            ss[t * 128 + threadIdx.x] = __float2half(z[t] * invZ);
    }
    float acc[4][4][4] = {};
    gemm_bulk<32, 3>(g_attns + (size_t)((b * NTOK + tok0) >> 7) * 32 * SLAB_H,
                     g_vts   + (size_t)(b * 2 + (c0 >> 7))      * 32 * SLAB_H,
                     smem, acc, ss);
    char* dst = g_ots + ((size_t)(b * 2 + (c0 >> 7)) * 32 + (tok0 >> 5)) * SLAB_H;
    epi_t_h16(acc, smem, dst, nullptr);
}

// ---------------------------------------------------------------------------
// Stage 4: z = Wp^T o, fp16 1-term. grid (2, 8, 16)
// ---------------------------------------------------------------------------
__global__ void __launch_bounds__(NTHREADS, 2) final_kernel(float* __restrict__ z)
{
    extern __shared__ char smem[];
    int c0 = blockIdx.x * 128, p0 = blockIdx.y * 128, b = blockIdx.z;
    float acc[4][4][4] = {};
    gemm_bulk<32, 3>(g_wpts + (size_t)(p0 >> 7) * 32 * SLAB_H,
                     g_ots  + (size_t)(b * 2 + (c0 >> 7)) * 32 * SLAB_H,
                     smem, acc);
    epi_f32(acc, z + ((long)b * NTOK + p0) * CDIM + c0, CDIM);
}

// ---------------------------------------------------------------------------
extern "C" void kernel_launch(void* const* d_in, const int* in_sizes, int n_in,
                              void* d_out, int out_size)
{
    const float* x  = (const float*)d_in[0];
    const float* Wq = (const float*)d_in[1];
    const float* bq = (const float*)d_in[2];
    const float* Wk = (const float*)d_in[3];
    const float* Wv = (const float*)d_in[5];
    const float* bv = (const float*)d_in[6];
    const float* Wp = (const float*)d_in[7];
    float* out = (float*)d_out;

    cudaFuncSetAttribute(proj_kernel,   cudaFuncAttributeMaxDynamicSharedMemorySize, SMEM_3T);
    cudaFuncSetAttribute(scores_kernel, cudaFuncAttributeMaxDynamicSharedMemorySize, SMEM_3T);
    cudaFuncSetAttribute(av_kernel,     cudaFuncAttributeMaxDynamicSharedMemorySize, SMEM_AV);
    cudaFuncSetAttribute(final_kernel,  cudaFuncAttributeMaxDynamicSharedMemorySize, SMEM_1T);

    prep_kernel <<<dim3(1105), NTHREADS>>>(Wq, Wk, Wv, Wp, bq);            // 1
    xconv_kernel<<<dim3(6144), NTHREADS>>>(x);                             // 2
    proj_kernel  <<<dim3(2, 128, 2), NTHREADS, SMEM_3T>>>(bv);             // 3
    scores_kernel<<<dim3(8, 8, 16),  NTHREADS, SMEM_3T>>>();               // 4 <- profiled
    av_kernel    <<<dim3(2, 8, 16),  NTHREADS, SMEM_AV>>>();               // 5
    final_kernel <<<dim3(2, 8, 16),  NTHREADS, SMEM_1T>>>(out);            // 6
}